// round 1
// baseline (speedup 1.0000x reference)
#include <cuda_runtime.h>
#include <math.h>
#include <stdint.h>

// ---------------- model dims ----------------
#define BB    16
#define SS    512
#define DD    256
#define HH    8
#define DHD   32
#define NLAY  2
#define NEXP  8
#define EHID  1024
#define NTOK  (BB*SS)   // 8192

// ---------------- scratch (static device globals; no runtime alloc) --------
__device__ float g_h   [NTOK*DD];
__device__ float g_qkv [NTOK*3*DD];
__device__ float g_ctx [NTOK*DD];
__device__ float g_tmp [NTOK*DD];
__device__ int   g_pad [NTOK];
__device__ int   g_eidx[NTOK];
__device__ float g_ew  [NTOK];

// ---------------- embedding + positional encoding + pad mask ---------------
__global__ void embed_kernel(const int* __restrict__ x, const float* __restrict__ emb)
{
    int n = blockIdx.x;          // token
    int d = threadIdx.x;         // dim (256 threads)
    int tok = x[n];
    int s = n & (SS - 1);

    // pe computed in double for robust range reduction (arg up to ~511)
    double freq = exp(-(double)(d & ~1) * (log(10000.0) / (double)DD));
    double arg  = (double)s * freq;
    float pe = (d & 1) ? (float)cos(arg) : (float)sin(arg);

    float v = emb[(size_t)tok * DD + d] * 16.0f + pe;   // sqrt(256)=16
    g_h[(size_t)n * DD + d] = v;

    __shared__ float red[DD];
    red[d] = v;
    __syncthreads();
    for (int st = DD/2; st > 0; st >>= 1) {
        if (d < st) red[d] += red[d + st];
        __syncthreads();
    }
    if (d == 0) g_pad[n] = (red[0] == 0.0f) ? 1 : 0;
}

// ---------------- generic fp32 GEMM: C[M,Nc] = A[M,K] @ W[Nc,K]^T + bias ----
// BM=BN=64, BK=16, 256 threads, 4x4 per thread. Assumes M%64==0, Nc%64==0, K%16==0.
__global__ void gemm_bias_kernel(const float* __restrict__ A,
                                 const float* __restrict__ W,
                                 const float* __restrict__ bias,
                                 float* __restrict__ C,
                                 int M, int Nc, int K)
{
    __shared__ float As[16][64];
    __shared__ float Bs[16][64];

    int tid  = threadIdx.x;
    int m0   = blockIdx.y * 64;
    int n0   = blockIdx.x * 64;
    int trow = tid >> 4;    // 0..15
    int tcol = tid & 15;    // 0..15

    float acc[4][4] = {};

    for (int k0 = 0; k0 < K; k0 += 16) {
        // load A tile: 64 rows x 16 cols, float4 per thread
        {
            int r  = tid >> 2;            // 0..63
            int kc = (tid & 3) * 4;       // 0,4,8,12
            float4 a4 = *(const float4*)(A + (size_t)(m0 + r) * K + k0 + kc);
            As[kc + 0][r] = a4.x; As[kc + 1][r] = a4.y;
            As[kc + 2][r] = a4.z; As[kc + 3][r] = a4.w;
        }
        // load W tile (transposed into Bs[k][n])
        {
            int r  = tid >> 2;            // output-col index 0..63
            int kc = (tid & 3) * 4;
            float4 b4 = *(const float4*)(W + (size_t)(n0 + r) * K + k0 + kc);
            Bs[kc + 0][r] = b4.x; Bs[kc + 1][r] = b4.y;
            Bs[kc + 2][r] = b4.z; Bs[kc + 3][r] = b4.w;
        }
        __syncthreads();

        #pragma unroll
        for (int k = 0; k < 16; k++) {
            float ar[4], bc[4];
            #pragma unroll
            for (int i = 0; i < 4; i++) ar[i] = As[k][trow * 4 + i];
            #pragma unroll
            for (int j = 0; j < 4; j++) bc[j] = Bs[k][tcol * 4 + j];
            #pragma unroll
            for (int i = 0; i < 4; i++)
                #pragma unroll
                for (int j = 0; j < 4; j++)
                    acc[i][j] += ar[i] * bc[j];
        }
        __syncthreads();
    }

    #pragma unroll
    for (int i = 0; i < 4; i++) {
        int row = m0 + trow * 4 + i;
        #pragma unroll
        for (int j = 0; j < 4; j++) {
            int col = n0 + tcol * 4 + j;
            C[(size_t)row * Nc + col] = acc[i][j] + bias[col];
        }
    }
}

// ---------------- attention: one block per (b,h,q) --------------------------
__global__ void attn_kernel()
{
    int idx = blockIdx.x;
    int q = idx & (SS - 1);
    int h = (idx >> 9) & (HH - 1);
    int b = idx >> 12;
    int tid = threadIdx.x;   // 256

    __shared__ float qs[DHD];
    __shared__ float sc[SS];
    __shared__ float red[256];
    __shared__ float part[256];

    size_t base = (size_t)(b * SS) * (3 * DD);
    if (tid < DHD) qs[tid] = g_qkv[base + (size_t)q * (3 * DD) + h * DHD + tid];
    __syncthreads();

    const float inv = 0.17677669529663689f;   // 1/sqrt(32)
    for (int k = tid; k < SS; k += 256) {
        const float* kp = &g_qkv[base + (size_t)k * (3 * DD) + DD + h * DHD];
        float s = 0.f;
        #pragma unroll
        for (int d = 0; d < DHD; d++) s += qs[d] * kp[d];
        s *= inv;
        if (g_pad[b * SS + k]) s = -1e9f;
        sc[k] = s;
    }
    __syncthreads();

    // max-reduce
    red[tid] = fmaxf(sc[tid], sc[tid + 256]);
    __syncthreads();
    for (int st = 128; st > 0; st >>= 1) {
        if (tid < st) red[tid] = fmaxf(red[tid], red[tid + st]);
        __syncthreads();
    }
    float mx = red[0];
    __syncthreads();

    // exp + sum-reduce
    float p0 = expf(sc[tid] - mx);
    float p1 = expf(sc[tid + 256] - mx);
    sc[tid] = p0; sc[tid + 256] = p1;
    red[tid] = p0 + p1;
    __syncthreads();
    for (int st = 128; st > 0; st >>= 1) {
        if (tid < st) red[tid] += red[tid + st];
        __syncthreads();
    }
    float inv_sum = 1.0f / red[0];

    // ctx: 8 groups of 32 lanes, group g handles k in [g*64, g*64+64)
    int g = tid >> 5, lane = tid & 31;
    float acc = 0.f;
    int kbeg = g * 64;
    for (int k = kbeg; k < kbeg + 64; k++)
        acc += sc[k] * g_qkv[base + (size_t)k * (3 * DD) + 2 * DD + h * DHD + lane];
    part[tid] = acc;
    __syncthreads();
    if (tid < DHD) {
        float s = 0.f;
        #pragma unroll
        for (int gg = 0; gg < 8; gg++) s += part[gg * 32 + tid];
        g_ctx[(size_t)(b * SS + q) * DD + h * DHD + tid] = s * inv_sum;
    }
}

// ---------------- residual + LayerNorm (in place on g_h) --------------------
__global__ void add_ln_kernel(const float* __restrict__ add,
                              const float* __restrict__ gamma,
                              const float* __restrict__ beta)
{
    int n = blockIdx.x, d = threadIdx.x;
    float v = g_h[(size_t)n * DD + d] + add[(size_t)n * DD + d];
    __shared__ float red[DD];
    __shared__ float s_mu, s_var;

    red[d] = v;
    __syncthreads();
    for (int st = DD/2; st > 0; st >>= 1) {
        if (d < st) red[d] += red[d + st];
        __syncthreads();
    }
    if (d == 0) s_mu = red[0] * (1.0f / DD);
    __syncthreads();
    float c = v - s_mu;
    red[d] = c * c;
    __syncthreads();
    for (int st = DD/2; st > 0; st >>= 1) {
        if (d < st) red[d] += red[d + st];
        __syncthreads();
    }
    if (d == 0) s_var = red[0] * (1.0f / DD);
    __syncthreads();
    g_h[(size_t)n * DD + d] = c / sqrtf(s_var + 1e-5f) * gamma[d] + beta[d];
}

// ---------------- top-1 gate -------------------------------------------------
__global__ void gate_kernel(const float* __restrict__ gw, const float* __restrict__ gb)
{
    int n = blockIdx.x, tid = threadIdx.x;   // 256
    int e = tid >> 5, lane = tid & 31;
    const float* xp = &g_h[(size_t)n * DD];
    float s = 0.f;
    for (int d = lane; d < DD; d += 32) s += gw[e * DD + d] * xp[d];
    #pragma unroll
    for (int o = 16; o > 0; o >>= 1) s += __shfl_down_sync(0xffffffffu, s, o);
    __shared__ float logits[NEXP];
    if (lane == 0) logits[e] = s + gb[e];
    __syncthreads();
    if (tid == 0) {
        float m = -1e30f;
        #pragma unroll
        for (int i = 0; i < NEXP; i++) m = fmaxf(m, logits[i]);
        float p[NEXP], sum = 0.f;
        #pragma unroll
        for (int i = 0; i < NEXP; i++) { p[i] = expf(logits[i] - m); sum += p[i]; }
        int bi = 0; float bw = p[0];
        #pragma unroll
        for (int i = 1; i < NEXP; i++) if (p[i] > bw) { bw = p[i]; bi = i; }  // first max
        g_eidx[n] = bi;
        g_ew[n]   = bw / sum;
    }
}

// ---------------- routed-expert MoE (only top-1 expert computed) -------------
__global__ void moe_kernel(const float* __restrict__ w1, const float* __restrict__ b1,
                           const float* __restrict__ w2, const float* __restrict__ b2)
{
    int n = blockIdx.x, tid = threadIdx.x;  // 256
    int e = g_eidx[n];
    float gw = g_ew[n];

    __shared__ float xs[DD];
    __shared__ float h1[EHID];
    xs[tid] = g_h[(size_t)n * DD + tid];
    __syncthreads();

    const float* W1 = w1 + (size_t)e * EHID * DD;
    const float* B1 = b1 + (size_t)e * EHID;
    const float4* xr = (const float4*)xs;
    for (int j = tid; j < EHID; j += 256) {
        const float4* wr = (const float4*)(W1 + (size_t)j * DD);
        float s = 0.f;
        #pragma unroll 8
        for (int i = 0; i < DD/4; i++) {
            float4 w = wr[i], xv = xr[i];
            s += w.x * xv.x + w.y * xv.y + w.z * xv.z + w.w * xv.w;
        }
        h1[j] = fmaxf(s + B1[j], 0.f);
    }
    __syncthreads();

    const float* W2 = w2 + (size_t)e * DD * EHID;
    const float4* wr = (const float4*)(W2 + (size_t)tid * EHID);
    const float4* hr = (const float4*)h1;
    float s = 0.f;
    #pragma unroll 8
    for (int i = 0; i < EHID/4; i++) {
        float4 w = wr[i], hv = hr[i];
        s += w.x * hv.x + w.y * hv.y + w.z * hv.z + w.w * hv.w;
    }
    g_tmp[(size_t)n * DD + tid] = gw * (s + b2[e * DD + tid]);
}

// ---------------- masked mean pool + fc1(relu) + fc2 -------------------------
__global__ void head_kernel(const float* __restrict__ fc1w, const float* __restrict__ fc1b,
                            const float* __restrict__ fc2w, const float* __restrict__ fc2b,
                            float* __restrict__ out)
{
    int b = blockIdx.x, tid = threadIdx.x;  // 256
    __shared__ float pooled[DD];
    __shared__ float z[128];

    float s = 0.f;
    int cnt = 0;
    for (int si = 0; si < SS; si++) {
        int n = b * SS + si;
        if (!g_pad[n]) { s += g_h[(size_t)n * DD + tid]; cnt++; }
    }
    pooled[tid] = s / fmaxf((float)cnt, 1.0f);
    __syncthreads();

    if (tid < 128) {
        float a = fc1b[tid];
        const float* wr = fc1w + (size_t)tid * DD;
        #pragma unroll 8
        for (int d = 0; d < DD; d++) a += pooled[d] * wr[d];
        z[tid] = fmaxf(a, 0.f);
    }
    __syncthreads();
    if (tid < 2) {
        float a = fc2b[tid];
        const float* wr = fc2w + (size_t)tid * 128;
        #pragma unroll 8
        for (int i = 0; i < 128; i++) a += z[i] * wr[i];
        out[b * 2 + tid] = a;
    }
}

// ---------------- host launch ------------------------------------------------
static float* sym_addr(const void* sym)
{
    void* p = nullptr;
    cudaGetSymbolAddress(&p, sym);
    return (float*)p;
}

extern "C" void kernel_launch(void* const* d_in, const int* in_sizes, int n_in,
                              void* d_out, int out_size)
{
    const int*   x          = (const int*)  d_in[0];
    const float* emb        = (const float*)d_in[1];
    const float* in_proj_w  = (const float*)d_in[2];
    const float* in_proj_b  = (const float*)d_in[3];
    const float* out_proj_w = (const float*)d_in[4];
    const float* out_proj_b = (const float*)d_in[5];
    const float* ln1_g      = (const float*)d_in[6];
    const float* ln1_b      = (const float*)d_in[7];
    const float* ln2_g      = (const float*)d_in[8];
    const float* ln2_b      = (const float*)d_in[9];
    const float* gate_w     = (const float*)d_in[10];
    const float* gate_b     = (const float*)d_in[11];
    const float* w1         = (const float*)d_in[12];
    const float* b1         = (const float*)d_in[13];
    const float* w2         = (const float*)d_in[14];
    const float* b2         = (const float*)d_in[15];
    const float* fc1_w      = (const float*)d_in[16];
    const float* fc1_b      = (const float*)d_in[17];
    const float* fc2_w      = (const float*)d_in[18];
    const float* fc2_b      = (const float*)d_in[19];
    float* out = (float*)d_out;

    float* p_h   = sym_addr(g_h);
    float* p_qkv = sym_addr(g_qkv);
    float* p_ctx = sym_addr(g_ctx);
    float* p_tmp = sym_addr(g_tmp);

    embed_kernel<<<NTOK, DD>>>(x, emb);

    for (int l = 0; l < NLAY; l++) {
        // QKV projection: [8192,256] @ [768,256]^T
        gemm_bias_kernel<<<dim3(3*DD/64, NTOK/64), 256>>>(
            p_h, in_proj_w + (size_t)l * 3*DD*DD, in_proj_b + (size_t)l * 3*DD,
            p_qkv, NTOK, 3*DD, DD);

        attn_kernel<<<BB * HH * SS, 256>>>();

        // out projection: [8192,256] @ [256,256]^T
        gemm_bias_kernel<<<dim3(DD/64, NTOK/64), 256>>>(
            p_ctx, out_proj_w + (size_t)l * DD*DD, out_proj_b + (size_t)l * DD,
            p_tmp, NTOK, DD, DD);

        add_ln_kernel<<<NTOK, DD>>>(p_tmp, ln1_g + (size_t)l * DD, ln1_b + (size_t)l * DD);

        gate_kernel<<<NTOK, 256>>>(gate_w + (size_t)l * NEXP*DD, gate_b + (size_t)l * NEXP);

        moe_kernel<<<NTOK, 256>>>(
            w1 + (size_t)l * NEXP*EHID*DD, b1 + (size_t)l * NEXP*EHID,
            w2 + (size_t)l * NEXP*DD*EHID, b2 + (size_t)l * NEXP*DD);

        add_ln_kernel<<<NTOK, DD>>>(p_tmp, ln2_g + (size_t)l * DD, ln2_b + (size_t)l * DD);
    }

    head_kernel<<<BB, 256>>>(fc1_w, fc1_b, fc2_w, fc2_b, out);
}

// round 2
// speedup vs baseline: 8.2582x; 8.2582x over previous
#include <cuda_runtime.h>
#include <math.h>
#include <stdint.h>

// ---------------- model dims ----------------
#define BB    16
#define SS    512
#define DD    256
#define HH    8
#define DHD   32
#define NLAY  2
#define NEXP  8
#define EHID  1024
#define NTOK  (BB*SS)   // 8192

// ---------------- scratch (static device globals) ---------------------------
__device__ float g_h   [NTOK*DD];
__device__ float g_qkv [NTOK*3*DD];   // split: [0..]=Q, [+2097152]=K, [+4194304]=V, each [B][H][S][32]
__device__ float g_ctx [NTOK*DD];
__device__ float g_tmp [NTOK*DD];
__device__ float g_h1  [NTOK*EHID];   // MoE hidden (permuted row order)
__device__ int   g_pad [NTOK];
__device__ int   g_eidx[NTOK];
__device__ float g_ew  [NTOK];
__device__ int   g_cnt [NEXP];
__device__ int   g_base[NEXP];
__device__ int   g_cursor[NEXP];
__device__ int   g_perm[NTOK];

#define QKV_HSZ (BB*HH*SS*DHD)   // 2097152

// ---------------- embedding + positional encoding + pad mask ---------------
__global__ void embed_kernel(const int* __restrict__ x, const float* __restrict__ emb)
{
    int n = blockIdx.x;
    int d = threadIdx.x;
    int tok = x[n];
    int s = n & (SS - 1);

    double freq = exp(-(double)(d & ~1) * (log(10000.0) / (double)DD));
    double arg  = (double)s * freq;
    float pe = (d & 1) ? (float)cos(arg) : (float)sin(arg);

    float v = emb[(size_t)tok * DD + d] * 16.0f + pe;
    g_h[(size_t)n * DD + d] = v;

    __shared__ float red[DD];
    red[d] = v;
    __syncthreads();
    for (int st = DD/2; st > 0; st >>= 1) {
        if (d < st) red[d] += red[d + st];
        __syncthreads();
    }
    if (d == 0) g_pad[n] = (red[0] == 0.0f) ? 1 : 0;
}

// ---------------- generic fp32 GEMM: C[M,Nc] = A[M,K] @ W[Nc,K]^T + bias ----
__global__ void gemm_bias_kernel(const float* __restrict__ A,
                                 const float* __restrict__ W,
                                 const float* __restrict__ bias,
                                 float* __restrict__ C,
                                 int M, int Nc, int K)
{
    __shared__ float As[16][64];
    __shared__ float Bs[16][64];

    int tid  = threadIdx.x;
    int m0   = blockIdx.y * 64;
    int n0   = blockIdx.x * 64;
    int trow = tid >> 4;
    int tcol = tid & 15;

    float acc[4][4] = {};

    for (int k0 = 0; k0 < K; k0 += 16) {
        {
            int r  = tid >> 2;
            int kc = (tid & 3) * 4;
            float4 a4 = *(const float4*)(A + (size_t)(m0 + r) * K + k0 + kc);
            As[kc + 0][r] = a4.x; As[kc + 1][r] = a4.y;
            As[kc + 2][r] = a4.z; As[kc + 3][r] = a4.w;
            float4 b4 = *(const float4*)(W + (size_t)(n0 + r) * K + k0 + kc);
            Bs[kc + 0][r] = b4.x; Bs[kc + 1][r] = b4.y;
            Bs[kc + 2][r] = b4.z; Bs[kc + 3][r] = b4.w;
        }
        __syncthreads();
        #pragma unroll
        for (int k = 0; k < 16; k++) {
            float ar[4], bc[4];
            #pragma unroll
            for (int i = 0; i < 4; i++) ar[i] = As[k][trow * 4 + i];
            #pragma unroll
            for (int j = 0; j < 4; j++) bc[j] = Bs[k][tcol * 4 + j];
            #pragma unroll
            for (int i = 0; i < 4; i++)
                #pragma unroll
                for (int j = 0; j < 4; j++)
                    acc[i][j] += ar[i] * bc[j];
        }
        __syncthreads();
    }

    #pragma unroll
    for (int i = 0; i < 4; i++) {
        int row = m0 + trow * 4 + i;
        #pragma unroll
        for (int j = 0; j < 4; j++) {
            int col = n0 + tcol * 4 + j;
            C[(size_t)row * Nc + col] = acc[i][j] + bias[col];
        }
    }
}

// ---------------- QKV GEMM with split head-major store ----------------------
// C col c: t=c>>8 (q/k/v), h=(c>>5)&7, d=c&31 ; store to g_qkv[t][b][h][s][d]
__global__ void gemm_qkv_kernel(const float* __restrict__ A,
                                const float* __restrict__ W,
                                const float* __restrict__ bias)
{
    __shared__ float As[16][64];
    __shared__ float Bs[16][64];

    int tid  = threadIdx.x;
    int m0   = blockIdx.y * 64;
    int n0   = blockIdx.x * 64;
    int trow = tid >> 4;
    int tcol = tid & 15;

    float acc[4][4] = {};
    const int K = DD;

    for (int k0 = 0; k0 < K; k0 += 16) {
        {
            int r  = tid >> 2;
            int kc = (tid & 3) * 4;
            float4 a4 = *(const float4*)(A + (size_t)(m0 + r) * K + k0 + kc);
            As[kc + 0][r] = a4.x; As[kc + 1][r] = a4.y;
            As[kc + 2][r] = a4.z; As[kc + 3][r] = a4.w;
            float4 b4 = *(const float4*)(W + (size_t)(n0 + r) * K + k0 + kc);
            Bs[kc + 0][r] = b4.x; Bs[kc + 1][r] = b4.y;
            Bs[kc + 2][r] = b4.z; Bs[kc + 3][r] = b4.w;
        }
        __syncthreads();
        #pragma unroll
        for (int k = 0; k < 16; k++) {
            float ar[4], bc[4];
            #pragma unroll
            for (int i = 0; i < 4; i++) ar[i] = As[k][trow * 4 + i];
            #pragma unroll
            for (int j = 0; j < 4; j++) bc[j] = Bs[k][tcol * 4 + j];
            #pragma unroll
            for (int i = 0; i < 4; i++)
                #pragma unroll
                for (int j = 0; j < 4; j++)
                    acc[i][j] += ar[i] * bc[j];
        }
        __syncthreads();
    }

    #pragma unroll
    for (int i = 0; i < 4; i++) {
        int row = m0 + trow * 4 + i;
        int b = row >> 9, s = row & (SS - 1);
        #pragma unroll
        for (int j = 0; j < 4; j++) {
            int col = n0 + tcol * 4 + j;
            int t = col >> 8, h = (col >> 5) & 7, d = col & 31;
            size_t dst = (size_t)t * QKV_HSZ + ((size_t)((b * HH + h) * SS + s)) * DHD + d;
            g_qkv[dst] = acc[i][j] + bias[col];
        }
    }
}

// ---------------- attention: block per (b,h,qtile32) ------------------------
// dyn smem: sc[32][513] | KV[4096] | Qs[32][33] | invs[32] | padS[512 ints]
#define SCS 513
__global__ void attn_kernel()
{
    extern __shared__ float sm[];
    float* sc   = sm;                  // 32*513
    float* KV   = sc + 32 * SCS;       // 4096
    float* Qs   = KV + 4096;           // 32*33
    float* invs = Qs + 32 * 33;        // 32
    int*   padS = (int*)(invs + 32);   // 512

    int qt = blockIdx.x, h = blockIdx.y, b = blockIdx.z;
    int tid = threadIdx.x;
    int w = tid >> 5, l = tid & 31;

    const float* Qg = g_qkv + ((size_t)((b * HH + h) * SS + qt * 32)) * DHD;
    const float* Kg = g_qkv + (size_t)QKV_HSZ     + ((size_t)((b * HH + h) * SS)) * DHD;
    const float* Vg = g_qkv + (size_t)2 * QKV_HSZ + ((size_t)((b * HH + h) * SS)) * DHD;

    // pad mask for this batch row
    padS[tid]       = g_pad[b * SS + tid];
    padS[tid + 256] = g_pad[b * SS + tid + 256];

    // load Q tile (coalesced), padded rows of 33
    for (int idx = tid; idx < 1024; idx += 256) {
        int q = idx >> 5, d = idx & 31;
        Qs[q * 33 + d] = Qg[idx];
    }
    __syncthreads();

    float qv[32];
    #pragma unroll
    for (int d = 0; d < 32; d++) qv[d] = Qs[l * 33 + d];

    const float inv = 0.17677669529663689f;   // 1/sqrt(32)

    // ---- scores ----
    for (int kc = 0; kc < 4; kc++) {
        __syncthreads();
        {
            const float4* src = (const float4*)(Kg + kc * 4096);
            float4* dst = (float4*)KV;
            for (int i = tid; i < 1024; i += 256) dst[i] = src[i];
        }
        __syncthreads();
        #pragma unroll
        for (int i = 0; i < 16; i++) {
            int kl = w * 16 + i;
            int kg = kc * 128 + kl;
            const float4* kr = (const float4*)(KV + kl * 32);
            float s = 0.f;
            #pragma unroll
            for (int d4 = 0; d4 < 8; d4++) {
                float4 kvv = kr[d4];
                s += qv[d4*4+0]*kvv.x + qv[d4*4+1]*kvv.y
                   + qv[d4*4+2]*kvv.z + qv[d4*4+3]*kvv.w;
            }
            s *= inv;
            if (padS[kg]) s = -1e9f;
            sc[l * SCS + kg] = s;
        }
    }
    __syncthreads();

    // ---- softmax: warp w handles rows 4w..4w+3 ----
    #pragma unroll
    for (int qi = 0; qi < 4; qi++) {
        int q = w * 4 + qi;
        float m = -1e30f;
        #pragma unroll
        for (int j = 0; j < 16; j++) m = fmaxf(m, sc[q * SCS + l + 32 * j]);
        #pragma unroll
        for (int o = 16; o > 0; o >>= 1) m = fmaxf(m, __shfl_xor_sync(0xffffffffu, m, o));
        float sum = 0.f;
        #pragma unroll
        for (int j = 0; j < 16; j++) {
            float p = expf(sc[q * SCS + l + 32 * j] - m);
            sc[q * SCS + l + 32 * j] = p;
            sum += p;
        }
        #pragma unroll
        for (int o = 16; o > 0; o >>= 1) sum += __shfl_xor_sync(0xffffffffu, sum, o);
        if (l == 0) invs[q] = 1.0f / sum;
    }

    // ---- ctx: thread (w,l): q=l, dims w*4..w*4+3 ----
    float acc[4] = {0.f, 0.f, 0.f, 0.f};
    for (int kc = 0; kc < 4; kc++) {
        __syncthreads();
        {
            const float4* src = (const float4*)(Vg + kc * 4096);
            float4* dst = (float4*)KV;
            for (int i = tid; i < 1024; i += 256) dst[i] = src[i];
        }
        __syncthreads();
        #pragma unroll 4
        for (int i = 0; i < 128; i++) {
            float p = sc[l * SCS + kc * 128 + i];
            float4 vv = *(const float4*)(KV + i * 32 + w * 4);
            acc[0] += p * vv.x; acc[1] += p * vv.y;
            acc[2] += p * vv.z; acc[3] += p * vv.w;
        }
    }
    float is = invs[l];
    __syncthreads();
    // transpose through Qs (rows of 33) then coalesced store
    #pragma unroll
    for (int j = 0; j < 4; j++) Qs[l * 33 + w * 4 + j] = acc[j] * is;
    __syncthreads();
    {
        int q = tid >> 3, dsub = (tid & 7) * 4;
        float4 ov = make_float4(Qs[q*33+dsub], Qs[q*33+dsub+1],
                                Qs[q*33+dsub+2], Qs[q*33+dsub+3]);
        *(float4*)(g_ctx + (size_t)(b * SS + qt * 32 + q) * DD + h * DHD + dsub) = ov;
    }
}

// ---------------- residual + LayerNorm (in place on g_h) --------------------
__global__ void add_ln_kernel(const float* __restrict__ add,
                              const float* __restrict__ gamma,
                              const float* __restrict__ beta)
{
    int n = blockIdx.x, d = threadIdx.x;
    float v = g_h[(size_t)n * DD + d] + add[(size_t)n * DD + d];
    __shared__ float red[DD];
    __shared__ float s_mu, s_var;

    red[d] = v;
    __syncthreads();
    for (int st = DD/2; st > 0; st >>= 1) {
        if (d < st) red[d] += red[d + st];
        __syncthreads();
    }
    if (d == 0) s_mu = red[0] * (1.0f / DD);
    __syncthreads();
    float c = v - s_mu;
    red[d] = c * c;
    __syncthreads();
    for (int st = DD/2; st > 0; st >>= 1) {
        if (d < st) red[d] += red[d + st];
        __syncthreads();
    }
    if (d == 0) s_var = red[0] * (1.0f / DD);
    __syncthreads();
    g_h[(size_t)n * DD + d] = c / sqrtf(s_var + 1e-5f) * gamma[d] + beta[d];
}

// ---------------- gate + routing bookkeeping --------------------------------
__global__ void zero_cnt_kernel()
{
    if (threadIdx.x < NEXP) g_cnt[threadIdx.x] = 0;
}

__global__ void gate_kernel(const float* __restrict__ gw, const float* __restrict__ gb)
{
    int n = blockIdx.x, tid = threadIdx.x;
    int e = tid >> 5, lane = tid & 31;
    const float* xp = &g_h[(size_t)n * DD];
    float s = 0.f;
    for (int d = lane; d < DD; d += 32) s += gw[e * DD + d] * xp[d];
    #pragma unroll
    for (int o = 16; o > 0; o >>= 1) s += __shfl_down_sync(0xffffffffu, s, o);
    __shared__ float logits[NEXP];
    if (lane == 0) logits[e] = s + gb[e];
    __syncthreads();
    if (tid == 0) {
        float m = -1e30f;
        #pragma unroll
        for (int i = 0; i < NEXP; i++) m = fmaxf(m, logits[i]);
        float p[NEXP], sum = 0.f;
        #pragma unroll
        for (int i = 0; i < NEXP; i++) { p[i] = expf(logits[i] - m); sum += p[i]; }
        int bi = 0; float bw = p[0];
        #pragma unroll
        for (int i = 1; i < NEXP; i++) if (p[i] > bw) { bw = p[i]; bi = i; }
        g_eidx[n] = bi;
        g_ew[n]   = bw / sum;
        atomicAdd(&g_cnt[bi], 1);
    }
}

__global__ void prefix_kernel()
{
    if (threadIdx.x == 0) {
        int acc = 0;
        #pragma unroll
        for (int e = 0; e < NEXP; e++) {
            g_base[e] = acc; g_cursor[e] = acc; acc += g_cnt[e];
        }
    }
}

__global__ void scatter_kernel()
{
    int n = blockIdx.x * blockDim.x + threadIdx.x;
    if (n < NTOK) {
        int e = g_eidx[n];
        int pos = atomicAdd(&g_cursor[e], 1);
        g_perm[pos] = n;
    }
}

// ---------------- MoE GEMM1: H = relu(X_perm @ W1[e]^T + b1[e]) -------------
// grid: (EHID/64, NEXP*128); y -> (e, tile)
__global__ void moe_gemm1_kernel(const float* __restrict__ w1, const float* __restrict__ b1)
{
    int y = blockIdx.y;
    int e = y >> 7, tile = y & 127;
    int cnt = g_cnt[e];
    if (tile * 64 >= cnt) return;
    int pbase = g_base[e] + tile * 64;

    __shared__ int   toks[64];
    __shared__ float As[16][64];
    __shared__ float Bs[16][64];

    int tid = threadIdx.x;
    if (tid < 64) {
        int rr = tile * 64 + tid;
        toks[tid] = g_perm[pbase + ((rr < cnt) ? tid : 0)];
    }
    __syncthreads();

    int n0   = blockIdx.x * 64;
    int trow = tid >> 4, tcol = tid & 15;
    const float* W = w1 + (size_t)e * EHID * DD;

    float acc[4][4] = {};

    for (int k0 = 0; k0 < DD; k0 += 16) {
        {
            int r  = tid >> 2;
            int kc = (tid & 3) * 4;
            float4 a4 = *(const float4*)(g_h + (size_t)toks[r] * DD + k0 + kc);
            As[kc + 0][r] = a4.x; As[kc + 1][r] = a4.y;
            As[kc + 2][r] = a4.z; As[kc + 3][r] = a4.w;
            float4 b4 = *(const float4*)(W + (size_t)(n0 + r) * DD + k0 + kc);
            Bs[kc + 0][r] = b4.x; Bs[kc + 1][r] = b4.y;
            Bs[kc + 2][r] = b4.z; Bs[kc + 3][r] = b4.w;
        }
        __syncthreads();
        #pragma unroll
        for (int k = 0; k < 16; k++) {
            float ar[4], bc[4];
            #pragma unroll
            for (int i = 0; i < 4; i++) ar[i] = As[k][trow * 4 + i];
            #pragma unroll
            for (int j = 0; j < 4; j++) bc[j] = Bs[k][tcol * 4 + j];
            #pragma unroll
            for (int i = 0; i < 4; i++)
                #pragma unroll
                for (int j = 0; j < 4; j++)
                    acc[i][j] += ar[i] * bc[j];
        }
        __syncthreads();
    }

    #pragma unroll
    for (int i = 0; i < 4; i++) {
        int lr = trow * 4 + i;
        if (tile * 64 + lr >= cnt) continue;
        size_t row = (size_t)(pbase + lr) * EHID;
        #pragma unroll
        for (int j = 0; j < 4; j++) {
            int col = n0 + tcol * 4 + j;
            g_h1[row + col] = fmaxf(acc[i][j] + b1[e * EHID + col], 0.f);
        }
    }
}

// ---------------- MoE GEMM2: Y = gw * (H @ W2[e]^T + b2[e]) -> g_tmp --------
// grid: (DD/64, NEXP*128)
__global__ void moe_gemm2_kernel(const float* __restrict__ w2, const float* __restrict__ b2)
{
    int y = blockIdx.y;
    int e = y >> 7, tile = y & 127;
    int cnt = g_cnt[e];
    if (tile * 64 >= cnt) return;
    int pbase = g_base[e] + tile * 64;

    __shared__ int   toks[64];
    __shared__ float As[16][64];
    __shared__ float Bs[16][64];

    int tid = threadIdx.x;
    if (tid < 64) {
        int rr = tile * 64 + tid;
        toks[tid] = g_perm[pbase + ((rr < cnt) ? tid : 0)];
    }
    __syncthreads();

    int n0   = blockIdx.x * 64;
    int trow = tid >> 4, tcol = tid & 15;
    const float* W = w2 + (size_t)e * DD * EHID;

    float acc[4][4] = {};

    for (int k0 = 0; k0 < EHID; k0 += 16) {
        {
            int r  = tid >> 2;
            int kc = (tid & 3) * 4;
            int rr = tile * 64 + r;
            int pidx = pbase + ((rr < cnt) ? r : 0);
            float4 a4 = *(const float4*)(g_h1 + (size_t)pidx * EHID + k0 + kc);
            As[kc + 0][r] = a4.x; As[kc + 1][r] = a4.y;
            As[kc + 2][r] = a4.z; As[kc + 3][r] = a4.w;
            float4 b4 = *(const float4*)(W + (size_t)(n0 + r) * EHID + k0 + kc);
            Bs[kc + 0][r] = b4.x; Bs[kc + 1][r] = b4.y;
            Bs[kc + 2][r] = b4.z; Bs[kc + 3][r] = b4.w;
        }
        __syncthreads();
        #pragma unroll
        for (int k = 0; k < 16; k++) {
            float ar[4], bc[4];
            #pragma unroll
            for (int i = 0; i < 4; i++) ar[i] = As[k][trow * 4 + i];
            #pragma unroll
            for (int j = 0; j < 4; j++) bc[j] = Bs[k][tcol * 4 + j];
            #pragma unroll
            for (int i = 0; i < 4; i++)
                #pragma unroll
                for (int j = 0; j < 4; j++)
                    acc[i][j] += ar[i] * bc[j];
        }
        __syncthreads();
    }

    #pragma unroll
    for (int i = 0; i < 4; i++) {
        int lr = trow * 4 + i;
        if (tile * 64 + lr >= cnt) continue;
        int token = toks[lr];
        float gwv = g_ew[token];
        #pragma unroll
        for (int j = 0; j < 4; j++) {
            int col = n0 + tcol * 4 + j;
            g_tmp[(size_t)token * DD + col] = gwv * (acc[i][j] + b2[e * DD + col]);
        }
    }
}

// ---------------- masked mean pool + fc1(relu) + fc2 -------------------------
__global__ void head_kernel(const float* __restrict__ fc1w, const float* __restrict__ fc1b,
                            const float* __restrict__ fc2w, const float* __restrict__ fc2b,
                            float* __restrict__ out)
{
    int b = blockIdx.x, tid = threadIdx.x;
    __shared__ float pooled[DD];
    __shared__ float z[128];

    float s = 0.f;
    int cnt = 0;
    for (int si = 0; si < SS; si++) {
        int n = b * SS + si;
        if (!g_pad[n]) { s += g_h[(size_t)n * DD + tid]; cnt++; }
    }
    pooled[tid] = s / fmaxf((float)cnt, 1.0f);
    __syncthreads();

    if (tid < 128) {
        float a = fc1b[tid];
        const float* wr = fc1w + (size_t)tid * DD;
        #pragma unroll 8
        for (int d = 0; d < DD; d++) a += pooled[d] * wr[d];
        z[tid] = fmaxf(a, 0.f);
    }
    __syncthreads();
    if (tid < 2) {
        float a = fc2b[tid];
        const float* wr = fc2w + (size_t)tid * 128;
        #pragma unroll 8
        for (int i = 0; i < 128; i++) a += z[i] * wr[i];
        out[b * 2 + tid] = a;
    }
}

// ---------------- host launch ------------------------------------------------
static float* sym_addr(const void* sym)
{
    void* p = nullptr;
    cudaGetSymbolAddress(&p, sym);
    return (float*)p;
}

extern "C" void kernel_launch(void* const* d_in, const int* in_sizes, int n_in,
                              void* d_out, int out_size)
{
    const int*   x          = (const int*)  d_in[0];
    const float* emb        = (const float*)d_in[1];
    const float* in_proj_w  = (const float*)d_in[2];
    const float* in_proj_b  = (const float*)d_in[3];
    const float* out_proj_w = (const float*)d_in[4];
    const float* out_proj_b = (const float*)d_in[5];
    const float* ln1_g      = (const float*)d_in[6];
    const float* ln1_b      = (const float*)d_in[7];
    const float* ln2_g      = (const float*)d_in[8];
    const float* ln2_b      = (const float*)d_in[9];
    const float* gate_w     = (const float*)d_in[10];
    const float* gate_b     = (const float*)d_in[11];
    const float* w1         = (const float*)d_in[12];
    const float* b1         = (const float*)d_in[13];
    const float* w2         = (const float*)d_in[14];
    const float* b2         = (const float*)d_in[15];
    const float* fc1_w      = (const float*)d_in[16];
    const float* fc1_b      = (const float*)d_in[17];
    const float* fc2_w      = (const float*)d_in[18];
    const float* fc2_b      = (const float*)d_in[19];
    float* out = (float*)d_out;

    float* p_h   = sym_addr(g_h);
    float* p_ctx = sym_addr(g_ctx);
    float* p_tmp = sym_addr(g_tmp);

    // dynamic smem for attention: (32*513 + 4096 + 32*33 + 32)*4 + 512*4
    int attn_smem = (32 * SCS + 4096 + 32 * 33 + 32) * 4 + 512 * 4;
    cudaFuncSetAttribute(attn_kernel, cudaFuncAttributeMaxDynamicSharedMemorySize, attn_smem);

    embed_kernel<<<NTOK, DD>>>(x, emb);

    for (int l = 0; l < NLAY; l++) {
        gemm_qkv_kernel<<<dim3(3*DD/64, NTOK/64), 256>>>(
            p_h, in_proj_w + (size_t)l * 3*DD*DD, in_proj_b + (size_t)l * 3*DD);

        attn_kernel<<<dim3(SS/32, HH, BB), 256, attn_smem>>>();

        gemm_bias_kernel<<<dim3(DD/64, NTOK/64), 256>>>(
            p_ctx, out_proj_w + (size_t)l * DD*DD, out_proj_b + (size_t)l * DD,
            p_tmp, NTOK, DD, DD);

        add_ln_kernel<<<NTOK, DD>>>(p_tmp, ln1_g + (size_t)l * DD, ln1_b + (size_t)l * DD);

        zero_cnt_kernel<<<1, 32>>>();
        gate_kernel<<<NTOK, 256>>>(gate_w + (size_t)l * NEXP*DD, gate_b + (size_t)l * NEXP);
        prefix_kernel<<<1, 32>>>();
        scatter_kernel<<<NTOK/256, 256>>>();

        moe_gemm1_kernel<<<dim3(EHID/64, NEXP*128), 256>>>(
            w1 + (size_t)l * NEXP*EHID*DD, b1 + (size_t)l * NEXP*EHID);
        moe_gemm2_kernel<<<dim3(DD/64, NEXP*128), 256>>>(
            w2 + (size_t)l * NEXP*DD*EHID, b2 + (size_t)l * NEXP*DD);

        add_ln_kernel<<<NTOK, DD>>>(p_tmp, ln2_g + (size_t)l * DD, ln2_b + (size_t)l * DD);
    }

    head_kernel<<<BB, 256>>>(fc1_w, fc1_b, fc2_w, fc2_b, out);
}

// round 3
// speedup vs baseline: 14.5742x; 1.7648x over previous
#include <cuda_runtime.h>
#include <math.h>
#include <stdint.h>

// ---------------- model dims ----------------
#define BB    16
#define SS    512
#define DD    256
#define HH    8
#define DHD   32
#define NLAY  2
#define NEXP  8
#define EHID  1024
#define NTOK  (BB*SS)   // 8192

// ---------------- scratch (static device globals) ---------------------------
__device__ float g_h   [NTOK*DD];
__device__ float g_qkv [NTOK*3*DD];   // split: Q | K | V, each [B][H][S][32]
__device__ float g_ctx [NTOK*DD];
__device__ float g_tmp [NTOK*DD];
__device__ float g_h1  [NTOK*EHID];   // MoE hidden (permuted row order)
__device__ float g_pe  [SS*DD];       // positional encoding table
__device__ int   g_pad [NTOK];
__device__ int   g_eidx[NTOK];
__device__ float g_ew  [NTOK];
__device__ int   g_cnt [NEXP];
__device__ int   g_base[NEXP];
__device__ int   g_cursor[NEXP];
__device__ int   g_perm[NTOK];

#define QKV_HSZ (BB*HH*SS*DHD)   // 2097152

// ---------------- tf32 helpers ----------------------------------------------
__device__ __forceinline__ uint32_t f2tf(float x)
{
    uint32_t r;
    asm("cvt.rna.tf32.f32 %0, %1;" : "=r"(r) : "f"(x));
    return r;
}

__device__ __forceinline__ void mma_tf32(float* d, const uint32_t* a, const uint32_t* b)
{
    asm volatile(
        "mma.sync.aligned.m16n8k8.row.col.f32.tf32.tf32.f32 "
        "{%0,%1,%2,%3}, {%4,%5,%6,%7}, {%8,%9}, {%0,%1,%2,%3};\n"
        : "+f"(d[0]), "+f"(d[1]), "+f"(d[2]), "+f"(d[3])
        : "r"(a[0]), "r"(a[1]), "r"(a[2]), "r"(a[3]),
          "r"(b[0]), "r"(b[1]));
}

// smem strides (uint32 elements), pad 20 -> conflict-free frags + 16B aligned
#define ASTR 20

// Core 128x64 tile mainloop. arow0/arow1: this thread's two A rows (global).
// W: weight base for this block's 64 output cols (row-major [64][K]).
// acc[mt][nt][4] per-thread accumulators.
__device__ __forceinline__ void gemm_tile_mainloop(
    const float* __restrict__ arow0, const float* __restrict__ arow1,
    const float* __restrict__ W, int K,
    uint32_t* As, uint32_t* Ws, float acc[2][4][4])
{
    int tid  = threadIdx.x;
    int lane = tid & 31;
    int warp = tid >> 5;
    int wm = warp & 3, wn = warp >> 2;     // 4 x 2 warp grid
    int r  = tid >> 2;                     // 0..63
    int kc = (tid & 3) * 4;

    for (int k0 = 0; k0 < K; k0 += 16) {
        float4 a0 = *(const float4*)(arow0 + k0 + kc);
        float4 a1 = *(const float4*)(arow1 + k0 + kc);
        float4 w0 = *(const float4*)(W + (size_t)r * K + k0 + kc);
        uint4 ua0 = make_uint4(f2tf(a0.x), f2tf(a0.y), f2tf(a0.z), f2tf(a0.w));
        uint4 ua1 = make_uint4(f2tf(a1.x), f2tf(a1.y), f2tf(a1.z), f2tf(a1.w));
        uint4 uw0 = make_uint4(f2tf(w0.x), f2tf(w0.y), f2tf(w0.z), f2tf(w0.w));
        *(uint4*)(As + r * ASTR + kc)        = ua0;
        *(uint4*)(As + (r + 64) * ASTR + kc) = ua1;
        *(uint4*)(Ws + r * ASTR + kc)        = uw0;
        __syncthreads();

        #pragma unroll
        for (int kh = 0; kh < 2; kh++) {
            uint32_t afr[2][4], bfr[4][2];
            #pragma unroll
            for (int mt = 0; mt < 2; mt++) {
                int rb = wm * 32 + mt * 16 + (lane >> 2);
                int cb = kh * 8 + (lane & 3);
                afr[mt][0] = As[(rb    ) * ASTR + cb];
                afr[mt][1] = As[(rb + 8) * ASTR + cb];
                afr[mt][2] = As[(rb    ) * ASTR + cb + 4];
                afr[mt][3] = As[(rb + 8) * ASTR + cb + 4];
            }
            #pragma unroll
            for (int nt = 0; nt < 4; nt++) {
                int nb = wn * 32 + nt * 8 + (lane >> 2);
                int cb = kh * 8 + (lane & 3);
                bfr[nt][0] = Ws[nb * ASTR + cb];
                bfr[nt][1] = Ws[nb * ASTR + cb + 4];
            }
            #pragma unroll
            for (int mt = 0; mt < 2; mt++)
                #pragma unroll
                for (int nt = 0; nt < 4; nt++)
                    mma_tf32(acc[mt][nt], afr[mt], bfr[nt]);
        }
        __syncthreads();
    }
}

// ---------------- positional encoding table ----------------------------------
__global__ void pe_kernel()
{
    int s = blockIdx.x, d = threadIdx.x;
    double freq = exp(-(double)(d & ~1) * (log(10000.0) / (double)DD));
    double arg  = (double)s * freq;
    g_pe[s * DD + d] = (d & 1) ? (float)cos(arg) : (float)sin(arg);
}

// ---------------- embedding + pad mask ---------------------------------------
__global__ void embed_kernel(const int* __restrict__ x, const float* __restrict__ emb)
{
    int n = blockIdx.x;
    int d = threadIdx.x;
    int tok = x[n];
    int s = n & (SS - 1);

    float v = emb[(size_t)tok * DD + d] * 16.0f + g_pe[s * DD + d];
    g_h[(size_t)n * DD + d] = v;

    // block sum for pad mask
    float sum = v;
    #pragma unroll
    for (int o = 16; o > 0; o >>= 1) sum += __shfl_xor_sync(0xffffffffu, sum, o);
    __shared__ float ws[8];
    if ((d & 31) == 0) ws[d >> 5] = sum;
    __syncthreads();
    if (d == 0) {
        float t = 0.f;
        #pragma unroll
        for (int i = 0; i < 8; i++) t += ws[i];
        g_pad[n] = (t == 0.0f) ? 1 : 0;
    }
}

// ---------------- QKV GEMM (tf32 mma) + split head-major store ---------------
__global__ void gemm_qkv_mma(const float* __restrict__ A,
                             const float* __restrict__ W,
                             const float* __restrict__ bias)
{
    __shared__ uint32_t As[128 * ASTR];
    __shared__ uint32_t Ws[64 * ASTR];

    int tid = threadIdx.x, lane = tid & 31, warp = tid >> 5;
    int wm = warp & 3, wn = warp >> 2;
    int m0 = blockIdx.y * 128, n0 = blockIdx.x * 64;

    float acc[2][4][4] = {};
    const float* arow0 = A + (size_t)(m0 + (tid >> 2)) * DD;
    const float* arow1 = arow0 + (size_t)64 * DD;

    gemm_tile_mainloop(arow0, arow1, W + (size_t)n0 * DD, DD, As, Ws, acc);

    #pragma unroll
    for (int mt = 0; mt < 2; mt++) {
        #pragma unroll
        for (int nt = 0; nt < 4; nt++) {
            int r0 = m0 + wm * 32 + mt * 16 + (lane >> 2);
            int c0 = n0 + wn * 32 + nt * 8 + 2 * (lane & 3);
            int t = c0 >> 8, h = (c0 >> 5) & 7, d = c0 & 31;
            #pragma unroll
            for (int half = 0; half < 2; half++) {
                int row = r0 + half * 8;
                int b = row >> 9, s = row & (SS - 1);
                size_t dst = (size_t)t * QKV_HSZ
                           + ((size_t)((b * HH + h) * SS + s)) * DHD + d;
                float2 v = make_float2(acc[mt][nt][half * 2 + 0] + bias[c0],
                                       acc[mt][nt][half * 2 + 1] + bias[c0 + 1]);
                *(float2*)(g_qkv + dst) = v;
            }
        }
    }
}

// ---------------- generic GEMM (tf32 mma): C = A @ W^T + bias ----------------
__global__ void gemm_mma(const float* __restrict__ A,
                         const float* __restrict__ W,
                         const float* __restrict__ bias,
                         float* __restrict__ C, int Nc, int K)
{
    __shared__ uint32_t As[128 * ASTR];
    __shared__ uint32_t Ws[64 * ASTR];

    int tid = threadIdx.x, lane = tid & 31, warp = tid >> 5;
    int wm = warp & 3, wn = warp >> 2;
    int m0 = blockIdx.y * 128, n0 = blockIdx.x * 64;

    float acc[2][4][4] = {};
    const float* arow0 = A + (size_t)(m0 + (tid >> 2)) * K;
    const float* arow1 = arow0 + (size_t)64 * K;

    gemm_tile_mainloop(arow0, arow1, W + (size_t)n0 * K, K, As, Ws, acc);

    #pragma unroll
    for (int mt = 0; mt < 2; mt++) {
        #pragma unroll
        for (int nt = 0; nt < 4; nt++) {
            int r0 = m0 + wm * 32 + mt * 16 + (lane >> 2);
            int c0 = n0 + wn * 32 + nt * 8 + 2 * (lane & 3);
            float bx = bias[c0], by = bias[c0 + 1];
            #pragma unroll
            for (int half = 0; half < 2; half++) {
                int row = r0 + half * 8;
                float2 v = make_float2(acc[mt][nt][half * 2 + 0] + bx,
                                       acc[mt][nt][half * 2 + 1] + by);
                *(float2*)(C + (size_t)row * Nc + c0) = v;
            }
        }
    }
}

// ---------------- MoE GEMM1 (tf32 mma): H = relu(Xperm @ W1[e]^T + b1) -------
// grid: (EHID/64, NEXP*64) ; y -> (e = y>>6, tile = y&63), BM=128
__global__ void moe_gemm1_mma(const float* __restrict__ w1, const float* __restrict__ b1)
{
    int y = blockIdx.y;
    int e = y >> 6, tile = y & 63;
    int cnt = g_cnt[e];
    if (tile * 128 >= cnt) return;
    int ebase = g_base[e];

    __shared__ uint32_t As[128 * ASTR];
    __shared__ uint32_t Ws[64 * ASTR];
    __shared__ int toks[128];

    int tid = threadIdx.x, lane = tid & 31, warp = tid >> 5;
    int wm = warp & 3, wn = warp >> 2;

    if (tid < 128) {
        int rr = tile * 128 + tid;
        toks[tid] = g_perm[ebase + ((rr < cnt) ? rr : (cnt - 1))];
    }
    __syncthreads();

    int n0 = blockIdx.x * 64;
    float acc[2][4][4] = {};
    const float* arow0 = g_h + (size_t)toks[tid >> 2] * DD;
    const float* arow1 = g_h + (size_t)toks[(tid >> 2) + 64] * DD;

    gemm_tile_mainloop(arow0, arow1, w1 + (size_t)e * EHID * DD + (size_t)n0 * DD,
                       DD, As, Ws, acc);

    #pragma unroll
    for (int mt = 0; mt < 2; mt++) {
        #pragma unroll
        for (int nt = 0; nt < 4; nt++) {
            int lr0 = wm * 32 + mt * 16 + (lane >> 2);
            int c0  = n0 + wn * 32 + nt * 8 + 2 * (lane & 3);
            float bx = b1[e * EHID + c0], by = b1[e * EHID + c0 + 1];
            #pragma unroll
            for (int half = 0; half < 2; half++) {
                int lr = lr0 + half * 8;
                int gr = tile * 128 + lr;
                if (gr < cnt) {
                    float2 v = make_float2(
                        fmaxf(acc[mt][nt][half * 2 + 0] + bx, 0.f),
                        fmaxf(acc[mt][nt][half * 2 + 1] + by, 0.f));
                    *(float2*)(g_h1 + (size_t)(ebase + gr) * EHID + c0) = v;
                }
            }
        }
    }
}

// ---------------- MoE GEMM2 (tf32 mma): Y = gw*(H @ W2[e]^T + b2) ------------
// grid: (DD/64, NEXP*64)
__global__ void moe_gemm2_mma(const float* __restrict__ w2, const float* __restrict__ b2)
{
    int y = blockIdx.y;
    int e = y >> 6, tile = y & 63;
    int cnt = g_cnt[e];
    if (tile * 128 >= cnt) return;
    int ebase = g_base[e];

    __shared__ uint32_t As[128 * ASTR];
    __shared__ uint32_t Ws[64 * ASTR];

    int tid = threadIdx.x, lane = tid & 31, warp = tid >> 5;
    int wm = warp & 3, wn = warp >> 2;

    int n0 = blockIdx.x * 64;
    float acc[2][4][4] = {};

    int r  = tid >> 2;
    int gr0 = tile * 128 + r;       if (gr0 >= cnt) gr0 = cnt - 1;
    int gr1 = tile * 128 + r + 64;  if (gr1 >= cnt) gr1 = cnt - 1;
    const float* arow0 = g_h1 + (size_t)(ebase + gr0) * EHID;
    const float* arow1 = g_h1 + (size_t)(ebase + gr1) * EHID;

    gemm_tile_mainloop(arow0, arow1, w2 + (size_t)e * DD * EHID + (size_t)n0 * EHID,
                       EHID, As, Ws, acc);

    #pragma unroll
    for (int mt = 0; mt < 2; mt++) {
        #pragma unroll
        for (int nt = 0; nt < 4; nt++) {
            int lr0 = wm * 32 + mt * 16 + (lane >> 2);
            int c0  = n0 + wn * 32 + nt * 8 + 2 * (lane & 3);
            float bx = b2[e * DD + c0], by = b2[e * DD + c0 + 1];
            #pragma unroll
            for (int half = 0; half < 2; half++) {
                int lr = lr0 + half * 8;
                int gr = tile * 128 + lr;
                if (gr < cnt) {
                    int token = g_perm[ebase + gr];
                    float gwv = g_ew[token];
                    float2 v = make_float2(gwv * (acc[mt][nt][half * 2 + 0] + bx),
                                           gwv * (acc[mt][nt][half * 2 + 1] + by));
                    *(float2*)(g_tmp + (size_t)token * DD + c0) = v;
                }
            }
        }
    }
}

// ---------------- attention: block per (b,h,qtile32) ------------------------
#define SCS 513
__global__ void attn_kernel()
{
    extern __shared__ float sm[];
    float* sc   = sm;                  // 32*513
    float* KV   = sc + 32 * SCS;       // 4096
    float* Qs   = KV + 4096;           // 32*33
    float* invs = Qs + 32 * 33;        // 32
    int*   padS = (int*)(invs + 32);   // 512

    int qt = blockIdx.x, h = blockIdx.y, b = blockIdx.z;
    int tid = threadIdx.x;
    int w = tid >> 5, l = tid & 31;

    const float* Qg = g_qkv + ((size_t)((b * HH + h) * SS + qt * 32)) * DHD;
    const float* Kg = g_qkv + (size_t)QKV_HSZ     + ((size_t)((b * HH + h) * SS)) * DHD;
    const float* Vg = g_qkv + (size_t)2 * QKV_HSZ + ((size_t)((b * HH + h) * SS)) * DHD;

    padS[tid]       = g_pad[b * SS + tid];
    padS[tid + 256] = g_pad[b * SS + tid + 256];

    for (int idx = tid; idx < 1024; idx += 256) {
        int q = idx >> 5, d = idx & 31;
        Qs[q * 33 + d] = Qg[idx];
    }
    __syncthreads();

    float qv[32];
    #pragma unroll
    for (int d = 0; d < 32; d++) qv[d] = Qs[l * 33 + d];

    const float inv = 0.17677669529663689f;   // 1/sqrt(32)

    for (int kc = 0; kc < 4; kc++) {
        __syncthreads();
        {
            const float4* src = (const float4*)(Kg + kc * 4096);
            float4* dst = (float4*)KV;
            for (int i = tid; i < 1024; i += 256) dst[i] = src[i];
        }
        __syncthreads();
        #pragma unroll
        for (int i = 0; i < 16; i++) {
            int kl = w * 16 + i;
            int kg = kc * 128 + kl;
            const float4* kr = (const float4*)(KV + kl * 32);
            float s = 0.f;
            #pragma unroll
            for (int d4 = 0; d4 < 8; d4++) {
                float4 kvv = kr[d4];
                s += qv[d4*4+0]*kvv.x + qv[d4*4+1]*kvv.y
                   + qv[d4*4+2]*kvv.z + qv[d4*4+3]*kvv.w;
            }
            s *= inv;
            if (padS[kg]) s = -1e9f;
            sc[l * SCS + kg] = s;
        }
    }
    __syncthreads();

    #pragma unroll
    for (int qi = 0; qi < 4; qi++) {
        int q = w * 4 + qi;
        float m = -1e30f;
        #pragma unroll
        for (int j = 0; j < 16; j++) m = fmaxf(m, sc[q * SCS + l + 32 * j]);
        #pragma unroll
        for (int o = 16; o > 0; o >>= 1) m = fmaxf(m, __shfl_xor_sync(0xffffffffu, m, o));
        float sum = 0.f;
        #pragma unroll
        for (int j = 0; j < 16; j++) {
            float p = expf(sc[q * SCS + l + 32 * j] - m);
            sc[q * SCS + l + 32 * j] = p;
            sum += p;
        }
        #pragma unroll
        for (int o = 16; o > 0; o >>= 1) sum += __shfl_xor_sync(0xffffffffu, sum, o);
        if (l == 0) invs[q] = 1.0f / sum;
    }

    float acc[4] = {0.f, 0.f, 0.f, 0.f};
    for (int kc = 0; kc < 4; kc++) {
        __syncthreads();
        {
            const float4* src = (const float4*)(Vg + kc * 4096);
            float4* dst = (float4*)KV;
            for (int i = tid; i < 1024; i += 256) dst[i] = src[i];
        }
        __syncthreads();
        #pragma unroll 4
        for (int i = 0; i < 128; i++) {
            float p = sc[l * SCS + kc * 128 + i];
            float4 vv = *(const float4*)(KV + i * 32 + w * 4);
            acc[0] += p * vv.x; acc[1] += p * vv.y;
            acc[2] += p * vv.z; acc[3] += p * vv.w;
        }
    }
    float is = invs[l];
    __syncthreads();
    #pragma unroll
    for (int j = 0; j < 4; j++) Qs[l * 33 + w * 4 + j] = acc[j] * is;
    __syncthreads();
    {
        int q = tid >> 3, dsub = (tid & 7) * 4;
        float4 ov = make_float4(Qs[q*33+dsub], Qs[q*33+dsub+1],
                                Qs[q*33+dsub+2], Qs[q*33+dsub+3]);
        *(float4*)(g_ctx + (size_t)(b * SS + qt * 32 + q) * DD + h * DHD + dsub) = ov;
    }
}

// ---------------- residual + LayerNorm (in place on g_h) --------------------
__global__ void add_ln_kernel(const float* __restrict__ add,
                              const float* __restrict__ gamma,
                              const float* __restrict__ beta)
{
    int n = blockIdx.x, d = threadIdx.x;
    float v = g_h[(size_t)n * DD + d] + add[(size_t)n * DD + d];

    __shared__ float ws[8];
    __shared__ float s_mu, s_var;

    float sum = v;
    #pragma unroll
    for (int o = 16; o > 0; o >>= 1) sum += __shfl_xor_sync(0xffffffffu, sum, o);
    if ((d & 31) == 0) ws[d >> 5] = sum;
    __syncthreads();
    if (d == 0) {
        float t = 0.f;
        #pragma unroll
        for (int i = 0; i < 8; i++) t += ws[i];
        s_mu = t * (1.0f / DD);
    }
    __syncthreads();
    float c = v - s_mu;
    float sq = c * c;
    #pragma unroll
    for (int o = 16; o > 0; o >>= 1) sq += __shfl_xor_sync(0xffffffffu, sq, o);
    if ((d & 31) == 0) ws[d >> 5] = sq;
    __syncthreads();
    if (d == 0) {
        float t = 0.f;
        #pragma unroll
        for (int i = 0; i < 8; i++) t += ws[i];
        s_var = t * (1.0f / DD);
    }
    __syncthreads();
    g_h[(size_t)n * DD + d] = c * rsqrtf(s_var + 1e-5f) * gamma[d] + beta[d];
}

// ---------------- gate + routing bookkeeping --------------------------------
__global__ void zero_cnt_kernel()
{
    if (threadIdx.x < NEXP) g_cnt[threadIdx.x] = 0;
}

__global__ void gate_kernel(const float* __restrict__ gw, const float* __restrict__ gb)
{
    int n = blockIdx.x, tid = threadIdx.x;
    int e = tid >> 5, lane = tid & 31;
    const float* xp = &g_h[(size_t)n * DD];
    float s = 0.f;
    for (int d = lane; d < DD; d += 32) s += gw[e * DD + d] * xp[d];
    #pragma unroll
    for (int o = 16; o > 0; o >>= 1) s += __shfl_down_sync(0xffffffffu, s, o);
    __shared__ float logits[NEXP];
    if (lane == 0) logits[e] = s + gb[e];
    __syncthreads();
    if (tid == 0) {
        float m = -1e30f;
        #pragma unroll
        for (int i = 0; i < NEXP; i++) m = fmaxf(m, logits[i]);
        float p[NEXP], sum = 0.f;
        #pragma unroll
        for (int i = 0; i < NEXP; i++) { p[i] = expf(logits[i] - m); sum += p[i]; }
        int bi = 0; float bw = p[0];
        #pragma unroll
        for (int i = 1; i < NEXP; i++) if (p[i] > bw) { bw = p[i]; bi = i; }
        g_eidx[n] = bi;
        g_ew[n]   = bw / sum;
        atomicAdd(&g_cnt[bi], 1);
    }
}

__global__ void prefix_kernel()
{
    if (threadIdx.x == 0) {
        int acc = 0;
        #pragma unroll
        for (int e = 0; e < NEXP; e++) {
            g_base[e] = acc; g_cursor[e] = acc; acc += g_cnt[e];
        }
    }
}

__global__ void scatter_kernel()
{
    int n = blockIdx.x * blockDim.x + threadIdx.x;
    if (n < NTOK) {
        int e = g_eidx[n];
        int pos = atomicAdd(&g_cursor[e], 1);
        g_perm[pos] = n;
    }
}

// ---------------- masked mean pool + fc1(relu) + fc2 -------------------------
__global__ void head_kernel(const float* __restrict__ fc1w, const float* __restrict__ fc1b,
                            const float* __restrict__ fc2w, const float* __restrict__ fc2b,
                            float* __restrict__ out)
{
    int b = blockIdx.x, tid = threadIdx.x;
    __shared__ float pooled[DD];
    __shared__ float z[128];

    float s = 0.f;
    int cnt = 0;
    for (int si = 0; si < SS; si++) {
        int n = b * SS + si;
        if (!g_pad[n]) { s += g_h[(size_t)n * DD + tid]; cnt++; }
    }
    pooled[tid] = s / fmaxf((float)cnt, 1.0f);
    __syncthreads();

    if (tid < 128) {
        float a = fc1b[tid];
        const float* wr = fc1w + (size_t)tid * DD;
        #pragma unroll 8
        for (int d = 0; d < DD; d++) a += pooled[d] * wr[d];
        z[tid] = fmaxf(a, 0.f);
    }
    __syncthreads();
    if (tid < 2) {
        float a = fc2b[tid];
        const float* wr = fc2w + (size_t)tid * 128;
        #pragma unroll 8
        for (int i = 0; i < 128; i++) a += z[i] * wr[i];
        out[b * 2 + tid] = a;
    }
}

// ---------------- host launch ------------------------------------------------
static float* sym_addr(const void* sym)
{
    void* p = nullptr;
    cudaGetSymbolAddress(&p, sym);
    return (float*)p;
}

extern "C" void kernel_launch(void* const* d_in, const int* in_sizes, int n_in,
                              void* d_out, int out_size)
{
    const int*   x          = (const int*)  d_in[0];
    const float* emb        = (const float*)d_in[1];
    const float* in_proj_w  = (const float*)d_in[2];
    const float* in_proj_b  = (const float*)d_in[3];
    const float* out_proj_w = (const float*)d_in[4];
    const float* out_proj_b = (const float*)d_in[5];
    const float* ln1_g      = (const float*)d_in[6];
    const float* ln1_b      = (const float*)d_in[7];
    const float* ln2_g      = (const float*)d_in[8];
    const float* ln2_b      = (const float*)d_in[9];
    const float* gate_w     = (const float*)d_in[10];
    const float* gate_b     = (const float*)d_in[11];
    const float* w1         = (const float*)d_in[12];
    const float* b1         = (const float*)d_in[13];
    const float* w2         = (const float*)d_in[14];
    const float* b2         = (const float*)d_in[15];
    const float* fc1_w      = (const float*)d_in[16];
    const float* fc1_b      = (const float*)d_in[17];
    const float* fc2_w      = (const float*)d_in[18];
    const float* fc2_b      = (const float*)d_in[19];
    float* out = (float*)d_out;

    float* p_h   = sym_addr(g_h);
    float* p_ctx = sym_addr(g_ctx);
    float* p_tmp = sym_addr(g_tmp);

    int attn_smem = (32 * SCS + 4096 + 32 * 33 + 32) * 4 + 512 * 4;
    cudaFuncSetAttribute(attn_kernel, cudaFuncAttributeMaxDynamicSharedMemorySize, attn_smem);

    pe_kernel<<<SS, DD>>>();
    embed_kernel<<<NTOK, DD>>>(x, emb);

    for (int l = 0; l < NLAY; l++) {
        gemm_qkv_mma<<<dim3(3*DD/64, NTOK/128), 256>>>(
            p_h, in_proj_w + (size_t)l * 3*DD*DD, in_proj_b + (size_t)l * 3*DD);

        attn_kernel<<<dim3(SS/32, HH, BB), 256, attn_smem>>>();

        gemm_mma<<<dim3(DD/64, NTOK/128), 256>>>(
            p_ctx, out_proj_w + (size_t)l * DD*DD, out_proj_b + (size_t)l * DD,
            p_tmp, DD, DD);

        add_ln_kernel<<<NTOK, DD>>>(p_tmp, ln1_g + (size_t)l * DD, ln1_b + (size_t)l * DD);

        zero_cnt_kernel<<<1, 32>>>();
        gate_kernel<<<NTOK, 256>>>(gate_w + (size_t)l * NEXP*DD, gate_b + (size_t)l * NEXP);
        prefix_kernel<<<1, 32>>>();
        scatter_kernel<<<NTOK/256, 256>>>();

        moe_gemm1_mma<<<dim3(EHID/64, NEXP*64), 256>>>(
            w1 + (size_t)l * NEXP*EHID*DD, b1 + (size_t)l * NEXP*EHID);
        moe_gemm2_mma<<<dim3(DD/64, NEXP*64), 256>>>(
            w2 + (size_t)l * NEXP*DD*EHID, b2 + (size_t)l * NEXP*DD);

        add_ln_kernel<<<NTOK, DD>>>(p_tmp, ln2_g + (size_t)l * DD, ln2_b + (size_t)l * DD);
    }

    head_kernel<<<BB, 256>>>(fc1_w, fc1_b, fc2_w, fc2_b, out);
}

// round 4
// speedup vs baseline: 21.1789x; 1.4532x over previous
#include <cuda_runtime.h>
#include <cuda_fp16.h>
#include <math.h>
#include <stdint.h>

// ---------------- model dims ----------------
#define BB    16
#define SS    512
#define DD    256
#define HH    8
#define DHD   32
#define NLAY  2
#define NEXP  8
#define EHID  1024
#define NTOK  (BB*SS)   // 8192

// ---------------- scratch (static device globals) ---------------------------
__device__ float g_h   [NTOK*DD];
__device__ float g_qkv [NTOK*3*DD];   // split: Q | K | V, each [B][H][S][32]
__device__ float g_ctx [NTOK*DD];
__device__ float g_tmp [NTOK*DD];
__device__ float g_h1  [NTOK*EHID];   // MoE hidden (permuted row order)
__device__ float g_pe  [SS*DD];       // positional encoding table
__device__ int   g_pad [NTOK];
__device__ int   g_eidx[NTOK];
__device__ float g_ew  [NTOK];
__device__ int   g_cnt [NEXP];
__device__ int   g_base[NEXP];
__device__ int   g_cursor[NEXP];
__device__ int   g_perm[NTOK];

#define QKV_HSZ (BB*HH*SS*DHD)   // 2097152

// ---------------- tf32 / mma helpers ----------------------------------------
__device__ __forceinline__ uint32_t f2tf(float x)
{
    uint32_t r;
    asm("cvt.rna.tf32.f32 %0, %1;" : "=r"(r) : "f"(x));
    return r;
}

__device__ __forceinline__ void mma_tf32(float* d, const uint32_t* a, const uint32_t* b)
{
    asm volatile(
        "mma.sync.aligned.m16n8k8.row.col.f32.tf32.tf32.f32 "
        "{%0,%1,%2,%3}, {%4,%5,%6,%7}, {%8,%9}, {%0,%1,%2,%3};\n"
        : "+f"(d[0]), "+f"(d[1]), "+f"(d[2]), "+f"(d[3])
        : "r"(a[0]), "r"(a[1]), "r"(a[2]), "r"(a[3]),
          "r"(b[0]), "r"(b[1]));
}

__device__ __forceinline__ void mma_f16(float* d, uint32_t a0, uint32_t a1,
                                        uint32_t a2, uint32_t a3,
                                        uint32_t b0, uint32_t b1)
{
    asm volatile(
        "mma.sync.aligned.m16n8k16.row.col.f32.f16.f16.f32 "
        "{%0,%1,%2,%3}, {%4,%5,%6,%7}, {%8,%9}, {%0,%1,%2,%3};\n"
        : "+f"(d[0]), "+f"(d[1]), "+f"(d[2]), "+f"(d[3])
        : "r"(a0), "r"(a1), "r"(a2), "r"(a3), "r"(b0), "r"(b1));
}

// fast exp on the FMA pipe (no MUFU): exp(x) = 2^k * 2^r, valid for x <= 0
__device__ __forceinline__ float fexp(float x)
{
    x = fmaxf(x, -87.0f);
    const float L2E = 1.4426950408889634f;
    float t  = fmaf(x, L2E, 12582912.0f);         // round-to-nearest-int trick
    int   ki = __float_as_int(t) - 0x4B400000;    // k as int (no F2I)
    float kf = t - 12582912.0f;
    float r  = fmaf(x, L2E, -kf);                 // r in [-0.5, 0.5]
    float p  = 1.3333558146e-3f;
    p = fmaf(p, r, 9.6181291076e-3f);
    p = fmaf(p, r, 5.5504108664e-2f);
    p = fmaf(p, r, 2.4022650696e-1f);
    p = fmaf(p, r, 6.9314718056e-1f);
    p = fmaf(p, r, 1.0f);
    return p * __int_as_float((ki + 127) << 23);
}

__device__ __forceinline__ uint32_t packh2(float a, float b)
{
    __half2 h = __floats2half2_rn(a, b);
    return *(uint32_t*)&h;
}

// smem strides (uint32 elements), pad 20 -> conflict-free frags + 16B aligned
#define ASTR 20

// Core 128x64 tile mainloop (tf32 gemms).
__device__ __forceinline__ void gemm_tile_mainloop(
    const float* __restrict__ arow0, const float* __restrict__ arow1,
    const float* __restrict__ W, int K,
    uint32_t* As, uint32_t* Ws, float acc[2][4][4])
{
    int tid  = threadIdx.x;
    int lane = tid & 31;
    int warp = tid >> 5;
    int wm = warp & 3, wn = warp >> 2;     // 4 x 2 warp grid
    int r  = tid >> 2;                     // 0..63
    int kc = (tid & 3) * 4;

    for (int k0 = 0; k0 < K; k0 += 16) {
        float4 a0 = *(const float4*)(arow0 + k0 + kc);
        float4 a1 = *(const float4*)(arow1 + k0 + kc);
        float4 w0 = *(const float4*)(W + (size_t)r * K + k0 + kc);
        uint4 ua0 = make_uint4(f2tf(a0.x), f2tf(a0.y), f2tf(a0.z), f2tf(a0.w));
        uint4 ua1 = make_uint4(f2tf(a1.x), f2tf(a1.y), f2tf(a1.z), f2tf(a1.w));
        uint4 uw0 = make_uint4(f2tf(w0.x), f2tf(w0.y), f2tf(w0.z), f2tf(w0.w));
        *(uint4*)(As + r * ASTR + kc)        = ua0;
        *(uint4*)(As + (r + 64) * ASTR + kc) = ua1;
        *(uint4*)(Ws + r * ASTR + kc)        = uw0;
        __syncthreads();

        #pragma unroll
        for (int kh = 0; kh < 2; kh++) {
            uint32_t afr[2][4], bfr[4][2];
            #pragma unroll
            for (int mt = 0; mt < 2; mt++) {
                int rb = wm * 32 + mt * 16 + (lane >> 2);
                int cb = kh * 8 + (lane & 3);
                afr[mt][0] = As[(rb    ) * ASTR + cb];
                afr[mt][1] = As[(rb + 8) * ASTR + cb];
                afr[mt][2] = As[(rb    ) * ASTR + cb + 4];
                afr[mt][3] = As[(rb + 8) * ASTR + cb + 4];
            }
            #pragma unroll
            for (int nt = 0; nt < 4; nt++) {
                int nb = wn * 32 + nt * 8 + (lane >> 2);
                int cb = kh * 8 + (lane & 3);
                bfr[nt][0] = Ws[nb * ASTR + cb];
                bfr[nt][1] = Ws[nb * ASTR + cb + 4];
            }
            #pragma unroll
            for (int mt = 0; mt < 2; mt++)
                #pragma unroll
                for (int nt = 0; nt < 4; nt++)
                    mma_tf32(acc[mt][nt], afr[mt], bfr[nt]);
        }
        __syncthreads();
    }
}

// ---------------- positional encoding table ----------------------------------
__global__ void pe_kernel()
{
    int s = blockIdx.x, d = threadIdx.x;
    double freq = exp(-(double)(d & ~1) * (log(10000.0) / (double)DD));
    double arg  = (double)s * freq;
    g_pe[s * DD + d] = (d & 1) ? (float)cos(arg) : (float)sin(arg);
}

// ---------------- embedding + pad mask ---------------------------------------
__global__ void embed_kernel(const int* __restrict__ x, const float* __restrict__ emb)
{
    int n = blockIdx.x;
    int d = threadIdx.x;
    int tok = x[n];
    int s = n & (SS - 1);

    float v = emb[(size_t)tok * DD + d] * 16.0f + g_pe[s * DD + d];
    g_h[(size_t)n * DD + d] = v;

    float sum = v;
    #pragma unroll
    for (int o = 16; o > 0; o >>= 1) sum += __shfl_xor_sync(0xffffffffu, sum, o);
    __shared__ float ws[8];
    if ((d & 31) == 0) ws[d >> 5] = sum;
    __syncthreads();
    if (d == 0) {
        float t = 0.f;
        #pragma unroll
        for (int i = 0; i < 8; i++) t += ws[i];
        g_pad[n] = (t == 0.0f) ? 1 : 0;
    }
}

// ---------------- QKV GEMM (tf32 mma) + split head-major store ---------------
__global__ void gemm_qkv_mma(const float* __restrict__ A,
                             const float* __restrict__ W,
                             const float* __restrict__ bias)
{
    __shared__ uint32_t As[128 * ASTR];
    __shared__ uint32_t Ws[64 * ASTR];

    int tid = threadIdx.x, lane = tid & 31, warp = tid >> 5;
    int wm = warp & 3, wn = warp >> 2;
    int m0 = blockIdx.y * 128, n0 = blockIdx.x * 64;

    float acc[2][4][4] = {};
    const float* arow0 = A + (size_t)(m0 + (tid >> 2)) * DD;
    const float* arow1 = arow0 + (size_t)64 * DD;

    gemm_tile_mainloop(arow0, arow1, W + (size_t)n0 * DD, DD, As, Ws, acc);

    #pragma unroll
    for (int mt = 0; mt < 2; mt++) {
        #pragma unroll
        for (int nt = 0; nt < 4; nt++) {
            int r0 = m0 + wm * 32 + mt * 16 + (lane >> 2);
            int c0 = n0 + wn * 32 + nt * 8 + 2 * (lane & 3);
            int t = c0 >> 8, h = (c0 >> 5) & 7, d = c0 & 31;
            #pragma unroll
            for (int half = 0; half < 2; half++) {
                int row = r0 + half * 8;
                int b = row >> 9, s = row & (SS - 1);
                size_t dst = (size_t)t * QKV_HSZ
                           + ((size_t)((b * HH + h) * SS + s)) * DHD + d;
                float2 v = make_float2(acc[mt][nt][half * 2 + 0] + bias[c0],
                                       acc[mt][nt][half * 2 + 1] + bias[c0 + 1]);
                *(float2*)(g_qkv + dst) = v;
            }
        }
    }
}

// ---------------- generic GEMM (tf32 mma): C = A @ W^T + bias ----------------
__global__ void gemm_mma(const float* __restrict__ A,
                         const float* __restrict__ W,
                         const float* __restrict__ bias,
                         float* __restrict__ C, int Nc, int K)
{
    __shared__ uint32_t As[128 * ASTR];
    __shared__ uint32_t Ws[64 * ASTR];

    int tid = threadIdx.x, lane = tid & 31, warp = tid >> 5;
    int wm = warp & 3, wn = warp >> 2;
    int m0 = blockIdx.y * 128, n0 = blockIdx.x * 64;

    float acc[2][4][4] = {};
    const float* arow0 = A + (size_t)(m0 + (tid >> 2)) * K;
    const float* arow1 = arow0 + (size_t)64 * K;

    gemm_tile_mainloop(arow0, arow1, W + (size_t)n0 * K, K, As, Ws, acc);

    #pragma unroll
    for (int mt = 0; mt < 2; mt++) {
        #pragma unroll
        for (int nt = 0; nt < 4; nt++) {
            int r0 = m0 + wm * 32 + mt * 16 + (lane >> 2);
            int c0 = n0 + wn * 32 + nt * 8 + 2 * (lane & 3);
            float bx = bias[c0], by = bias[c0 + 1];
            #pragma unroll
            for (int half = 0; half < 2; half++) {
                int row = r0 + half * 8;
                float2 v = make_float2(acc[mt][nt][half * 2 + 0] + bx,
                                       acc[mt][nt][half * 2 + 1] + by);
                *(float2*)(C + (size_t)row * Nc + c0) = v;
            }
        }
    }
}

// ---------------- MoE GEMM1 (tf32 mma): H = relu(Xperm @ W1[e]^T + b1) -------
__global__ void moe_gemm1_mma(const float* __restrict__ w1, const float* __restrict__ b1)
{
    int y = blockIdx.y;
    int e = y >> 6, tile = y & 63;
    int cnt = g_cnt[e];
    if (tile * 128 >= cnt) return;
    int ebase = g_base[e];

    __shared__ uint32_t As[128 * ASTR];
    __shared__ uint32_t Ws[64 * ASTR];
    __shared__ int toks[128];

    int tid = threadIdx.x, lane = tid & 31, warp = tid >> 5;
    int wm = warp & 3, wn = warp >> 2;

    if (tid < 128) {
        int rr = tile * 128 + tid;
        toks[tid] = g_perm[ebase + ((rr < cnt) ? rr : (cnt - 1))];
    }
    __syncthreads();

    int n0 = blockIdx.x * 64;
    float acc[2][4][4] = {};
    const float* arow0 = g_h + (size_t)toks[tid >> 2] * DD;
    const float* arow1 = g_h + (size_t)toks[(tid >> 2) + 64] * DD;

    gemm_tile_mainloop(arow0, arow1, w1 + (size_t)e * EHID * DD + (size_t)n0 * DD,
                       DD, As, Ws, acc);

    #pragma unroll
    for (int mt = 0; mt < 2; mt++) {
        #pragma unroll
        for (int nt = 0; nt < 4; nt++) {
            int lr0 = wm * 32 + mt * 16 + (lane >> 2);
            int c0  = n0 + wn * 32 + nt * 8 + 2 * (lane & 3);
            float bx = b1[e * EHID + c0], by = b1[e * EHID + c0 + 1];
            #pragma unroll
            for (int half = 0; half < 2; half++) {
                int lr = lr0 + half * 8;
                int gr = tile * 128 + lr;
                if (gr < cnt) {
                    float2 v = make_float2(
                        fmaxf(acc[mt][nt][half * 2 + 0] + bx, 0.f),
                        fmaxf(acc[mt][nt][half * 2 + 1] + by, 0.f));
                    *(float2*)(g_h1 + (size_t)(ebase + gr) * EHID + c0) = v;
                }
            }
        }
    }
}

// ---------------- MoE GEMM2 (tf32 mma): Y = gw*(H @ W2[e]^T + b2) ------------
__global__ void moe_gemm2_mma(const float* __restrict__ w2, const float* __restrict__ b2)
{
    int y = blockIdx.y;
    int e = y >> 6, tile = y & 63;
    int cnt = g_cnt[e];
    if (tile * 128 >= cnt) return;
    int ebase = g_base[e];

    __shared__ uint32_t As[128 * ASTR];
    __shared__ uint32_t Ws[64 * ASTR];

    int tid = threadIdx.x, lane = tid & 31, warp = tid >> 5;
    int wm = warp & 3, wn = warp >> 2;

    int n0 = blockIdx.x * 64;
    float acc[2][4][4] = {};

    int r  = tid >> 2;
    int gr0 = tile * 128 + r;       if (gr0 >= cnt) gr0 = cnt - 1;
    int gr1 = tile * 128 + r + 64;  if (gr1 >= cnt) gr1 = cnt - 1;
    const float* arow0 = g_h1 + (size_t)(ebase + gr0) * EHID;
    const float* arow1 = g_h1 + (size_t)(ebase + gr1) * EHID;

    gemm_tile_mainloop(arow0, arow1, w2 + (size_t)e * DD * EHID + (size_t)n0 * EHID,
                       EHID, As, Ws, acc);

    #pragma unroll
    for (int mt = 0; mt < 2; mt++) {
        #pragma unroll
        for (int nt = 0; nt < 4; nt++) {
            int lr0 = wm * 32 + mt * 16 + (lane >> 2);
            int c0  = n0 + wn * 32 + nt * 8 + 2 * (lane & 3);
            float bx = b2[e * DD + c0], by = b2[e * DD + c0 + 1];
            #pragma unroll
            for (int half = 0; half < 2; half++) {
                int lr = lr0 + half * 8;
                int gr = tile * 128 + lr;
                if (gr < cnt) {
                    int token = g_perm[ebase + gr];
                    float gwv = g_ew[token];
                    float2 v = make_float2(gwv * (acc[mt][nt][half * 2 + 0] + bx),
                                           gwv * (acc[mt][nt][half * 2 + 1] + by));
                    *(float2*)(g_tmp + (size_t)token * DD + c0) = v;
                }
            }
        }
    }
}

// ---------------- flash attention (tensor cores + poly exp) ------------------
// block = (qtile of 128, h, b); 256 threads = 8 warps; warp w owns q rows w*16..
#define QTILE 128
#define KCH   64
#define QSTR  36   // tf32 row stride
#define VSTR  72   // half row stride for V^T

__global__ void attn_fa_kernel()
{
    __shared__ uint32_t Qs[QTILE * QSTR];   // Q tf32 (scaled by 1/sqrt(dh))
    __shared__ uint32_t Ks[KCH * QSTR];     // K chunk tf32
    __shared__ __half   Vt[DHD * VSTR];     // V chunk transposed, fp16
    __shared__ int      mk[KCH];            // pad flags

    int qt = blockIdx.x, h = blockIdx.y, b = blockIdx.z;
    int tid = threadIdx.x, lane = tid & 31, w = tid >> 5;
    int g = lane >> 2, T = lane & 3;

    const float* Qg = g_qkv + ((size_t)((b * HH + h) * SS + qt * QTILE)) * DHD;
    const float* Kg = g_qkv + (size_t)QKV_HSZ     + ((size_t)((b * HH + h) * SS)) * DHD;
    const float* Vg = g_qkv + (size_t)2 * QKV_HSZ + ((size_t)((b * HH + h) * SS)) * DHD;

    const float inv = 0.17677669529663689f;   // 1/sqrt(32)

    // load Q (scaled, tf32): 1024 float4
    for (int i = tid; i < QTILE * 8; i += 256) {
        float4 v = ((const float4*)Qg)[i];
        int row = i >> 3, c = (i & 7) * 4;
        Qs[row * QSTR + c + 0] = f2tf(v.x * inv);
        Qs[row * QSTR + c + 1] = f2tf(v.y * inv);
        Qs[row * QSTR + c + 2] = f2tf(v.z * inv);
        Qs[row * QSTR + c + 3] = f2tf(v.w * inv);
    }

    float m_[2]  = {-1e30f, -1e30f};
    float sum_[2] = {0.f, 0.f};
    float o[4][4] = {};

    for (int kc = 0; kc < SS / KCH; kc++) {
        __syncthreads();   // protect smem from previous iteration readers
        for (int i = tid; i < KCH * 8; i += 256) {
            float4 v = ((const float4*)(Kg + kc * KCH * DHD))[i];
            int row = i >> 3, c = (i & 7) * 4;
            Ks[row * QSTR + c + 0] = f2tf(v.x);
            Ks[row * QSTR + c + 1] = f2tf(v.y);
            Ks[row * QSTR + c + 2] = f2tf(v.z);
            Ks[row * QSTR + c + 3] = f2tf(v.w);
        }
        for (int i = tid; i < KCH * 8; i += 256) {
            float4 v = ((const float4*)(Vg + kc * KCH * DHD))[i];
            int key = i >> 3, c = (i & 7) * 4;
            Vt[(c + 0) * VSTR + key] = __float2half(v.x);
            Vt[(c + 1) * VSTR + key] = __float2half(v.y);
            Vt[(c + 2) * VSTR + key] = __float2half(v.z);
            Vt[(c + 3) * VSTR + key] = __float2half(v.w);
        }
        if (tid < KCH) mk[tid] = g_pad[b * SS + kc * KCH + tid];
        __syncthreads();

        // ---- S = Q K^T (tf32): 8 n-tiles x 4 k-steps ----
        float s[8][4];
        #pragma unroll
        for (int nt = 0; nt < 8; nt++)
            #pragma unroll
            for (int j = 0; j < 4; j++) s[nt][j] = 0.f;

        #pragma unroll
        for (int ks = 0; ks < 4; ks++) {
            uint32_t af[4];
            int row = w * 16 + g, col = ks * 8 + T;
            af[0] = Qs[row * QSTR + col];
            af[1] = Qs[(row + 8) * QSTR + col];
            af[2] = Qs[row * QSTR + col + 4];
            af[3] = Qs[(row + 8) * QSTR + col + 4];
            #pragma unroll
            for (int nt = 0; nt < 8; nt++) {
                uint32_t bf[2];
                int kr = nt * 8 + g;
                bf[0] = Ks[kr * QSTR + ks * 8 + T];
                bf[1] = Ks[kr * QSTR + ks * 8 + T + 4];
                mma_tf32(s[nt], af, bf);
            }
        }

        // ---- mask (cols 2T, 2T+1 per n-tile) ----
        #pragma unroll
        for (int nt = 0; nt < 8; nt++) {
            if (mk[nt * 8 + 2 * T])     { s[nt][0] = -1e9f; s[nt][2] = -1e9f; }
            if (mk[nt * 8 + 2 * T + 1]) { s[nt][1] = -1e9f; s[nt][3] = -1e9f; }
        }

        // ---- online softmax per row-half (c0,c1 -> row g ; c2,c3 -> row g+8) ----
        #pragma unroll
        for (int half = 0; half < 2; half++) {
            float cmax = -1e30f;
            #pragma unroll
            for (int nt = 0; nt < 8; nt++)
                cmax = fmaxf(cmax, fmaxf(s[nt][2 * half], s[nt][2 * half + 1]));
            cmax = fmaxf(cmax, __shfl_xor_sync(0xffffffffu, cmax, 1));
            cmax = fmaxf(cmax, __shfl_xor_sync(0xffffffffu, cmax, 2));
            float mnew  = fmaxf(m_[half], cmax);
            float scale = fexp(m_[half] - mnew);
            m_[half] = mnew;
            float part = 0.f;
            #pragma unroll
            for (int nt = 0; nt < 8; nt++) {
                float p0 = fexp(s[nt][2 * half]     - mnew);
                float p1 = fexp(s[nt][2 * half + 1] - mnew);
                s[nt][2 * half] = p0; s[nt][2 * half + 1] = p1;
                part += p0 + p1;
            }
            part += __shfl_xor_sync(0xffffffffu, part, 1);
            part += __shfl_xor_sync(0xffffffffu, part, 2);
            sum_[half] = sum_[half] * scale + part;
            #pragma unroll
            for (int nt = 0; nt < 4; nt++) {
                o[nt][2 * half]     *= scale;
                o[nt][2 * half + 1] *= scale;
            }
        }

        // ---- O += P @ V : P (f16) from S frags, V from Vt ----
        #pragma unroll
        for (int kt = 0; kt < 4; kt++) {
            uint32_t a0 = packh2(s[2 * kt][0],     s[2 * kt][1]);
            uint32_t a1 = packh2(s[2 * kt][2],     s[2 * kt][3]);
            uint32_t a2 = packh2(s[2 * kt + 1][0], s[2 * kt + 1][1]);
            uint32_t a3 = packh2(s[2 * kt + 1][2], s[2 * kt + 1][3]);
            #pragma unroll
            for (int nt = 0; nt < 4; nt++) {
                const __half* vp = &Vt[(nt * 8 + g) * VSTR + kt * 16 + 2 * T];
                uint32_t b0 = *(const uint32_t*)vp;
                uint32_t b1 = *(const uint32_t*)(vp + 8);
                mma_f16(o[nt], a0, a1, a2, a3, b0, b1);
            }
        }
    }

    // ---- finalize + store ----
    float i0 = 1.0f / sum_[0];
    float i1 = 1.0f / sum_[1];
    int q0 = qt * QTILE + w * 16 + g;
    #pragma unroll
    for (int nt = 0; nt < 4; nt++) {
        int col = h * DHD + nt * 8 + 2 * T;
        float2 v0 = make_float2(o[nt][0] * i0, o[nt][1] * i0);
        float2 v1 = make_float2(o[nt][2] * i1, o[nt][3] * i1);
        *(float2*)(g_ctx + (size_t)(b * SS + q0) * DD + col)     = v0;
        *(float2*)(g_ctx + (size_t)(b * SS + q0 + 8) * DD + col) = v1;
    }
}

// ---------------- residual + LayerNorm (in place on g_h) --------------------
__global__ void add_ln_kernel(const float* __restrict__ add,
                              const float* __restrict__ gamma,
                              const float* __restrict__ beta)
{
    int n = blockIdx.x, d = threadIdx.x;
    float v = g_h[(size_t)n * DD + d] + add[(size_t)n * DD + d];

    __shared__ float ws[8];
    __shared__ float s_mu, s_var;

    float sum = v;
    #pragma unroll
    for (int o = 16; o > 0; o >>= 1) sum += __shfl_xor_sync(0xffffffffu, sum, o);
    if ((d & 31) == 0) ws[d >> 5] = sum;
    __syncthreads();
    if (d == 0) {
        float t = 0.f;
        #pragma unroll
        for (int i = 0; i < 8; i++) t += ws[i];
        s_mu = t * (1.0f / DD);
    }
    __syncthreads();
    float c = v - s_mu;
    float sq = c * c;
    #pragma unroll
    for (int o = 16; o > 0; o >>= 1) sq += __shfl_xor_sync(0xffffffffu, sq, o);
    if ((d & 31) == 0) ws[d >> 5] = sq;
    __syncthreads();
    if (d == 0) {
        float t = 0.f;
        #pragma unroll
        for (int i = 0; i < 8; i++) t += ws[i];
        s_var = t * (1.0f / DD);
    }
    __syncthreads();
    g_h[(size_t)n * DD + d] = c * rsqrtf(s_var + 1e-5f) * gamma[d] + beta[d];
}

// ---------------- gate + routing bookkeeping --------------------------------
__global__ void zero_cnt_kernel()
{
    if (threadIdx.x < NEXP) g_cnt[threadIdx.x] = 0;
}

__global__ void gate_kernel(const float* __restrict__ gw, const float* __restrict__ gb)
{
    int n = blockIdx.x, tid = threadIdx.x;
    int e = tid >> 5, lane = tid & 31;
    const float* xp = &g_h[(size_t)n * DD];
    float s = 0.f;
    for (int d = lane; d < DD; d += 32) s += gw[e * DD + d] * xp[d];
    #pragma unroll
    for (int o = 16; o > 0; o >>= 1) s += __shfl_down_sync(0xffffffffu, s, o);
    __shared__ float logits[NEXP];
    if (lane == 0) logits[e] = s + gb[e];
    __syncthreads();
    if (tid == 0) {
        float m = -1e30f;
        #pragma unroll
        for (int i = 0; i < NEXP; i++) m = fmaxf(m, logits[i]);
        float p[NEXP], sum = 0.f;
        #pragma unroll
        for (int i = 0; i < NEXP; i++) { p[i] = expf(logits[i] - m); sum += p[i]; }
        int bi = 0; float bw = p[0];
        #pragma unroll
        for (int i = 1; i < NEXP; i++) if (p[i] > bw) { bw = p[i]; bi = i; }
        g_eidx[n] = bi;
        g_ew[n]   = bw / sum;
        atomicAdd(&g_cnt[bi], 1);
    }
}

__global__ void prefix_kernel()
{
    if (threadIdx.x == 0) {
        int acc = 0;
        #pragma unroll
        for (int e = 0; e < NEXP; e++) {
            g_base[e] = acc; g_cursor[e] = acc; acc += g_cnt[e];
        }
    }
}

__global__ void scatter_kernel()
{
    int n = blockIdx.x * blockDim.x + threadIdx.x;
    if (n < NTOK) {
        int e = g_eidx[n];
        int pos = atomicAdd(&g_cursor[e], 1);
        g_perm[pos] = n;
    }
}

// ---------------- masked mean pool + fc1(relu) + fc2 -------------------------
__global__ void head_kernel(const float* __restrict__ fc1w, const float* __restrict__ fc1b,
                            const float* __restrict__ fc2w, const float* __restrict__ fc2b,
                            float* __restrict__ out)
{
    int b = blockIdx.x, tid = threadIdx.x;
    __shared__ float pooled[DD];
    __shared__ float z[128];

    float s = 0.f;
    int cnt = 0;
    for (int si = 0; si < SS; si++) {
        int n = b * SS + si;
        if (!g_pad[n]) { s += g_h[(size_t)n * DD + tid]; cnt++; }
    }
    pooled[tid] = s / fmaxf((float)cnt, 1.0f);
    __syncthreads();

    if (tid < 128) {
        float a = fc1b[tid];
        const float* wr = fc1w + (size_t)tid * DD;
        #pragma unroll 8
        for (int d = 0; d < DD; d++) a += pooled[d] * wr[d];
        z[tid] = fmaxf(a, 0.f);
    }
    __syncthreads();
    if (tid < 2) {
        float a = fc2b[tid];
        const float* wr = fc2w + (size_t)tid * 128;
        #pragma unroll 8
        for (int i = 0; i < 128; i++) a += z[i] * wr[i];
        out[b * 2 + tid] = a;
    }
}

// ---------------- host launch ------------------------------------------------
static float* sym_addr(const void* sym)
{
    void* p = nullptr;
    cudaGetSymbolAddress(&p, sym);
    return (float*)p;
}

extern "C" void kernel_launch(void* const* d_in, const int* in_sizes, int n_in,
                              void* d_out, int out_size)
{
    const int*   x          = (const int*)  d_in[0];
    const float* emb        = (const float*)d_in[1];
    const float* in_proj_w  = (const float*)d_in[2];
    const float* in_proj_b  = (const float*)d_in[3];
    const float* out_proj_w = (const float*)d_in[4];
    const float* out_proj_b = (const float*)d_in[5];
    const float* ln1_g      = (const float*)d_in[6];
    const float* ln1_b      = (const float*)d_in[7];
    const float* ln2_g      = (const float*)d_in[8];
    const float* ln2_b      = (const float*)d_in[9];
    const float* gate_w     = (const float*)d_in[10];
    const float* gate_b     = (const float*)d_in[11];
    const float* w1         = (const float*)d_in[12];
    const float* b1         = (const float*)d_in[13];
    const float* w2         = (const float*)d_in[14];
    const float* b2         = (const float*)d_in[15];
    const float* fc1_w      = (const float*)d_in[16];
    const float* fc1_b      = (const float*)d_in[17];
    const float* fc2_w      = (const float*)d_in[18];
    const float* fc2_b      = (const float*)d_in[19];
    float* out = (float*)d_out;

    float* p_h   = sym_addr(g_h);
    float* p_ctx = sym_addr(g_ctx);
    float* p_tmp = sym_addr(g_tmp);

    pe_kernel<<<SS, DD>>>();
    embed_kernel<<<NTOK, DD>>>(x, emb);

    for (int l = 0; l < NLAY; l++) {
        gemm_qkv_mma<<<dim3(3*DD/64, NTOK/128), 256>>>(
            p_h, in_proj_w + (size_t)l * 3*DD*DD, in_proj_b + (size_t)l * 3*DD);

        attn_fa_kernel<<<dim3(SS/QTILE, HH, BB), 256>>>();

        gemm_mma<<<dim3(DD/64, NTOK/128), 256>>>(
            p_ctx, out_proj_w + (size_t)l * DD*DD, out_proj_b + (size_t)l * DD,
            p_tmp, DD, DD);

        add_ln_kernel<<<NTOK, DD>>>(p_tmp, ln1_g + (size_t)l * DD, ln1_b + (size_t)l * DD);

        zero_cnt_kernel<<<1, 32>>>();
        gate_kernel<<<NTOK, 256>>>(gate_w + (size_t)l * NEXP*DD, gate_b + (size_t)l * NEXP);
        prefix_kernel<<<1, 32>>>();
        scatter_kernel<<<NTOK/256, 256>>>();

        moe_gemm1_mma<<<dim3(EHID/64, NEXP*64), 256>>>(
            w1 + (size_t)l * NEXP*EHID*DD, b1 + (size_t)l * NEXP*EHID);
        moe_gemm2_mma<<<dim3(DD/64, NEXP*64), 256>>>(
            w2 + (size_t)l * NEXP*DD*EHID, b2 + (size_t)l * NEXP*DD);

        add_ln_kernel<<<NTOK, DD>>>(p_tmp, ln2_g + (size_t)l * DD, ln2_b + (size_t)l * DD);
    }

    head_kernel<<<BB, 256>>>(fc1_w, fc1_b, fc2_w, fc2_b, out);
}

// round 5
// speedup vs baseline: 22.0797x; 1.0425x over previous
#include <cuda_runtime.h>
#include <cuda_fp16.h>
#include <math.h>
#include <stdint.h>

// ---------------- model dims ----------------
#define BB    16
#define SS    512
#define DD    256
#define HH    8
#define DHD   32
#define NLAY  2
#define NEXP  8
#define EHID  1024
#define NTOK  (BB*SS)   // 8192

// ---------------- scratch (static device globals) ---------------------------
__device__ float g_h   [NTOK*DD];
__device__ float g_qkv [NTOK*3*DD];   // split: Q | K | V, each [B][H][S][32]
__device__ float g_ctx [NTOK*DD];
__device__ float g_tmp [NTOK*DD];
__device__ float g_h1  [NTOK*EHID];   // MoE hidden (permuted row order)
__device__ float g_pe  [SS*DD];       // positional encoding table
__device__ int   g_pad [NTOK];
__device__ int   g_eidx[NTOK];
__device__ float g_ew  [NTOK];
__device__ int   g_cnt [NEXP];
__device__ int   g_base[NEXP];
__device__ int   g_cursor[NEXP];
__device__ int   g_perm[NTOK];

#define QKV_HSZ (BB*HH*SS*DHD)   // 2097152

// ---------------- mma helpers ------------------------------------------------
__device__ __forceinline__ uint32_t f2tf(float x)
{
    uint32_t r;
    asm("cvt.rna.tf32.f32 %0, %1;" : "=r"(r) : "f"(x));
    return r;
}

__device__ __forceinline__ void mma_tf32(float* d, const uint32_t* a, const uint32_t* b)
{
    asm volatile(
        "mma.sync.aligned.m16n8k8.row.col.f32.tf32.tf32.f32 "
        "{%0,%1,%2,%3}, {%4,%5,%6,%7}, {%8,%9}, {%0,%1,%2,%3};\n"
        : "+f"(d[0]), "+f"(d[1]), "+f"(d[2]), "+f"(d[3])
        : "r"(a[0]), "r"(a[1]), "r"(a[2]), "r"(a[3]),
          "r"(b[0]), "r"(b[1]));
}

__device__ __forceinline__ void mma_f16(float* d, uint32_t a0, uint32_t a1,
                                        uint32_t a2, uint32_t a3,
                                        uint32_t b0, uint32_t b1)
{
    asm volatile(
        "mma.sync.aligned.m16n8k16.row.col.f32.f16.f16.f32 "
        "{%0,%1,%2,%3}, {%4,%5,%6,%7}, {%8,%9}, {%0,%1,%2,%3};\n"
        : "+f"(d[0]), "+f"(d[1]), "+f"(d[2]), "+f"(d[3])
        : "r"(a0), "r"(a1), "r"(a2), "r"(a3), "r"(b0), "r"(b1));
}

// fast exp on the FMA pipe (no MUFU): exp(x) = 2^k * 2^r, valid for x <= 0
__device__ __forceinline__ float fexp(float x)
{
    x = fmaxf(x, -87.0f);
    const float L2E = 1.4426950408889634f;
    float t  = fmaf(x, L2E, 12582912.0f);
    int   ki = __float_as_int(t) - 0x4B400000;
    float kf = t - 12582912.0f;
    float r  = fmaf(x, L2E, -kf);
    float p  = 1.3333558146e-3f;
    p = fmaf(p, r, 9.6181291076e-3f);
    p = fmaf(p, r, 5.5504108664e-2f);
    p = fmaf(p, r, 2.4022650696e-1f);
    p = fmaf(p, r, 6.9314718056e-1f);
    p = fmaf(p, r, 1.0f);
    return p * __int_as_float((ki + 127) << 23);
}

__device__ __forceinline__ uint32_t packh2(float a, float b)
{
    __half2 h = __floats2half2_rn(a, b);
    return *(uint32_t*)&h;
}

__device__ __forceinline__ void cp16(uint32_t dst, const void* src)
{
    asm volatile("cp.async.ca.shared.global [%0], [%1], 16;\n"
                 :: "r"(dst), "l"(src));
}

// ---------------- pipelined 128x128 tf32 GEMM core ---------------------------
// 256 threads, 8 warps in 2x4 (wm x wn). acc[mt 4][nt 4][4].
// A operands are raw fp32 bits fed to tf32 mma (HW uses upper 19 bits).
#define ASTR 20
#define GBUF (128 * ASTR)   // words per stage buffer

__device__ __forceinline__ void pipe_mainloop(
    const float* __restrict__ aptr,   // this thread's A row ptr, pre-offset by qb
    const float* __restrict__ wptr,   // this thread's W row ptr, pre-offset by qb
    int K, uint32_t* AsArr, uint32_t* BsArr, float acc[4][4][4])
{
    int tid = threadIdx.x, lane = tid & 31, w = tid >> 5;
    int wm = w & 1, wn = w >> 1;
    int g = lane >> 2, T = lane & 3;
    int ar = tid >> 1, qb = (tid & 1) * 8;

    uint32_t da = (uint32_t)__cvta_generic_to_shared(AsArr) + (ar * ASTR + qb) * 4;
    uint32_t db = (uint32_t)__cvta_generic_to_shared(BsArr) + (ar * ASTR + qb) * 4;
    const uint32_t BUFB = GBUF * 4;   // bytes per stage

    int KT = K / 16;

    // prefetch stage 0
    cp16(da,      aptr);     cp16(da + 16, aptr + 4);
    cp16(db,      wptr);     cp16(db + 16, wptr + 4);
    asm volatile("cp.async.commit_group;\n");

    for (int kt = 0; kt < KT; kt++) {
        if (kt + 1 < KT) {
            uint32_t off = ((kt + 1) & 1) * BUFB;
            const float* as = aptr + (kt + 1) * 16;
            const float* ws = wptr + (kt + 1) * 16;
            cp16(da + off,      as);     cp16(da + off + 16, as + 4);
            cp16(db + off,      ws);     cp16(db + off + 16, ws + 4);
            asm volatile("cp.async.commit_group;\n");
            asm volatile("cp.async.wait_group 1;\n");
        } else {
            asm volatile("cp.async.wait_group 0;\n");
        }
        __syncthreads();

        const uint32_t* A = AsArr + (kt & 1) * GBUF;
        const uint32_t* B = BsArr + (kt & 1) * GBUF;
        #pragma unroll
        for (int kh = 0; kh < 2; kh++) {
            uint32_t afr[4][4], bfr[4][2];
            #pragma unroll
            for (int mt = 0; mt < 4; mt++) {
                int rb = wm * 64 + mt * 16 + g;
                int cb = kh * 8 + T;
                afr[mt][0] = A[rb * ASTR + cb];
                afr[mt][1] = A[(rb + 8) * ASTR + cb];
                afr[mt][2] = A[rb * ASTR + cb + 4];
                afr[mt][3] = A[(rb + 8) * ASTR + cb + 4];
            }
            #pragma unroll
            for (int nt = 0; nt < 4; nt++) {
                int nb = wn * 32 + nt * 8 + g;
                bfr[nt][0] = B[nb * ASTR + kh * 8 + T];
                bfr[nt][1] = B[nb * ASTR + kh * 8 + T + 4];
            }
            #pragma unroll
            for (int mt = 0; mt < 4; mt++)
                #pragma unroll
                for (int nt = 0; nt < 4; nt++)
                    mma_tf32(acc[mt][nt], afr[mt], bfr[nt]);
        }
        __syncthreads();
    }
}

// ---------------- positional encoding table ----------------------------------
__global__ void pe_kernel()
{
    int s = blockIdx.x, d = threadIdx.x;
    double freq = exp(-(double)(d & ~1) * (log(10000.0) / (double)DD));
    double arg  = (double)s * freq;
    g_pe[s * DD + d] = (d & 1) ? (float)cos(arg) : (float)sin(arg);
}

// ---------------- embedding + pad mask ---------------------------------------
__global__ void embed_kernel(const int* __restrict__ x, const float* __restrict__ emb)
{
    int n = blockIdx.x;
    int d = threadIdx.x;
    int tok = x[n];
    int s = n & (SS - 1);

    float v = emb[(size_t)tok * DD + d] * 16.0f + g_pe[s * DD + d];
    g_h[(size_t)n * DD + d] = v;

    float sum = v;
    #pragma unroll
    for (int o = 16; o > 0; o >>= 1) sum += __shfl_xor_sync(0xffffffffu, sum, o);
    __shared__ float ws[8];
    if ((d & 31) == 0) ws[d >> 5] = sum;
    __syncthreads();
    if (d == 0) {
        float t = 0.f;
        #pragma unroll
        for (int i = 0; i < 8; i++) t += ws[i];
        g_pad[n] = (t == 0.0f) ? 1 : 0;
    }
}

// ---------------- QKV GEMM (pipelined) + split head-major store --------------
__global__ __launch_bounds__(256)
void gemm_qkv_mma(const float* __restrict__ A,
                  const float* __restrict__ W,
                  const float* __restrict__ bias)
{
    __shared__ uint32_t As[2 * GBUF];
    __shared__ uint32_t Bs[2 * GBUF];

    int tid = threadIdx.x, lane = tid & 31, w = tid >> 5;
    int wm = w & 1, wn = w >> 1, g = lane >> 2, T = lane & 3;
    int m0 = blockIdx.y * 128, n0 = blockIdx.x * 128;
    int ar = tid >> 1, qb = (tid & 1) * 8;

    float acc[4][4][4] = {};
    pipe_mainloop(A + (size_t)(m0 + ar) * DD + qb,
                  W + (size_t)(n0 + ar) * DD + qb, DD, As, Bs, acc);

    #pragma unroll
    for (int mt = 0; mt < 4; mt++) {
        #pragma unroll
        for (int nt = 0; nt < 4; nt++) {
            int r0 = m0 + wm * 64 + mt * 16 + g;
            int c0 = n0 + wn * 32 + nt * 8 + 2 * T;
            int t = c0 >> 8, h = (c0 >> 5) & 7, d = c0 & 31;
            float bx = bias[c0], by = bias[c0 + 1];
            #pragma unroll
            for (int half = 0; half < 2; half++) {
                int row = r0 + half * 8;
                int b = row >> 9, s = row & (SS - 1);
                size_t dst = (size_t)t * QKV_HSZ
                           + ((size_t)((b * HH + h) * SS + s)) * DHD + d;
                float2 v = make_float2(acc[mt][nt][half * 2 + 0] + bx,
                                       acc[mt][nt][half * 2 + 1] + by);
                *(float2*)(g_qkv + dst) = v;
            }
        }
    }
}

// ---------------- generic GEMM (pipelined): C = A @ W^T + bias ---------------
__global__ __launch_bounds__(256)
void gemm_mma(const float* __restrict__ A,
              const float* __restrict__ W,
              const float* __restrict__ bias,
              float* __restrict__ C, int Nc, int K)
{
    __shared__ uint32_t As[2 * GBUF];
    __shared__ uint32_t Bs[2 * GBUF];

    int tid = threadIdx.x, lane = tid & 31, w = tid >> 5;
    int wm = w & 1, wn = w >> 1, g = lane >> 2, T = lane & 3;
    int m0 = blockIdx.y * 128, n0 = blockIdx.x * 128;
    int ar = tid >> 1, qb = (tid & 1) * 8;

    float acc[4][4][4] = {};
    pipe_mainloop(A + (size_t)(m0 + ar) * K + qb,
                  W + (size_t)(n0 + ar) * K + qb, K, As, Bs, acc);

    #pragma unroll
    for (int mt = 0; mt < 4; mt++) {
        #pragma unroll
        for (int nt = 0; nt < 4; nt++) {
            int r0 = m0 + wm * 64 + mt * 16 + g;
            int c0 = n0 + wn * 32 + nt * 8 + 2 * T;
            float bx = bias[c0], by = bias[c0 + 1];
            #pragma unroll
            for (int half = 0; half < 2; half++) {
                int row = r0 + half * 8;
                float2 v = make_float2(acc[mt][nt][half * 2 + 0] + bx,
                                       acc[mt][nt][half * 2 + 1] + by);
                *(float2*)(C + (size_t)row * Nc + c0) = v;
            }
        }
    }
}

// ---------------- MoE GEMM1 (pipelined): H = relu(Xperm @ W1[e]^T + b1) ------
__global__ __launch_bounds__(256)
void moe_gemm1_mma(const float* __restrict__ w1, const float* __restrict__ b1)
{
    int y = blockIdx.y;
    int e = y >> 6, tile = y & 63;
    int cnt = g_cnt[e];
    if (tile * 128 >= cnt) return;
    int ebase = g_base[e];

    __shared__ uint32_t As[2 * GBUF];
    __shared__ uint32_t Bs[2 * GBUF];

    int tid = threadIdx.x, lane = tid & 31, w = tid >> 5;
    int wm = w & 1, wn = w >> 1, g = lane >> 2, T = lane & 3;
    int n0 = blockIdx.x * 128;
    int ar = tid >> 1, qb = (tid & 1) * 8;

    int gr = tile * 128 + ar;
    if (gr >= cnt) gr = cnt - 1;
    int token = g_perm[ebase + gr];

    float acc[4][4][4] = {};
    pipe_mainloop(g_h + (size_t)token * DD + qb,
                  w1 + (size_t)e * EHID * DD + (size_t)(n0 + ar) * DD + qb,
                  DD, As, Bs, acc);

    #pragma unroll
    for (int mt = 0; mt < 4; mt++) {
        #pragma unroll
        for (int nt = 0; nt < 4; nt++) {
            int lr0 = wm * 64 + mt * 16 + g;
            int c0  = n0 + wn * 32 + nt * 8 + 2 * T;
            float bx = b1[e * EHID + c0], by = b1[e * EHID + c0 + 1];
            #pragma unroll
            for (int half = 0; half < 2; half++) {
                int grr = tile * 128 + lr0 + half * 8;
                if (grr < cnt) {
                    float2 v = make_float2(
                        fmaxf(acc[mt][nt][half * 2 + 0] + bx, 0.f),
                        fmaxf(acc[mt][nt][half * 2 + 1] + by, 0.f));
                    *(float2*)(g_h1 + (size_t)(ebase + grr) * EHID + c0) = v;
                }
            }
        }
    }
}

// ---------------- MoE GEMM2 (pipelined): Y = gw*(H @ W2[e]^T + b2) -----------
__global__ __launch_bounds__(256)
void moe_gemm2_mma(const float* __restrict__ w2, const float* __restrict__ b2)
{
    int y = blockIdx.y;
    int e = y >> 6, tile = y & 63;
    int cnt = g_cnt[e];
    if (tile * 128 >= cnt) return;
    int ebase = g_base[e];

    __shared__ uint32_t As[2 * GBUF];
    __shared__ uint32_t Bs[2 * GBUF];

    int tid = threadIdx.x, lane = tid & 31, w = tid >> 5;
    int wm = w & 1, wn = w >> 1, g = lane >> 2, T = lane & 3;
    int n0 = blockIdx.x * 128;
    int ar = tid >> 1, qb = (tid & 1) * 8;

    int gr = tile * 128 + ar;
    if (gr >= cnt) gr = cnt - 1;

    float acc[4][4][4] = {};
    pipe_mainloop(g_h1 + (size_t)(ebase + gr) * EHID + qb,
                  w2 + (size_t)e * DD * EHID + (size_t)(n0 + ar) * EHID + qb,
                  EHID, As, Bs, acc);

    #pragma unroll
    for (int mt = 0; mt < 4; mt++) {
        #pragma unroll
        for (int nt = 0; nt < 4; nt++) {
            int lr0 = wm * 64 + mt * 16 + g;
            int c0  = n0 + wn * 32 + nt * 8 + 2 * T;
            float bx = b2[e * DD + c0], by = b2[e * DD + c0 + 1];
            #pragma unroll
            for (int half = 0; half < 2; half++) {
                int grr = tile * 128 + lr0 + half * 8;
                if (grr < cnt) {
                    int token = g_perm[ebase + grr];
                    float gwv = g_ew[token];
                    float2 v = make_float2(gwv * (acc[mt][nt][half * 2 + 0] + bx),
                                           gwv * (acc[mt][nt][half * 2 + 1] + by));
                    *(float2*)(g_tmp + (size_t)token * DD + c0) = v;
                }
            }
        }
    }
}

// ---------------- flash attention (tensor cores + poly exp) ------------------
#define QTILE 128
#define KCH   64
#define QSTR  36   // tf32 row stride
#define VSTR  72   // half row stride for V^T

__global__ void attn_fa_kernel()
{
    __shared__ uint32_t Qs[QTILE * QSTR];
    __shared__ uint32_t Ks[KCH * QSTR];
    __shared__ __half   Vt[DHD * VSTR];
    __shared__ int      mk[KCH];

    int qt = blockIdx.x, h = blockIdx.y, b = blockIdx.z;
    int tid = threadIdx.x, lane = tid & 31, w = tid >> 5;
    int g = lane >> 2, T = lane & 3;

    const float* Qg = g_qkv + ((size_t)((b * HH + h) * SS + qt * QTILE)) * DHD;
    const float* Kg = g_qkv + (size_t)QKV_HSZ     + ((size_t)((b * HH + h) * SS)) * DHD;
    const float* Vg = g_qkv + (size_t)2 * QKV_HSZ + ((size_t)((b * HH + h) * SS)) * DHD;

    const float inv = 0.17677669529663689f;

    for (int i = tid; i < QTILE * 8; i += 256) {
        float4 v = ((const float4*)Qg)[i];
        int row = i >> 3, c = (i & 7) * 4;
        Qs[row * QSTR + c + 0] = f2tf(v.x * inv);
        Qs[row * QSTR + c + 1] = f2tf(v.y * inv);
        Qs[row * QSTR + c + 2] = f2tf(v.z * inv);
        Qs[row * QSTR + c + 3] = f2tf(v.w * inv);
    }

    float m_[2]  = {-1e30f, -1e30f};
    float sum_[2] = {0.f, 0.f};
    float o[4][4] = {};

    for (int kc = 0; kc < SS / KCH; kc++) {
        __syncthreads();
        for (int i = tid; i < KCH * 8; i += 256) {
            float4 v = ((const float4*)(Kg + kc * KCH * DHD))[i];
            int row = i >> 3, c = (i & 7) * 4;
            Ks[row * QSTR + c + 0] = f2tf(v.x);
            Ks[row * QSTR + c + 1] = f2tf(v.y);
            Ks[row * QSTR + c + 2] = f2tf(v.z);
            Ks[row * QSTR + c + 3] = f2tf(v.w);
        }
        for (int i = tid; i < KCH * 8; i += 256) {
            float4 v = ((const float4*)(Vg + kc * KCH * DHD))[i];
            int key = i >> 3, c = (i & 7) * 4;
            Vt[(c + 0) * VSTR + key] = __float2half(v.x);
            Vt[(c + 1) * VSTR + key] = __float2half(v.y);
            Vt[(c + 2) * VSTR + key] = __float2half(v.z);
            Vt[(c + 3) * VSTR + key] = __float2half(v.w);
        }
        if (tid < KCH) mk[tid] = g_pad[b * SS + kc * KCH + tid];
        __syncthreads();

        float s[8][4];
        #pragma unroll
        for (int nt = 0; nt < 8; nt++)
            #pragma unroll
            for (int j = 0; j < 4; j++) s[nt][j] = 0.f;

        #pragma unroll
        for (int ks = 0; ks < 4; ks++) {
            uint32_t af[4];
            int row = w * 16 + g, col = ks * 8 + T;
            af[0] = Qs[row * QSTR + col];
            af[1] = Qs[(row + 8) * QSTR + col];
            af[2] = Qs[row * QSTR + col + 4];
            af[3] = Qs[(row + 8) * QSTR + col + 4];
            #pragma unroll
            for (int nt = 0; nt < 8; nt++) {
                uint32_t bf[2];
                int kr = nt * 8 + g;
                bf[0] = Ks[kr * QSTR + ks * 8 + T];
                bf[1] = Ks[kr * QSTR + ks * 8 + T + 4];
                mma_tf32(s[nt], af, bf);
            }
        }

        #pragma unroll
        for (int nt = 0; nt < 8; nt++) {
            if (mk[nt * 8 + 2 * T])     { s[nt][0] = -1e9f; s[nt][2] = -1e9f; }
            if (mk[nt * 8 + 2 * T + 1]) { s[nt][1] = -1e9f; s[nt][3] = -1e9f; }
        }

        #pragma unroll
        for (int half = 0; half < 2; half++) {
            float cmax = -1e30f;
            #pragma unroll
            for (int nt = 0; nt < 8; nt++)
                cmax = fmaxf(cmax, fmaxf(s[nt][2 * half], s[nt][2 * half + 1]));
            cmax = fmaxf(cmax, __shfl_xor_sync(0xffffffffu, cmax, 1));
            cmax = fmaxf(cmax, __shfl_xor_sync(0xffffffffu, cmax, 2));
            float mnew  = fmaxf(m_[half], cmax);
            float scale = fexp(m_[half] - mnew);
            m_[half] = mnew;
            float part = 0.f;
            #pragma unroll
            for (int nt = 0; nt < 8; nt++) {
                float p0 = fexp(s[nt][2 * half]     - mnew);
                float p1 = fexp(s[nt][2 * half + 1] - mnew);
                s[nt][2 * half] = p0; s[nt][2 * half + 1] = p1;
                part += p0 + p1;
            }
            part += __shfl_xor_sync(0xffffffffu, part, 1);
            part += __shfl_xor_sync(0xffffffffu, part, 2);
            sum_[half] = sum_[half] * scale + part;
            #pragma unroll
            for (int nt = 0; nt < 4; nt++) {
                o[nt][2 * half]     *= scale;
                o[nt][2 * half + 1] *= scale;
            }
        }

        #pragma unroll
        for (int kt = 0; kt < 4; kt++) {
            uint32_t a0 = packh2(s[2 * kt][0],     s[2 * kt][1]);
            uint32_t a1 = packh2(s[2 * kt][2],     s[2 * kt][3]);
            uint32_t a2 = packh2(s[2 * kt + 1][0], s[2 * kt + 1][1]);
            uint32_t a3 = packh2(s[2 * kt + 1][2], s[2 * kt + 1][3]);
            #pragma unroll
            for (int nt = 0; nt < 4; nt++) {
                const __half* vp = &Vt[(nt * 8 + g) * VSTR + kt * 16 + 2 * T];
                uint32_t b0 = *(const uint32_t*)vp;
                uint32_t b1 = *(const uint32_t*)(vp + 8);
                mma_f16(o[nt], a0, a1, a2, a3, b0, b1);
            }
        }
    }

    float i0 = 1.0f / sum_[0];
    float i1 = 1.0f / sum_[1];
    int q0 = qt * QTILE + w * 16 + g;
    #pragma unroll
    for (int nt = 0; nt < 4; nt++) {
        int col = h * DHD + nt * 8 + 2 * T;
        float2 v0 = make_float2(o[nt][0] * i0, o[nt][1] * i0);
        float2 v1 = make_float2(o[nt][2] * i1, o[nt][3] * i1);
        *(float2*)(g_ctx + (size_t)(b * SS + q0) * DD + col)     = v0;
        *(float2*)(g_ctx + (size_t)(b * SS + q0 + 8) * DD + col) = v1;
    }
}

// ---------------- residual + LayerNorm (in place on g_h) --------------------
__global__ void add_ln_kernel(const float* __restrict__ add,
                              const float* __restrict__ gamma,
                              const float* __restrict__ beta)
{
    int n = blockIdx.x, d = threadIdx.x;
    float v = g_h[(size_t)n * DD + d] + add[(size_t)n * DD + d];

    __shared__ float ws[8];
    __shared__ float s_mu, s_var;

    float sum = v;
    #pragma unroll
    for (int o = 16; o > 0; o >>= 1) sum += __shfl_xor_sync(0xffffffffu, sum, o);
    if ((d & 31) == 0) ws[d >> 5] = sum;
    __syncthreads();
    if (d == 0) {
        float t = 0.f;
        #pragma unroll
        for (int i = 0; i < 8; i++) t += ws[i];
        s_mu = t * (1.0f / DD);
    }
    __syncthreads();
    float c = v - s_mu;
    float sq = c * c;
    #pragma unroll
    for (int o = 16; o > 0; o >>= 1) sq += __shfl_xor_sync(0xffffffffu, sq, o);
    if ((d & 31) == 0) ws[d >> 5] = sq;
    __syncthreads();
    if (d == 0) {
        float t = 0.f;
        #pragma unroll
        for (int i = 0; i < 8; i++) t += ws[i];
        s_var = t * (1.0f / DD);
    }
    __syncthreads();
    g_h[(size_t)n * DD + d] = c * rsqrtf(s_var + 1e-5f) * gamma[d] + beta[d];
}

// ---------------- gate + routing bookkeeping --------------------------------
__global__ void zero_cnt_kernel()
{
    if (threadIdx.x < NEXP) g_cnt[threadIdx.x] = 0;
}

__global__ void gate_kernel(const float* __restrict__ gw, const float* __restrict__ gb)
{
    int n = blockIdx.x, tid = threadIdx.x;
    int e = tid >> 5, lane = tid & 31;
    const float* xp = &g_h[(size_t)n * DD];
    float s = 0.f;
    for (int d = lane; d < DD; d += 32) s += gw[e * DD + d] * xp[d];
    #pragma unroll
    for (int o = 16; o > 0; o >>= 1) s += __shfl_down_sync(0xffffffffu, s, o);
    __shared__ float logits[NEXP];
    if (lane == 0) logits[e] = s + gb[e];
    __syncthreads();
    if (tid == 0) {
        float m = -1e30f;
        #pragma unroll
        for (int i = 0; i < NEXP; i++) m = fmaxf(m, logits[i]);
        float p[NEXP], sum = 0.f;
        #pragma unroll
        for (int i = 0; i < NEXP; i++) { p[i] = expf(logits[i] - m); sum += p[i]; }
        int bi = 0; float bw = p[0];
        #pragma unroll
        for (int i = 1; i < NEXP; i++) if (p[i] > bw) { bw = p[i]; bi = i; }
        g_eidx[n] = bi;
        g_ew[n]   = bw / sum;
        atomicAdd(&g_cnt[bi], 1);
    }
}

__global__ void prefix_kernel()
{
    if (threadIdx.x == 0) {
        int acc = 0;
        #pragma unroll
        for (int e = 0; e < NEXP; e++) {
            g_base[e] = acc; g_cursor[e] = acc; acc += g_cnt[e];
        }
    }
}

__global__ void scatter_kernel()
{
    int n = blockIdx.x * blockDim.x + threadIdx.x;
    if (n < NTOK) {
        int e = g_eidx[n];
        int pos = atomicAdd(&g_cursor[e], 1);
        g_perm[pos] = n;
    }
}

// ---------------- masked mean pool + fc1(relu) + fc2 -------------------------
__global__ void head_kernel(const float* __restrict__ fc1w, const float* __restrict__ fc1b,
                            const float* __restrict__ fc2w, const float* __restrict__ fc2b,
                            float* __restrict__ out)
{
    int b = blockIdx.x, tid = threadIdx.x;
    __shared__ float pooled[DD];
    __shared__ float z[128];

    float s = 0.f;
    int cnt = 0;
    for (int si = 0; si < SS; si++) {
        int n = b * SS + si;
        if (!g_pad[n]) { s += g_h[(size_t)n * DD + tid]; cnt++; }
    }
    pooled[tid] = s / fmaxf((float)cnt, 1.0f);
    __syncthreads();

    if (tid < 128) {
        float a = fc1b[tid];
        const float* wr = fc1w + (size_t)tid * DD;
        #pragma unroll 8
        for (int d = 0; d < DD; d++) a += pooled[d] * wr[d];
        z[tid] = fmaxf(a, 0.f);
    }
    __syncthreads();
    if (tid < 2) {
        float a = fc2b[tid];
        const float* wr = fc2w + (size_t)tid * 128;
        #pragma unroll 8
        for (int i = 0; i < 128; i++) a += z[i] * wr[i];
        out[b * 2 + tid] = a;
    }
}

// ---------------- host launch ------------------------------------------------
static float* sym_addr(const void* sym)
{
    void* p = nullptr;
    cudaGetSymbolAddress(&p, sym);
    return (float*)p;
}

extern "C" void kernel_launch(void* const* d_in, const int* in_sizes, int n_in,
                              void* d_out, int out_size)
{
    const int*   x          = (const int*)  d_in[0];
    const float* emb        = (const float*)d_in[1];
    const float* in_proj_w  = (const float*)d_in[2];
    const float* in_proj_b  = (const float*)d_in[3];
    const float* out_proj_w = (const float*)d_in[4];
    const float* out_proj_b = (const float*)d_in[5];
    const float* ln1_g      = (const float*)d_in[6];
    const float* ln1_b      = (const float*)d_in[7];
    const float* ln2_g      = (const float*)d_in[8];
    const float* ln2_b      = (const float*)d_in[9];
    const float* gate_w     = (const float*)d_in[10];
    const float* gate_b     = (const float*)d_in[11];
    const float* w1         = (const float*)d_in[12];
    const float* b1         = (const float*)d_in[13];
    const float* w2         = (const float*)d_in[14];
    const float* b2         = (const float*)d_in[15];
    const float* fc1_w      = (const float*)d_in[16];
    const float* fc1_b      = (const float*)d_in[17];
    const float* fc2_w      = (const float*)d_in[18];
    const float* fc2_b      = (const float*)d_in[19];
    float* out = (float*)d_out;

    float* p_h   = sym_addr(g_h);
    float* p_ctx = sym_addr(g_ctx);
    float* p_tmp = sym_addr(g_tmp);

    pe_kernel<<<SS, DD>>>();
    embed_kernel<<<NTOK, DD>>>(x, emb);

    for (int l = 0; l < NLAY; l++) {
        gemm_qkv_mma<<<dim3(3*DD/128, NTOK/128), 256>>>(
            p_h, in_proj_w + (size_t)l * 3*DD*DD, in_proj_b + (size_t)l * 3*DD);

        attn_fa_kernel<<<dim3(SS/QTILE, HH, BB), 256>>>();

        gemm_mma<<<dim3(DD/128, NTOK/128), 256>>>(
            p_ctx, out_proj_w + (size_t)l * DD*DD, out_proj_b + (size_t)l * DD,
            p_tmp, DD, DD);

        add_ln_kernel<<<NTOK, DD>>>(p_tmp, ln1_g + (size_t)l * DD, ln1_b + (size_t)l * DD);

        zero_cnt_kernel<<<1, 32>>>();
        gate_kernel<<<NTOK, 256>>>(gate_w + (size_t)l * NEXP*DD, gate_b + (size_t)l * NEXP);
        prefix_kernel<<<1, 32>>>();
        scatter_kernel<<<NTOK/256, 256>>>();

        moe_gemm1_mma<<<dim3(EHID/128, NEXP*64), 256>>>(
            w1 + (size_t)l * NEXP*EHID*DD, b1 + (size_t)l * NEXP*EHID);
        moe_gemm2_mma<<<dim3(DD/128, NEXP*64), 256>>>(
            w2 + (size_t)l * NEXP*DD*EHID, b2 + (size_t)l * NEXP*DD);

        add_ln_kernel<<<NTOK, DD>>>(p_tmp, ln2_g + (size_t)l * DD, ln2_b + (size_t)l * DD);
    }

    head_kernel<<<BB, 256>>>(fc1_w, fc1_b, fc2_w, fc2_b, out);
}

// round 6
// speedup vs baseline: 29.7377x; 1.3468x over previous
#include <cuda_runtime.h>
#include <cuda_fp16.h>
#include <math.h>
#include <stdint.h>

// ---------------- model dims ----------------
#define BB    16
#define SS    512
#define DD    256
#define HH    8
#define DHD   32
#define NLAY  2
#define NEXP  8
#define EHID  1024
#define NTOK  (BB*SS)   // 8192

// ---------------- scratch (static device globals) ---------------------------
__device__ float  g_h   [NTOK*DD];
__device__ __half g_hh  [NTOK*DD];     // fp16 copy of g_h (GEMM operand)
__device__ float  g_qkv [NTOK*3*DD];   // split: Q | K | V, each [B][H][S][32]
__device__ __half g_ctxh[NTOK*DD];     // attention output (fp16)
__device__ float  g_tmp [NTOK*DD];
__device__ __half g_h1h [NTOK*EHID];   // MoE hidden (fp16, permuted rows)
__device__ float  g_pe  [SS*DD];
__device__ int    g_pad [NTOK];
__device__ int    g_eidx[NTOK];
__device__ float  g_ew  [NTOK];
__device__ int    g_cnt [NEXP];
__device__ int    g_base[NEXP];
__device__ int    g_cursor[NEXP];
__device__ int    g_perm[NTOK];

// fp16 weight buffer (converted once per launch)
#define IPH_OFF 0
#define IPH_SZ  (NLAY*3*DD*DD)         // 393216
#define OPH_OFF (IPH_OFF + IPH_SZ)
#define OPH_SZ  (NLAY*DD*DD)           // 131072
#define W1H_OFF (OPH_OFF + OPH_SZ)
#define W1H_SZ  (NLAY*NEXP*EHID*DD)    // 4194304
#define W2H_OFF (W1H_OFF + W1H_SZ)
#define W2H_SZ  (NLAY*NEXP*DD*EHID)    // 4194304
#define WH_TOTAL (W2H_OFF + W2H_SZ)
__device__ __half g_wh[WH_TOTAL];

#define QKV_HSZ (BB*HH*SS*DHD)   // 2097152

// ---------------- helpers ----------------------------------------------------
__device__ __forceinline__ uint32_t f2tf(float x)
{
    uint32_t r;
    asm("cvt.rna.tf32.f32 %0, %1;" : "=r"(r) : "f"(x));
    return r;
}

__device__ __forceinline__ void mma_tf32(float* d, const uint32_t* a, const uint32_t* b)
{
    asm volatile(
        "mma.sync.aligned.m16n8k8.row.col.f32.tf32.tf32.f32 "
        "{%0,%1,%2,%3}, {%4,%5,%6,%7}, {%8,%9}, {%0,%1,%2,%3};\n"
        : "+f"(d[0]), "+f"(d[1]), "+f"(d[2]), "+f"(d[3])
        : "r"(a[0]), "r"(a[1]), "r"(a[2]), "r"(a[3]),
          "r"(b[0]), "r"(b[1]));
}

__device__ __forceinline__ void mma_f16(float* d, uint32_t a0, uint32_t a1,
                                        uint32_t a2, uint32_t a3,
                                        uint32_t b0, uint32_t b1)
{
    asm volatile(
        "mma.sync.aligned.m16n8k16.row.col.f32.f16.f16.f32 "
        "{%0,%1,%2,%3}, {%4,%5,%6,%7}, {%8,%9}, {%0,%1,%2,%3};\n"
        : "+f"(d[0]), "+f"(d[1]), "+f"(d[2]), "+f"(d[3])
        : "r"(a0), "r"(a1), "r"(a2), "r"(a3), "r"(b0), "r"(b1));
}

// fast exp on the FMA pipe (no MUFU), valid for x <= 0
__device__ __forceinline__ float fexp(float x)
{
    x = fmaxf(x, -87.0f);
    const float L2E = 1.4426950408889634f;
    float t  = fmaf(x, L2E, 12582912.0f);
    int   ki = __float_as_int(t) - 0x4B400000;
    float kf = t - 12582912.0f;
    float r  = fmaf(x, L2E, -kf);
    float p  = 1.3333558146e-3f;
    p = fmaf(p, r, 9.6181291076e-3f);
    p = fmaf(p, r, 5.5504108664e-2f);
    p = fmaf(p, r, 2.4022650696e-1f);
    p = fmaf(p, r, 6.9314718056e-1f);
    p = fmaf(p, r, 1.0f);
    return p * __int_as_float((ki + 127) << 23);
}

__device__ __forceinline__ uint32_t packh2(float a, float b)
{
    __half2 h = __floats2half2_rn(a, b);
    return *(uint32_t*)&h;
}

__device__ __forceinline__ void cp16(uint32_t dst, const void* src)
{
    asm volatile("cp.async.ca.shared.global [%0], [%1], 16;\n"
                 :: "r"(dst), "l"(src));
}

// ---------------- fp16 pipelined 128x128 GEMM core ---------------------------
// 256 threads, 8 warps in 2x4 (wm x wn). acc[mt 4][nt 4][4].
#define HSTR 24                 // halves per smem row (48B -> conflict-free)
#define HBUF (128 * HSTR)       // halves per stage buffer

__device__ __forceinline__ void pipe16_mainloop(
    const __half* __restrict__ aptr,  // A row ptr pre-offset by this thread's seg
    const __half* __restrict__ wptr,  // W row ptr pre-offset by this thread's seg
    int K, __half* AsArr, __half* BsArr, float acc[4][4][4])
{
    int tid = threadIdx.x, lane = tid & 31, w = tid >> 5;
    int wm = w & 1, wn = w >> 1;
    int g = lane >> 2, T = lane & 3;
    int row = tid >> 1, seg = (tid & 1) * 8;

    uint32_t da = (uint32_t)__cvta_generic_to_shared(AsArr) + (row * HSTR + seg) * 2;
    uint32_t db = (uint32_t)__cvta_generic_to_shared(BsArr) + (row * HSTR + seg) * 2;
    const uint32_t BUFB = HBUF * 2;   // bytes per stage

    int KT = K / 16;

    cp16(da, aptr);
    cp16(db, wptr);
    asm volatile("cp.async.commit_group;\n");

    for (int kt = 0; kt < KT; kt++) {
        if (kt + 1 < KT) {
            uint32_t off = ((kt + 1) & 1) * BUFB;
            cp16(da + off, aptr + (kt + 1) * 16);
            cp16(db + off, wptr + (kt + 1) * 16);
            asm volatile("cp.async.commit_group;\n");
            asm volatile("cp.async.wait_group 1;\n");
        } else {
            asm volatile("cp.async.wait_group 0;\n");
        }
        __syncthreads();

        const __half* A = AsArr + (kt & 1) * HBUF;
        const __half* B = BsArr + (kt & 1) * HBUF;

        uint32_t afr[4][4], bfr[4][2];
        #pragma unroll
        for (int mt = 0; mt < 4; mt++) {
            int rb = wm * 64 + mt * 16 + g;
            afr[mt][0] = *(const uint32_t*)(A + rb * HSTR + 2 * T);
            afr[mt][1] = *(const uint32_t*)(A + (rb + 8) * HSTR + 2 * T);
            afr[mt][2] = *(const uint32_t*)(A + rb * HSTR + 8 + 2 * T);
            afr[mt][3] = *(const uint32_t*)(A + (rb + 8) * HSTR + 8 + 2 * T);
        }
        #pragma unroll
        for (int nt = 0; nt < 4; nt++) {
            int nb = wn * 32 + nt * 8 + g;
            bfr[nt][0] = *(const uint32_t*)(B + nb * HSTR + 2 * T);
            bfr[nt][1] = *(const uint32_t*)(B + nb * HSTR + 8 + 2 * T);
        }
        #pragma unroll
        for (int mt = 0; mt < 4; mt++)
            #pragma unroll
            for (int nt = 0; nt < 4; nt++)
                mma_f16(acc[mt][nt], afr[mt][0], afr[mt][1], afr[mt][2], afr[mt][3],
                        bfr[nt][0], bfr[nt][1]);
        __syncthreads();
    }
}

// ---------------- weight conversion (fp32 -> fp16) ---------------------------
__global__ void f2h_kernel(const float* __restrict__ src, __half* __restrict__ dst, int n4)
{
    int i = blockIdx.x * 256 + threadIdx.x;
    if (i < n4) {
        float4 v = ((const float4*)src)[i];
        ((__half2*)dst)[2 * i + 0] = __floats2half2_rn(v.x, v.y);
        ((__half2*)dst)[2 * i + 1] = __floats2half2_rn(v.z, v.w);
    }
}

// ---------------- positional encoding table ----------------------------------
__global__ void pe_kernel()
{
    int s = blockIdx.x, d = threadIdx.x;
    double freq = exp(-(double)(d & ~1) * (log(10000.0) / (double)DD));
    double arg  = (double)s * freq;
    g_pe[s * DD + d] = (d & 1) ? (float)cos(arg) : (float)sin(arg);
}

// ---------------- embedding + pad mask ---------------------------------------
__global__ void embed_kernel(const int* __restrict__ x, const float* __restrict__ emb)
{
    int n = blockIdx.x;
    int d = threadIdx.x;
    int tok = x[n];
    int s = n & (SS - 1);

    float v = emb[(size_t)tok * DD + d] * 16.0f + g_pe[s * DD + d];
    g_h [(size_t)n * DD + d] = v;
    g_hh[(size_t)n * DD + d] = __float2half(v);

    float sum = v;
    #pragma unroll
    for (int o = 16; o > 0; o >>= 1) sum += __shfl_xor_sync(0xffffffffu, sum, o);
    __shared__ float ws[8];
    if ((d & 31) == 0) ws[d >> 5] = sum;
    __syncthreads();
    if (d == 0) {
        float t = 0.f;
        #pragma unroll
        for (int i = 0; i < 8; i++) t += ws[i];
        g_pad[n] = (t == 0.0f) ? 1 : 0;
    }
}

// ---------------- QKV GEMM (fp16) + split head-major store -------------------
__global__ __launch_bounds__(256)
void gemm_qkv16(const __half* __restrict__ A,
                const __half* __restrict__ W,
                const float* __restrict__ bias)
{
    __shared__ __half As[2 * HBUF];
    __shared__ __half Bs[2 * HBUF];

    int tid = threadIdx.x, lane = tid & 31, w = tid >> 5;
    int wm = w & 1, wn = w >> 1, g = lane >> 2, T = lane & 3;
    int m0 = blockIdx.y * 128, n0 = blockIdx.x * 128;
    int row = tid >> 1, seg = (tid & 1) * 8;

    float acc[4][4][4] = {};
    pipe16_mainloop(A + (size_t)(m0 + row) * DD + seg,
                    W + (size_t)(n0 + row) * DD + seg, DD, As, Bs, acc);

    #pragma unroll
    for (int mt = 0; mt < 4; mt++) {
        #pragma unroll
        for (int nt = 0; nt < 4; nt++) {
            int r0 = m0 + wm * 64 + mt * 16 + g;
            int c0 = n0 + wn * 32 + nt * 8 + 2 * T;
            int t = c0 >> 8, h = (c0 >> 5) & 7, d = c0 & 31;
            float bx = bias[c0], by = bias[c0 + 1];
            #pragma unroll
            for (int half = 0; half < 2; half++) {
                int rr = r0 + half * 8;
                int b = rr >> 9, s = rr & (SS - 1);
                size_t dst = (size_t)t * QKV_HSZ
                           + ((size_t)((b * HH + h) * SS + s)) * DHD + d;
                float2 v = make_float2(acc[mt][nt][half * 2 + 0] + bx,
                                       acc[mt][nt][half * 2 + 1] + by);
                *(float2*)(g_qkv + dst) = v;
            }
        }
    }
}

// ---------------- out-proj GEMM (fp16): C = A @ W^T + bias (fp32 out) --------
__global__ __launch_bounds__(256)
void gemm_out16(const __half* __restrict__ A,
                const __half* __restrict__ W,
                const float* __restrict__ bias,
                float* __restrict__ C, int Nc, int K)
{
    __shared__ __half As[2 * HBUF];
    __shared__ __half Bs[2 * HBUF];

    int tid = threadIdx.x, lane = tid & 31, w = tid >> 5;
    int wm = w & 1, wn = w >> 1, g = lane >> 2, T = lane & 3;
    int m0 = blockIdx.y * 128, n0 = blockIdx.x * 128;
    int row = tid >> 1, seg = (tid & 1) * 8;

    float acc[4][4][4] = {};
    pipe16_mainloop(A + (size_t)(m0 + row) * K + seg,
                    W + (size_t)(n0 + row) * K + seg, K, As, Bs, acc);

    #pragma unroll
    for (int mt = 0; mt < 4; mt++) {
        #pragma unroll
        for (int nt = 0; nt < 4; nt++) {
            int r0 = m0 + wm * 64 + mt * 16 + g;
            int c0 = n0 + wn * 32 + nt * 8 + 2 * T;
            float bx = bias[c0], by = bias[c0 + 1];
            #pragma unroll
            for (int half = 0; half < 2; half++) {
                int rr = r0 + half * 8;
                float2 v = make_float2(acc[mt][nt][half * 2 + 0] + bx,
                                       acc[mt][nt][half * 2 + 1] + by);
                *(float2*)(C + (size_t)rr * Nc + c0) = v;
            }
        }
    }
}

// ---------------- MoE GEMM1 (fp16): H = relu(Xperm @ W1[e]^T + b1) -----------
__global__ __launch_bounds__(256)
void moe_gemm1_16(const __half* __restrict__ w1, const float* __restrict__ b1)
{
    int y = blockIdx.y;
    int e = y >> 6, tile = y & 63;
    int cnt = g_cnt[e];
    if (tile * 128 >= cnt) return;
    int ebase = g_base[e];

    __shared__ __half As[2 * HBUF];
    __shared__ __half Bs[2 * HBUF];

    int tid = threadIdx.x, lane = tid & 31, w = tid >> 5;
    int wm = w & 1, wn = w >> 1, g = lane >> 2, T = lane & 3;
    int n0 = blockIdx.x * 128;
    int row = tid >> 1, seg = (tid & 1) * 8;

    int gr = tile * 128 + row;
    if (gr >= cnt) gr = cnt - 1;
    int token = g_perm[ebase + gr];

    float acc[4][4][4] = {};
    pipe16_mainloop(g_hh + (size_t)token * DD + seg,
                    w1 + (size_t)e * EHID * DD + (size_t)(n0 + row) * DD + seg,
                    DD, As, Bs, acc);

    #pragma unroll
    for (int mt = 0; mt < 4; mt++) {
        #pragma unroll
        for (int nt = 0; nt < 4; nt++) {
            int lr0 = wm * 64 + mt * 16 + g;
            int c0  = n0 + wn * 32 + nt * 8 + 2 * T;
            float bx = b1[e * EHID + c0], by = b1[e * EHID + c0 + 1];
            #pragma unroll
            for (int half = 0; half < 2; half++) {
                int grr = tile * 128 + lr0 + half * 8;
                if (grr < cnt) {
                    float v0 = fmaxf(acc[mt][nt][half * 2 + 0] + bx, 0.f);
                    float v1 = fmaxf(acc[mt][nt][half * 2 + 1] + by, 0.f);
                    *(uint32_t*)(g_h1h + (size_t)(ebase + grr) * EHID + c0) = packh2(v0, v1);
                }
            }
        }
    }
}

// ---------------- MoE GEMM2 (fp16): Y = gw*(H @ W2[e]^T + b2) ----------------
__global__ __launch_bounds__(256)
void moe_gemm2_16(const __half* __restrict__ w2, const float* __restrict__ b2)
{
    int y = blockIdx.y;
    int e = y >> 6, tile = y & 63;
    int cnt = g_cnt[e];
    if (tile * 128 >= cnt) return;
    int ebase = g_base[e];

    __shared__ __half As[2 * HBUF];
    __shared__ __half Bs[2 * HBUF];

    int tid = threadIdx.x, lane = tid & 31, w = tid >> 5;
    int wm = w & 1, wn = w >> 1, g = lane >> 2, T = lane & 3;
    int n0 = blockIdx.x * 128;
    int row = tid >> 1, seg = (tid & 1) * 8;

    int gr = tile * 128 + row;
    if (gr >= cnt) gr = cnt - 1;

    float acc[4][4][4] = {};
    pipe16_mainloop(g_h1h + (size_t)(ebase + gr) * EHID + seg,
                    w2 + (size_t)e * DD * EHID + (size_t)(n0 + row) * EHID + seg,
                    EHID, As, Bs, acc);

    #pragma unroll
    for (int mt = 0; mt < 4; mt++) {
        #pragma unroll
        for (int nt = 0; nt < 4; nt++) {
            int lr0 = wm * 64 + mt * 16 + g;
            int c0  = n0 + wn * 32 + nt * 8 + 2 * T;
            float bx = b2[e * DD + c0], by = b2[e * DD + c0 + 1];
            #pragma unroll
            for (int half = 0; half < 2; half++) {
                int grr = tile * 128 + lr0 + half * 8;
                if (grr < cnt) {
                    int token = g_perm[ebase + grr];
                    float gwv = g_ew[token];
                    float2 v = make_float2(gwv * (acc[mt][nt][half * 2 + 0] + bx),
                                           gwv * (acc[mt][nt][half * 2 + 1] + by));
                    *(float2*)(g_tmp + (size_t)token * DD + c0) = v;
                }
            }
        }
    }
}

// ---------------- flash attention (tensor cores + poly exp) ------------------
#define QTILE 128
#define KCH   64
#define QSTR  36
#define VSTR  72

__global__ void attn_fa_kernel()
{
    __shared__ uint32_t Qs[QTILE * QSTR];
    __shared__ uint32_t Ks[KCH * QSTR];
    __shared__ __half   Vt[DHD * VSTR];
    __shared__ int      mk[KCH];

    int qt = blockIdx.x, h = blockIdx.y, b = blockIdx.z;
    int tid = threadIdx.x, lane = tid & 31, w = tid >> 5;
    int g = lane >> 2, T = lane & 3;

    const float* Qg = g_qkv + ((size_t)((b * HH + h) * SS + qt * QTILE)) * DHD;
    const float* Kg = g_qkv + (size_t)QKV_HSZ     + ((size_t)((b * HH + h) * SS)) * DHD;
    const float* Vg = g_qkv + (size_t)2 * QKV_HSZ + ((size_t)((b * HH + h) * SS)) * DHD;

    const float inv = 0.17677669529663689f;

    for (int i = tid; i < QTILE * 8; i += 256) {
        float4 v = ((const float4*)Qg)[i];
        int row = i >> 3, c = (i & 7) * 4;
        Qs[row * QSTR + c + 0] = f2tf(v.x * inv);
        Qs[row * QSTR + c + 1] = f2tf(v.y * inv);
        Qs[row * QSTR + c + 2] = f2tf(v.z * inv);
        Qs[row * QSTR + c + 3] = f2tf(v.w * inv);
    }

    float m_[2]  = {-1e30f, -1e30f};
    float sum_[2] = {0.f, 0.f};
    float o[4][4] = {};

    for (int kc = 0; kc < SS / KCH; kc++) {
        __syncthreads();
        for (int i = tid; i < KCH * 8; i += 256) {
            float4 v = ((const float4*)(Kg + kc * KCH * DHD))[i];
            int row = i >> 3, c = (i & 7) * 4;
            Ks[row * QSTR + c + 0] = f2tf(v.x);
            Ks[row * QSTR + c + 1] = f2tf(v.y);
            Ks[row * QSTR + c + 2] = f2tf(v.z);
            Ks[row * QSTR + c + 3] = f2tf(v.w);
        }
        for (int i = tid; i < KCH * 8; i += 256) {
            float4 v = ((const float4*)(Vg + kc * KCH * DHD))[i];
            int key = i >> 3, c = (i & 7) * 4;
            Vt[(c + 0) * VSTR + key] = __float2half(v.x);
            Vt[(c + 1) * VSTR + key] = __float2half(v.y);
            Vt[(c + 2) * VSTR + key] = __float2half(v.z);
            Vt[(c + 3) * VSTR + key] = __float2half(v.w);
        }
        if (tid < KCH) mk[tid] = g_pad[b * SS + kc * KCH + tid];
        __syncthreads();

        float s[8][4];
        #pragma unroll
        for (int nt = 0; nt < 8; nt++)
            #pragma unroll
            for (int j = 0; j < 4; j++) s[nt][j] = 0.f;

        #pragma unroll
        for (int ks = 0; ks < 4; ks++) {
            uint32_t af[4];
            int row = w * 16 + g, col = ks * 8 + T;
            af[0] = Qs[row * QSTR + col];
            af[1] = Qs[(row + 8) * QSTR + col];
            af[2] = Qs[row * QSTR + col + 4];
            af[3] = Qs[(row + 8) * QSTR + col + 4];
            #pragma unroll
            for (int nt = 0; nt < 8; nt++) {
                uint32_t bf[2];
                int kr = nt * 8 + g;
                bf[0] = Ks[kr * QSTR + ks * 8 + T];
                bf[1] = Ks[kr * QSTR + ks * 8 + T + 4];
                mma_tf32(s[nt], af, bf);
            }
        }

        #pragma unroll
        for (int nt = 0; nt < 8; nt++) {
            if (mk[nt * 8 + 2 * T])     { s[nt][0] = -1e9f; s[nt][2] = -1e9f; }
            if (mk[nt * 8 + 2 * T + 1]) { s[nt][1] = -1e9f; s[nt][3] = -1e9f; }
        }

        #pragma unroll
        for (int half = 0; half < 2; half++) {
            float cmax = -1e30f;
            #pragma unroll
            for (int nt = 0; nt < 8; nt++)
                cmax = fmaxf(cmax, fmaxf(s[nt][2 * half], s[nt][2 * half + 1]));
            cmax = fmaxf(cmax, __shfl_xor_sync(0xffffffffu, cmax, 1));
            cmax = fmaxf(cmax, __shfl_xor_sync(0xffffffffu, cmax, 2));
            float mnew  = fmaxf(m_[half], cmax);
            float scale = fexp(m_[half] - mnew);
            m_[half] = mnew;
            float part = 0.f;
            #pragma unroll
            for (int nt = 0; nt < 8; nt++) {
                float p0 = fexp(s[nt][2 * half]     - mnew);
                float p1 = fexp(s[nt][2 * half + 1] - mnew);
                s[nt][2 * half] = p0; s[nt][2 * half + 1] = p1;
                part += p0 + p1;
            }
            part += __shfl_xor_sync(0xffffffffu, part, 1);
            part += __shfl_xor_sync(0xffffffffu, part, 2);
            sum_[half] = sum_[half] * scale + part;
            #pragma unroll
            for (int nt = 0; nt < 4; nt++) {
                o[nt][2 * half]     *= scale;
                o[nt][2 * half + 1] *= scale;
            }
        }

        #pragma unroll
        for (int kt = 0; kt < 4; kt++) {
            uint32_t a0 = packh2(s[2 * kt][0],     s[2 * kt][1]);
            uint32_t a1 = packh2(s[2 * kt][2],     s[2 * kt][3]);
            uint32_t a2 = packh2(s[2 * kt + 1][0], s[2 * kt + 1][1]);
            uint32_t a3 = packh2(s[2 * kt + 1][2], s[2 * kt + 1][3]);
            #pragma unroll
            for (int nt = 0; nt < 4; nt++) {
                const __half* vp = &Vt[(nt * 8 + g) * VSTR + kt * 16 + 2 * T];
                uint32_t b0 = *(const uint32_t*)vp;
                uint32_t b1 = *(const uint32_t*)(vp + 8);
                mma_f16(o[nt], a0, a1, a2, a3, b0, b1);
            }
        }
    }

    float i0 = 1.0f / sum_[0];
    float i1 = 1.0f / sum_[1];
    int q0 = qt * QTILE + w * 16 + g;
    #pragma unroll
    for (int nt = 0; nt < 4; nt++) {
        int col = h * DHD + nt * 8 + 2 * T;
        *(uint32_t*)(g_ctxh + (size_t)(b * SS + q0) * DD + col) =
            packh2(o[nt][0] * i0, o[nt][1] * i0);
        *(uint32_t*)(g_ctxh + (size_t)(b * SS + q0 + 8) * DD + col) =
            packh2(o[nt][2] * i1, o[nt][3] * i1);
    }
}

// ---------------- fused residual + LN (+optional gate), warp per token -------
// grid = NTOK/8 blocks, 256 threads. Lane l handles dims l, l+32, ..., l+224.
__device__ __forceinline__ void warp_add_ln(
    int n, int lane, const float* __restrict__ add,
    const float* __restrict__ gamma, const float* __restrict__ beta,
    float out[8])
{
    size_t base = (size_t)n * DD + lane;
    float v[8];
    float sum = 0.f;
    #pragma unroll
    for (int j = 0; j < 8; j++) {
        v[j] = g_h[base + 32 * j] + add[base + 32 * j];
        sum += v[j];
    }
    #pragma unroll
    for (int o = 16; o > 0; o >>= 1) sum += __shfl_xor_sync(0xffffffffu, sum, o);
    float mu = sum * (1.0f / DD);
    float sq = 0.f;
    #pragma unroll
    for (int j = 0; j < 8; j++) {
        v[j] -= mu;
        sq += v[j] * v[j];
    }
    #pragma unroll
    for (int o = 16; o > 0; o >>= 1) sq += __shfl_xor_sync(0xffffffffu, sq, o);
    float r = rsqrtf(sq * (1.0f / DD) + 1e-5f);
    #pragma unroll
    for (int j = 0; j < 8; j++) {
        out[j] = v[j] * r * gamma[lane + 32 * j] + beta[lane + 32 * j];
        g_h [base + 32 * j] = out[j];
        g_hh[base + 32 * j] = __float2half(out[j]);
    }
}

__global__ void add_ln2_kernel(const float* __restrict__ add,
                               const float* __restrict__ gamma,
                               const float* __restrict__ beta)
{
    int lane = threadIdx.x & 31;
    int n = blockIdx.x * 8 + (threadIdx.x >> 5);
    float out[8];
    warp_add_ln(n, lane, add, gamma, beta, out);
}

__global__ void add_ln1_gate_kernel(const float* __restrict__ add,
                                    const float* __restrict__ gamma,
                                    const float* __restrict__ beta,
                                    const float* __restrict__ gw,
                                    const float* __restrict__ gb)
{
    int lane = threadIdx.x & 31;
    int n = blockIdx.x * 8 + (threadIdx.x >> 5);
    float out[8];
    warp_add_ln(n, lane, add, gamma, beta, out);

    // gate logits: 8 experts
    float lg[NEXP];
    #pragma unroll
    for (int e = 0; e < NEXP; e++) {
        float p = 0.f;
        #pragma unroll
        for (int j = 0; j < 8; j++)
            p = fmaf(gw[e * DD + lane + 32 * j], out[j], p);
        #pragma unroll
        for (int o = 16; o > 0; o >>= 1)
            p += __shfl_xor_sync(0xffffffffu, p, o);
        lg[e] = p;
    }
    if (lane == 0) {
        float m = -1e30f;
        #pragma unroll
        for (int i = 0; i < NEXP; i++) { lg[i] += gb[i]; m = fmaxf(m, lg[i]); }
        float p[NEXP], sum = 0.f;
        #pragma unroll
        for (int i = 0; i < NEXP; i++) { p[i] = expf(lg[i] - m); sum += p[i]; }
        int bi = 0; float bw = p[0];
        #pragma unroll
        for (int i = 1; i < NEXP; i++) if (p[i] > bw) { bw = p[i]; bi = i; }
        g_eidx[n] = bi;
        g_ew[n]   = bw / sum;
        atomicAdd(&g_cnt[bi], 1);
    }
}

// ---------------- routing bookkeeping ----------------------------------------
__global__ void zero_cnt_kernel()
{
    if (threadIdx.x < NEXP) g_cnt[threadIdx.x] = 0;
}

__global__ void prefix_kernel()
{
    if (threadIdx.x == 0) {
        int acc = 0;
        #pragma unroll
        for (int e = 0; e < NEXP; e++) {
            g_base[e] = acc; g_cursor[e] = acc; acc += g_cnt[e];
        }
    }
}

__global__ void scatter_kernel()
{
    int n = blockIdx.x * blockDim.x + threadIdx.x;
    if (n < NTOK) {
        int e = g_eidx[n];
        int pos = atomicAdd(&g_cursor[e], 1);
        g_perm[pos] = n;
    }
}

// ---------------- masked mean pool + fc1(relu) + fc2 -------------------------
__global__ void head_kernel(const float* __restrict__ fc1w, const float* __restrict__ fc1b,
                            const float* __restrict__ fc2w, const float* __restrict__ fc2b,
                            float* __restrict__ out)
{
    int b = blockIdx.x, tid = threadIdx.x;
    __shared__ float pooled[DD];
    __shared__ float z[128];

    float s = 0.f;
    int cnt = 0;
    #pragma unroll 4
    for (int si = 0; si < SS; si++) {
        int n = b * SS + si;
        if (!g_pad[n]) { s += g_h[(size_t)n * DD + tid]; cnt++; }
    }
    pooled[tid] = s / fmaxf((float)cnt, 1.0f);
    __syncthreads();

    if (tid < 128) {
        float a = fc1b[tid];
        const float* wr = fc1w + (size_t)tid * DD;
        #pragma unroll 8
        for (int d = 0; d < DD; d++) a += pooled[d] * wr[d];
        z[tid] = fmaxf(a, 0.f);
    }
    __syncthreads();
    if (tid < 2) {
        float a = fc2b[tid];
        const float* wr = fc2w + (size_t)tid * 128;
        #pragma unroll 8
        for (int i = 0; i < 128; i++) a += z[i] * wr[i];
        out[b * 2 + tid] = a;
    }
}

// ---------------- host launch ------------------------------------------------
static void* sym_addr(const void* sym)
{
    void* p = nullptr;
    cudaGetSymbolAddress(&p, sym);
    return p;
}

extern "C" void kernel_launch(void* const* d_in, const int* in_sizes, int n_in,
                              void* d_out, int out_size)
{
    const int*   x          = (const int*)  d_in[0];
    const float* emb        = (const float*)d_in[1];
    const float* in_proj_w  = (const float*)d_in[2];
    const float* in_proj_b  = (const float*)d_in[3];
    const float* out_proj_w = (const float*)d_in[4];
    const float* out_proj_b = (const float*)d_in[5];
    const float* ln1_g      = (const float*)d_in[6];
    const float* ln1_b      = (const float*)d_in[7];
    const float* ln2_g      = (const float*)d_in[8];
    const float* ln2_b      = (const float*)d_in[9];
    const float* gate_w     = (const float*)d_in[10];
    const float* gate_b     = (const float*)d_in[11];
    const float* w1         = (const float*)d_in[12];
    const float* b1         = (const float*)d_in[13];
    const float* w2         = (const float*)d_in[14];
    const float* b2         = (const float*)d_in[15];
    const float* fc1_w      = (const float*)d_in[16];
    const float* fc1_b      = (const float*)d_in[17];
    const float* fc2_w      = (const float*)d_in[18];
    const float* fc2_b      = (const float*)d_in[19];
    float* out = (float*)d_out;

    __half* wh    = (__half*)sym_addr(g_wh);
    __half* hh    = (__half*)sym_addr(g_hh);
    __half* ctxh  = (__half*)sym_addr(g_ctxh);
    float*  p_tmp = (float*)sym_addr(g_tmp);

    // one-time per launch: PE table, embeddings, weight conversion
    pe_kernel<<<SS, DD>>>();
    embed_kernel<<<NTOK, DD>>>(x, emb);
    f2h_kernel<<<(IPH_SZ/4 + 255)/256, 256>>>(in_proj_w,  wh + IPH_OFF, IPH_SZ/4);
    f2h_kernel<<<(OPH_SZ/4 + 255)/256, 256>>>(out_proj_w, wh + OPH_OFF, OPH_SZ/4);
    f2h_kernel<<<(W1H_SZ/4 + 255)/256, 256>>>(w1,         wh + W1H_OFF, W1H_SZ/4);
    f2h_kernel<<<(W2H_SZ/4 + 255)/256, 256>>>(w2,         wh + W2H_OFF, W2H_SZ/4);

    for (int l = 0; l < NLAY; l++) {
        gemm_qkv16<<<dim3(3*DD/128, NTOK/128), 256>>>(
            hh, wh + IPH_OFF + (size_t)l * 3*DD*DD, in_proj_b + (size_t)l * 3*DD);

        attn_fa_kernel<<<dim3(SS/QTILE, HH, BB), 256>>>();

        gemm_out16<<<dim3(DD/128, NTOK/128), 256>>>(
            ctxh, wh + OPH_OFF + (size_t)l * DD*DD, out_proj_b + (size_t)l * DD,
            p_tmp, DD, DD);

        zero_cnt_kernel<<<1, 32>>>();
        add_ln1_gate_kernel<<<NTOK/8, 256>>>(
            p_tmp, ln1_g + (size_t)l * DD, ln1_b + (size_t)l * DD,
            gate_w + (size_t)l * NEXP*DD, gate_b + (size_t)l * NEXP);
        prefix_kernel<<<1, 32>>>();
        scatter_kernel<<<NTOK/256, 256>>>();

        moe_gemm1_16<<<dim3(EHID/128, NEXP*64), 256>>>(
            wh + W1H_OFF + (size_t)l * NEXP*EHID*DD, b1 + (size_t)l * NEXP*EHID);
        moe_gemm2_16<<<dim3(DD/128, NEXP*64), 256>>>(
            wh + W2H_OFF + (size_t)l * NEXP*DD*EHID, b2 + (size_t)l * NEXP*DD);

        add_ln2_kernel<<<NTOK/8, 256>>>(
            p_tmp, ln2_g + (size_t)l * DD, ln2_b + (size_t)l * DD);
    }

    head_kernel<<<BB, 256>>>(fc1_w, fc1_b, fc2_w, fc2_b, out);
}

// round 7
// speedup vs baseline: 31.7979x; 1.0693x over previous
#include <cuda_runtime.h>
#include <cuda_fp16.h>
#include <math.h>
#include <stdint.h>

// ---------------- model dims ----------------
#define BB    16
#define SS    512
#define DD    256
#define HH    8
#define DHD   32
#define NLAY  2
#define NEXP  8
#define EHID  1024
#define NTOK  (BB*SS)   // 8192

// ---------------- scratch (static device globals) ---------------------------
__device__ float  g_h   [NTOK*DD];
__device__ __half g_hh  [NTOK*DD];     // fp16 copy of g_h (GEMM operand)
__device__ __half g_qh  [NTOK*DD];     // Q fp16, pre-scaled, [B][H][S][32]
__device__ __half g_kh  [NTOK*DD];     // K fp16, [B][H][S][32]
__device__ __half g_vth [NTOK*DD];     // V fp16 transposed, [B][H][32][S]
__device__ __half g_ctxh[NTOK*DD];     // attention output (fp16)
__device__ float  g_tmp [NTOK*DD];
__device__ __half g_h1h [NTOK*EHID];   // MoE hidden (fp16, permuted rows)
__device__ float  g_pe  [SS*DD];
__device__ int    g_pad [NTOK];
__device__ int    g_eidx[NTOK];
__device__ float  g_ew  [NTOK];
__device__ int    g_cnt [NLAY*NEXP];
__device__ int    g_base[NEXP];
__device__ int    g_cursor[NEXP];
__device__ int    g_perm[NTOK];

// fp16 weight buffer (converted once per launch)
#define IPH_OFF 0
#define IPH_SZ  (NLAY*3*DD*DD)
#define OPH_OFF (IPH_OFF + IPH_SZ)
#define OPH_SZ  (NLAY*DD*DD)
#define W1H_OFF (OPH_OFF + OPH_SZ)
#define W1H_SZ  (NLAY*NEXP*EHID*DD)
#define W2H_OFF (W1H_OFF + W1H_SZ)
#define W2H_SZ  (NLAY*NEXP*DD*EHID)
#define WH_TOTAL (W2H_OFF + W2H_SZ)
__device__ __half g_wh[WH_TOTAL];

#define QKV_HSZ (BB*HH*SS*DHD)   // per-tensor halves (used for head indexing)

// ---------------- helpers ----------------------------------------------------
__device__ __forceinline__ void mma_f16(float* d, uint32_t a0, uint32_t a1,
                                        uint32_t a2, uint32_t a3,
                                        uint32_t b0, uint32_t b1)
{
    asm volatile(
        "mma.sync.aligned.m16n8k16.row.col.f32.f16.f16.f32 "
        "{%0,%1,%2,%3}, {%4,%5,%6,%7}, {%8,%9}, {%0,%1,%2,%3};\n"
        : "+f"(d[0]), "+f"(d[1]), "+f"(d[2]), "+f"(d[3])
        : "r"(a0), "r"(a1), "r"(a2), "r"(a3), "r"(b0), "r"(b1));
}

// fast exp on the FMA pipe (no MUFU), valid for x <= 0
__device__ __forceinline__ float fexp(float x)
{
    x = fmaxf(x, -87.0f);
    const float L2E = 1.4426950408889634f;
    float t  = fmaf(x, L2E, 12582912.0f);
    int   ki = __float_as_int(t) - 0x4B400000;
    float kf = t - 12582912.0f;
    float r  = fmaf(x, L2E, -kf);
    float p  = 1.3333558146e-3f;
    p = fmaf(p, r, 9.6181291076e-3f);
    p = fmaf(p, r, 5.5504108664e-2f);
    p = fmaf(p, r, 2.4022650696e-1f);
    p = fmaf(p, r, 6.9314718056e-1f);
    p = fmaf(p, r, 1.0f);
    return p * __int_as_float((ki + 127) << 23);
}

__device__ __forceinline__ uint32_t packh2(float a, float b)
{
    __half2 h = __floats2half2_rn(a, b);
    return *(uint32_t*)&h;
}

__device__ __forceinline__ void cp16(uint32_t dst, const void* src)
{
    asm volatile("cp.async.ca.shared.global [%0], [%1], 16;\n"
                 :: "r"(dst), "l"(src));
}

// ---------------- fp16 pipelined 128x128 GEMM core ---------------------------
#define HSTR 24
#define HBUF (128 * HSTR)

__device__ __forceinline__ void pipe16_mainloop(
    const __half* __restrict__ aptr,
    const __half* __restrict__ wptr,
    int K, __half* AsArr, __half* BsArr, float acc[4][4][4])
{
    int tid = threadIdx.x, lane = tid & 31, w = tid >> 5;
    int wm = w & 1, wn = w >> 1;
    int g = lane >> 2, T = lane & 3;
    int row = tid >> 1, seg = (tid & 1) * 8;

    uint32_t da = (uint32_t)__cvta_generic_to_shared(AsArr) + (row * HSTR + seg) * 2;
    uint32_t db = (uint32_t)__cvta_generic_to_shared(BsArr) + (row * HSTR + seg) * 2;
    const uint32_t BUFB = HBUF * 2;

    int KT = K / 16;

    cp16(da, aptr);
    cp16(db, wptr);
    asm volatile("cp.async.commit_group;\n");

    for (int kt = 0; kt < KT; kt++) {
        if (kt + 1 < KT) {
            uint32_t off = ((kt + 1) & 1) * BUFB;
            cp16(da + off, aptr + (kt + 1) * 16);
            cp16(db + off, wptr + (kt + 1) * 16);
            asm volatile("cp.async.commit_group;\n");
            asm volatile("cp.async.wait_group 1;\n");
        } else {
            asm volatile("cp.async.wait_group 0;\n");
        }
        __syncthreads();

        const __half* A = AsArr + (kt & 1) * HBUF;
        const __half* B = BsArr + (kt & 1) * HBUF;

        uint32_t afr[4][4], bfr[4][2];
        #pragma unroll
        for (int mt = 0; mt < 4; mt++) {
            int rb = wm * 64 + mt * 16 + g;
            afr[mt][0] = *(const uint32_t*)(A + rb * HSTR + 2 * T);
            afr[mt][1] = *(const uint32_t*)(A + (rb + 8) * HSTR + 2 * T);
            afr[mt][2] = *(const uint32_t*)(A + rb * HSTR + 8 + 2 * T);
            afr[mt][3] = *(const uint32_t*)(A + (rb + 8) * HSTR + 8 + 2 * T);
        }
        #pragma unroll
        for (int nt = 0; nt < 4; nt++) {
            int nb = wn * 32 + nt * 8 + g;
            bfr[nt][0] = *(const uint32_t*)(B + nb * HSTR + 2 * T);
            bfr[nt][1] = *(const uint32_t*)(B + nb * HSTR + 8 + 2 * T);
        }
        #pragma unroll
        for (int mt = 0; mt < 4; mt++)
            #pragma unroll
            for (int nt = 0; nt < 4; nt++)
                mma_f16(acc[mt][nt], afr[mt][0], afr[mt][1], afr[mt][2], afr[mt][3],
                        bfr[nt][0], bfr[nt][1]);
        __syncthreads();
    }
}

// ---------------- weight conversion (fp32 -> fp16) ---------------------------
__global__ void f2h_kernel(const float* __restrict__ src, __half* __restrict__ dst, int n4)
{
    int i = blockIdx.x * 256 + threadIdx.x;
    if (i < n4) {
        float4 v = ((const float4*)src)[i];
        ((__half2*)dst)[2 * i + 0] = __floats2half2_rn(v.x, v.y);
        ((__half2*)dst)[2 * i + 1] = __floats2half2_rn(v.z, v.w);
    }
}

// ---------------- positional encoding table ----------------------------------
__global__ void pe_kernel()
{
    int s = blockIdx.x, d = threadIdx.x;
    double freq = exp(-(double)(d & ~1) * (log(10000.0) / (double)DD));
    double arg  = (double)s * freq;
    g_pe[s * DD + d] = (d & 1) ? (float)cos(arg) : (float)sin(arg);
}

__global__ void zero_cnt_all()
{
    if (threadIdx.x < NLAY * NEXP) g_cnt[threadIdx.x] = 0;
}

// ---------------- embedding + pad mask ---------------------------------------
__global__ void embed_kernel(const int* __restrict__ x, const float* __restrict__ emb)
{
    int n = blockIdx.x;
    int d = threadIdx.x;
    int tok = x[n];
    int s = n & (SS - 1);

    float v = emb[(size_t)tok * DD + d] * 16.0f + g_pe[s * DD + d];
    g_h [(size_t)n * DD + d] = v;
    g_hh[(size_t)n * DD + d] = __float2half(v);

    float sum = v;
    #pragma unroll
    for (int o = 16; o > 0; o >>= 1) sum += __shfl_xor_sync(0xffffffffu, sum, o);
    __shared__ float ws[8];
    if ((d & 31) == 0) ws[d >> 5] = sum;
    __syncthreads();
    if (d == 0) {
        float t = 0.f;
        #pragma unroll
        for (int i = 0; i < 8; i++) t += ws[i];
        g_pad[n] = (t == 0.0f) ? 1 : 0;
    }
}

// ---------------- QKV GEMM (fp16) + fp16 split store (Q scaled, V transposed)
__global__ __launch_bounds__(256)
void gemm_qkv16(const __half* __restrict__ A,
                const __half* __restrict__ W,
                const float* __restrict__ bias)
{
    __shared__ __half As[2 * HBUF];
    __shared__ __half Bs[2 * HBUF];

    int tid = threadIdx.x, lane = tid & 31, w = tid >> 5;
    int wm = w & 1, wn = w >> 1, g = lane >> 2, T = lane & 3;
    int m0 = blockIdx.y * 128, n0 = blockIdx.x * 128;
    int row = tid >> 1, seg = (tid & 1) * 8;

    const float inv = 0.17677669529663689f;   // 1/sqrt(32)

    float acc[4][4][4] = {};
    pipe16_mainloop(A + (size_t)(m0 + row) * DD + seg,
                    W + (size_t)(n0 + row) * DD + seg, DD, As, Bs, acc);

    #pragma unroll
    for (int mt = 0; mt < 4; mt++) {
        #pragma unroll
        for (int nt = 0; nt < 4; nt++) {
            int r0 = m0 + wm * 64 + mt * 16 + g;
            int c0 = n0 + wn * 32 + nt * 8 + 2 * T;
            int t = c0 >> 8, h = (c0 >> 5) & 7, d = c0 & 31;
            float bx = bias[c0], by = bias[c0 + 1];
            #pragma unroll
            for (int half = 0; half < 2; half++) {
                int rr = r0 + half * 8;
                int b = rr >> 9, s = rr & (SS - 1);
                int bh = b * HH + h;
                float v0 = acc[mt][nt][half * 2 + 0] + bx;
                float v1 = acc[mt][nt][half * 2 + 1] + by;
                if (t == 0) {
                    *(uint32_t*)(g_qh + ((size_t)(bh * SS + s)) * DHD + d) =
                        packh2(v0 * inv, v1 * inv);
                } else if (t == 1) {
                    *(uint32_t*)(g_kh + ((size_t)(bh * SS + s)) * DHD + d) =
                        packh2(v0, v1);
                } else {
                    g_vth[((size_t)(bh * DHD + d    )) * SS + s] = __float2half(v0);
                    g_vth[((size_t)(bh * DHD + d + 1)) * SS + s] = __float2half(v1);
                }
            }
        }
    }
}

// ---------------- out-proj GEMM (fp16): C = A @ W^T + bias (fp32 out) --------
__global__ __launch_bounds__(256)
void gemm_out16(const __half* __restrict__ A,
                const __half* __restrict__ W,
                const float* __restrict__ bias,
                float* __restrict__ C, int Nc, int K)
{
    __shared__ __half As[2 * HBUF];
    __shared__ __half Bs[2 * HBUF];

    int tid = threadIdx.x, lane = tid & 31, w = tid >> 5;
    int wm = w & 1, wn = w >> 1, g = lane >> 2, T = lane & 3;
    int m0 = blockIdx.y * 128, n0 = blockIdx.x * 128;
    int row = tid >> 1, seg = (tid & 1) * 8;

    float acc[4][4][4] = {};
    pipe16_mainloop(A + (size_t)(m0 + row) * K + seg,
                    W + (size_t)(n0 + row) * K + seg, K, As, Bs, acc);

    #pragma unroll
    for (int mt = 0; mt < 4; mt++) {
        #pragma unroll
        for (int nt = 0; nt < 4; nt++) {
            int r0 = m0 + wm * 64 + mt * 16 + g;
            int c0 = n0 + wn * 32 + nt * 8 + 2 * T;
            float bx = bias[c0], by = bias[c0 + 1];
            #pragma unroll
            for (int half = 0; half < 2; half++) {
                int rr = r0 + half * 8;
                float2 v = make_float2(acc[mt][nt][half * 2 + 0] + bx,
                                       acc[mt][nt][half * 2 + 1] + by);
                *(float2*)(C + (size_t)rr * Nc + c0) = v;
            }
        }
    }
}

// ---------------- MoE GEMM1 (fp16): H = relu(Xperm @ W1[e]^T + b1) -----------
__global__ __launch_bounds__(256)
void moe_gemm1_16(const __half* __restrict__ w1, const float* __restrict__ b1,
                  const int* __restrict__ cnt_l)
{
    int y = blockIdx.y;
    int e = y >> 6, tile = y & 63;
    int cnt = cnt_l[e];
    if (tile * 128 >= cnt) return;
    int ebase = g_base[e];

    __shared__ __half As[2 * HBUF];
    __shared__ __half Bs[2 * HBUF];

    int tid = threadIdx.x, lane = tid & 31, w = tid >> 5;
    int wm = w & 1, wn = w >> 1, g = lane >> 2, T = lane & 3;
    int n0 = blockIdx.x * 128;
    int row = tid >> 1, seg = (tid & 1) * 8;

    int gr = tile * 128 + row;
    if (gr >= cnt) gr = cnt - 1;
    int token = g_perm[ebase + gr];

    float acc[4][4][4] = {};
    pipe16_mainloop(g_hh + (size_t)token * DD + seg,
                    w1 + (size_t)e * EHID * DD + (size_t)(n0 + row) * DD + seg,
                    DD, As, Bs, acc);

    #pragma unroll
    for (int mt = 0; mt < 4; mt++) {
        #pragma unroll
        for (int nt = 0; nt < 4; nt++) {
            int lr0 = wm * 64 + mt * 16 + g;
            int c0  = n0 + wn * 32 + nt * 8 + 2 * T;
            float bx = b1[e * EHID + c0], by = b1[e * EHID + c0 + 1];
            #pragma unroll
            for (int half = 0; half < 2; half++) {
                int grr = tile * 128 + lr0 + half * 8;
                if (grr < cnt) {
                    float v0 = fmaxf(acc[mt][nt][half * 2 + 0] + bx, 0.f);
                    float v1 = fmaxf(acc[mt][nt][half * 2 + 1] + by, 0.f);
                    *(uint32_t*)(g_h1h + (size_t)(ebase + grr) * EHID + c0) = packh2(v0, v1);
                }
            }
        }
    }
}

// ---------------- MoE GEMM2 (fp16): Y = gw*(H @ W2[e]^T + b2) ----------------
__global__ __launch_bounds__(256)
void moe_gemm2_16(const __half* __restrict__ w2, const float* __restrict__ b2,
                  const int* __restrict__ cnt_l)
{
    int y = blockIdx.y;
    int e = y >> 6, tile = y & 63;
    int cnt = cnt_l[e];
    if (tile * 128 >= cnt) return;
    int ebase = g_base[e];

    __shared__ __half As[2 * HBUF];
    __shared__ __half Bs[2 * HBUF];

    int tid = threadIdx.x, lane = tid & 31, w = tid >> 5;
    int wm = w & 1, wn = w >> 1, g = lane >> 2, T = lane & 3;
    int n0 = blockIdx.x * 128;
    int row = tid >> 1, seg = (tid & 1) * 8;

    int gr = tile * 128 + row;
    if (gr >= cnt) gr = cnt - 1;

    float acc[4][4][4] = {};
    pipe16_mainloop(g_h1h + (size_t)(ebase + gr) * EHID + seg,
                    w2 + (size_t)e * DD * EHID + (size_t)(n0 + row) * EHID + seg,
                    EHID, As, Bs, acc);

    #pragma unroll
    for (int mt = 0; mt < 4; mt++) {
        #pragma unroll
        for (int nt = 0; nt < 4; nt++) {
            int lr0 = wm * 64 + mt * 16 + g;
            int c0  = n0 + wn * 32 + nt * 8 + 2 * T;
            float bx = b2[e * DD + c0], by = b2[e * DD + c0 + 1];
            #pragma unroll
            for (int half = 0; half < 2; half++) {
                int grr = tile * 128 + lr0 + half * 8;
                if (grr < cnt) {
                    int token = g_perm[ebase + grr];
                    float gwv = g_ew[token];
                    float2 v = make_float2(gwv * (acc[mt][nt][half * 2 + 0] + bx),
                                           gwv * (acc[mt][nt][half * 2 + 1] + by));
                    *(float2*)(g_tmp + (size_t)token * DD + c0) = v;
                }
            }
        }
    }
}

// ---------------- flash attention (full fp16 datapath) -----------------------
#define QTILE 128
#define KCH   64
#define QH    40   // halves per Q/K smem row
#define VSTR  72   // halves per V^T smem row

__global__ void attn_fa_kernel()
{
    __shared__ __half Qs [QTILE * QH];   // 10 KB
    __shared__ __half Ks [KCH * QH];     // 5 KB
    __shared__ __half Vts[DHD * VSTR];   // 4.5 KB
    __shared__ int    mk[KCH];

    int qt = blockIdx.x, h = blockIdx.y, b = blockIdx.z;
    int tid = threadIdx.x, lane = tid & 31, w = tid >> 5;
    int g = lane >> 2, T = lane & 3;
    int bh = b * HH + h;

    const __half* Qgh = g_qh  + ((size_t)(bh * SS + qt * QTILE)) * DHD;
    const __half* Kgh = g_kh  + ((size_t)(bh * SS)) * DHD;
    const __half* Vgh = g_vth + ((size_t)bh * DHD) * SS;

    // load Q tile: 128 rows x 32 halves -> 512 uint4
    for (int i = tid; i < 512; i += 256) {
        int row = i >> 2, c = (i & 3) * 8;
        *(uint4*)(Qs + row * QH + c) = *(const uint4*)(Qgh + row * DHD + c);
    }

    float m_[2]  = {-1e30f, -1e30f};
    float sum_[2] = {0.f, 0.f};
    float o[4][4] = {};

    for (int kc = 0; kc < SS / KCH; kc++) {
        __syncthreads();
        {   // K chunk: 64 x 32 halves -> 256 uint4
            int row = tid >> 2, c = (tid & 3) * 8;
            *(uint4*)(Ks + row * QH + c) =
                *(const uint4*)(Kgh + (kc * KCH + row) * DHD + c);
        }
        {   // V^T chunk: 32 dims x 64 keys -> 256 uint4
            int d = tid >> 3, c = (tid & 7) * 8;
            *(uint4*)(Vts + d * VSTR + c) =
                *(const uint4*)(Vgh + (size_t)d * SS + kc * KCH + c);
        }
        if (tid < KCH) mk[tid] = g_pad[b * SS + kc * KCH + tid];
        __syncthreads();

        // ---- S = Q K^T (fp16 mma, 2 k-steps) ----
        float s[8][4];
        #pragma unroll
        for (int nt = 0; nt < 8; nt++)
            #pragma unroll
            for (int j = 0; j < 4; j++) s[nt][j] = 0.f;

        #pragma unroll
        for (int ks = 0; ks < 2; ks++) {
            int row = w * 16 + g, col = ks * 16 + 2 * T;
            uint32_t a0 = *(const uint32_t*)(Qs + row * QH + col);
            uint32_t a1 = *(const uint32_t*)(Qs + (row + 8) * QH + col);
            uint32_t a2 = *(const uint32_t*)(Qs + row * QH + col + 8);
            uint32_t a3 = *(const uint32_t*)(Qs + (row + 8) * QH + col + 8);
            #pragma unroll
            for (int nt = 0; nt < 8; nt++) {
                int kr = nt * 8 + g;
                uint32_t b0 = *(const uint32_t*)(Ks + kr * QH + col);
                uint32_t b1 = *(const uint32_t*)(Ks + kr * QH + col + 8);
                mma_f16(s[nt], a0, a1, a2, a3, b0, b1);
            }
        }

        #pragma unroll
        for (int nt = 0; nt < 8; nt++) {
            if (mk[nt * 8 + 2 * T])     { s[nt][0] = -1e9f; s[nt][2] = -1e9f; }
            if (mk[nt * 8 + 2 * T + 1]) { s[nt][1] = -1e9f; s[nt][3] = -1e9f; }
        }

        // ---- online softmax ----
        #pragma unroll
        for (int half = 0; half < 2; half++) {
            float cmax = -1e30f;
            #pragma unroll
            for (int nt = 0; nt < 8; nt++)
                cmax = fmaxf(cmax, fmaxf(s[nt][2 * half], s[nt][2 * half + 1]));
            cmax = fmaxf(cmax, __shfl_xor_sync(0xffffffffu, cmax, 1));
            cmax = fmaxf(cmax, __shfl_xor_sync(0xffffffffu, cmax, 2));
            float mnew  = fmaxf(m_[half], cmax);
            float scale = fexp(m_[half] - mnew);
            m_[half] = mnew;
            float part = 0.f;
            #pragma unroll
            for (int nt = 0; nt < 8; nt++) {
                float p0 = fexp(s[nt][2 * half]     - mnew);
                float p1 = fexp(s[nt][2 * half + 1] - mnew);
                s[nt][2 * half] = p0; s[nt][2 * half + 1] = p1;
                part += p0 + p1;
            }
            part += __shfl_xor_sync(0xffffffffu, part, 1);
            part += __shfl_xor_sync(0xffffffffu, part, 2);
            sum_[half] = sum_[half] * scale + part;
            #pragma unroll
            for (int nt = 0; nt < 4; nt++) {
                o[nt][2 * half]     *= scale;
                o[nt][2 * half + 1] *= scale;
            }
        }

        // ---- O += P @ V ----
        #pragma unroll
        for (int kt = 0; kt < 4; kt++) {
            uint32_t a0 = packh2(s[2 * kt][0],     s[2 * kt][1]);
            uint32_t a1 = packh2(s[2 * kt][2],     s[2 * kt][3]);
            uint32_t a2 = packh2(s[2 * kt + 1][0], s[2 * kt + 1][1]);
            uint32_t a3 = packh2(s[2 * kt + 1][2], s[2 * kt + 1][3]);
            #pragma unroll
            for (int nt = 0; nt < 4; nt++) {
                const __half* vp = &Vts[(nt * 8 + g) * VSTR + kt * 16 + 2 * T];
                uint32_t b0 = *(const uint32_t*)vp;
                uint32_t b1 = *(const uint32_t*)(vp + 8);
                mma_f16(o[nt], a0, a1, a2, a3, b0, b1);
            }
        }
    }

    float i0 = 1.0f / sum_[0];
    float i1 = 1.0f / sum_[1];
    int q0 = qt * QTILE + w * 16 + g;
    #pragma unroll
    for (int nt = 0; nt < 4; nt++) {
        int col = h * DHD + nt * 8 + 2 * T;
        *(uint32_t*)(g_ctxh + (size_t)(b * SS + q0) * DD + col) =
            packh2(o[nt][0] * i0, o[nt][1] * i0);
        *(uint32_t*)(g_ctxh + (size_t)(b * SS + q0 + 8) * DD + col) =
            packh2(o[nt][2] * i1, o[nt][3] * i1);
    }
}

// ---------------- fused residual + LN (+optional gate), warp per token -------
__device__ __forceinline__ void warp_add_ln(
    int n, int lane, const float* __restrict__ add,
    const float* __restrict__ gamma, const float* __restrict__ beta,
    float out[8])
{
    size_t base = (size_t)n * DD + lane;
    float v[8];
    float sum = 0.f;
    #pragma unroll
    for (int j = 0; j < 8; j++) {
        v[j] = g_h[base + 32 * j] + add[base + 32 * j];
        sum += v[j];
    }
    #pragma unroll
    for (int o = 16; o > 0; o >>= 1) sum += __shfl_xor_sync(0xffffffffu, sum, o);
    float mu = sum * (1.0f / DD);
    float sq = 0.f;
    #pragma unroll
    for (int j = 0; j < 8; j++) {
        v[j] -= mu;
        sq += v[j] * v[j];
    }
    #pragma unroll
    for (int o = 16; o > 0; o >>= 1) sq += __shfl_xor_sync(0xffffffffu, sq, o);
    float r = rsqrtf(sq * (1.0f / DD) + 1e-5f);
    #pragma unroll
    for (int j = 0; j < 8; j++) {
        out[j] = v[j] * r * gamma[lane + 32 * j] + beta[lane + 32 * j];
        g_h [base + 32 * j] = out[j];
        g_hh[base + 32 * j] = __float2half(out[j]);
    }
}

__global__ void add_ln2_kernel(const float* __restrict__ add,
                               const float* __restrict__ gamma,
                               const float* __restrict__ beta)
{
    int lane = threadIdx.x & 31;
    int n = blockIdx.x * 8 + (threadIdx.x >> 5);
    float out[8];
    warp_add_ln(n, lane, add, gamma, beta, out);
}

__global__ void add_ln1_gate_kernel(const float* __restrict__ add,
                                    const float* __restrict__ gamma,
                                    const float* __restrict__ beta,
                                    const float* __restrict__ gw,
                                    const float* __restrict__ gb,
                                    int* __restrict__ cnt_l)
{
    int lane = threadIdx.x & 31;
    int n = blockIdx.x * 8 + (threadIdx.x >> 5);
    float out[8];
    warp_add_ln(n, lane, add, gamma, beta, out);

    float lg[NEXP];
    #pragma unroll
    for (int e = 0; e < NEXP; e++) {
        float p = 0.f;
        #pragma unroll
        for (int j = 0; j < 8; j++)
            p = fmaf(gw[e * DD + lane + 32 * j], out[j], p);
        #pragma unroll
        for (int o = 16; o > 0; o >>= 1)
            p += __shfl_xor_sync(0xffffffffu, p, o);
        lg[e] = p;
    }
    if (lane == 0) {
        float m = -1e30f;
        #pragma unroll
        for (int i = 0; i < NEXP; i++) { lg[i] += gb[i]; m = fmaxf(m, lg[i]); }
        float p[NEXP], sum = 0.f;
        #pragma unroll
        for (int i = 0; i < NEXP; i++) { p[i] = expf(lg[i] - m); sum += p[i]; }
        int bi = 0; float bw = p[0];
        #pragma unroll
        for (int i = 1; i < NEXP; i++) if (p[i] > bw) { bw = p[i]; bi = i; }
        g_eidx[n] = bi;
        g_ew[n]   = bw / sum;
        atomicAdd(&cnt_l[bi], 1);
    }
}

// ---------------- routing bookkeeping ----------------------------------------
__global__ void prefix_kernel(const int* __restrict__ cnt_l)
{
    if (threadIdx.x == 0) {
        int acc = 0;
        #pragma unroll
        for (int e = 0; e < NEXP; e++) {
            g_base[e] = acc; g_cursor[e] = acc; acc += cnt_l[e];
        }
    }
}

__global__ void scatter_kernel()
{
    int n = blockIdx.x * blockDim.x + threadIdx.x;
    if (n < NTOK) {
        int e = g_eidx[n];
        int pos = atomicAdd(&g_cursor[e], 1);
        g_perm[pos] = n;
    }
}

// ---------------- masked mean pool + fc1(relu) + fc2 -------------------------
__global__ void head_kernel(const float* __restrict__ fc1w, const float* __restrict__ fc1b,
                            const float* __restrict__ fc2w, const float* __restrict__ fc2b,
                            float* __restrict__ out)
{
    int b = blockIdx.x, tid = threadIdx.x;
    __shared__ float pooled[DD];
    __shared__ float z[128];

    float s = 0.f;
    int cnt = 0;
    #pragma unroll 4
    for (int si = 0; si < SS; si++) {
        int n = b * SS + si;
        if (!g_pad[n]) { s += g_h[(size_t)n * DD + tid]; cnt++; }
    }
    pooled[tid] = s / fmaxf((float)cnt, 1.0f);
    __syncthreads();

    if (tid < 128) {
        float a = fc1b[tid];
        const float* wr = fc1w + (size_t)tid * DD;
        #pragma unroll 8
        for (int d = 0; d < DD; d++) a += pooled[d] * wr[d];
        z[tid] = fmaxf(a, 0.f);
    }
    __syncthreads();
    if (tid < 2) {
        float a = fc2b[tid];
        const float* wr = fc2w + (size_t)tid * 128;
        #pragma unroll 8
        for (int i = 0; i < 128; i++) a += z[i] * wr[i];
        out[b * 2 + tid] = a;
    }
}

// ---------------- host launch ------------------------------------------------
static void* sym_addr(const void* sym)
{
    void* p = nullptr;
    cudaGetSymbolAddress(&p, sym);
    return p;
}

extern "C" void kernel_launch(void* const* d_in, const int* in_sizes, int n_in,
                              void* d_out, int out_size)
{
    const int*   x          = (const int*)  d_in[0];
    const float* emb        = (const float*)d_in[1];
    const float* in_proj_w  = (const float*)d_in[2];
    const float* in_proj_b  = (const float*)d_in[3];
    const float* out_proj_w = (const float*)d_in[4];
    const float* out_proj_b = (const float*)d_in[5];
    const float* ln1_g      = (const float*)d_in[6];
    const float* ln1_b      = (const float*)d_in[7];
    const float* ln2_g      = (const float*)d_in[8];
    const float* ln2_b      = (const float*)d_in[9];
    const float* gate_w     = (const float*)d_in[10];
    const float* gate_b     = (const float*)d_in[11];
    const float* w1         = (const float*)d_in[12];
    const float* b1         = (const float*)d_in[13];
    const float* w2         = (const float*)d_in[14];
    const float* b2         = (const float*)d_in[15];
    const float* fc1_w      = (const float*)d_in[16];
    const float* fc1_b      = (const float*)d_in[17];
    const float* fc2_w      = (const float*)d_in[18];
    const float* fc2_b      = (const float*)d_in[19];
    float* out = (float*)d_out;

    __half* wh    = (__half*)sym_addr(g_wh);
    __half* hh    = (__half*)sym_addr(g_hh);
    __half* ctxh  = (__half*)sym_addr(g_ctxh);
    float*  p_tmp = (float*)sym_addr(g_tmp);
    int*    cnt   = (int*)sym_addr(g_cnt);

    pe_kernel<<<SS, DD>>>();
    zero_cnt_all<<<1, 32>>>();
    embed_kernel<<<NTOK, DD>>>(x, emb);
    f2h_kernel<<<(IPH_SZ/4 + 255)/256, 256>>>(in_proj_w,  wh + IPH_OFF, IPH_SZ/4);
    f2h_kernel<<<(OPH_SZ/4 + 255)/256, 256>>>(out_proj_w, wh + OPH_OFF, OPH_SZ/4);
    f2h_kernel<<<(W1H_SZ/4 + 255)/256, 256>>>(w1,         wh + W1H_OFF, W1H_SZ/4);
    f2h_kernel<<<(W2H_SZ/4 + 255)/256, 256>>>(w2,         wh + W2H_OFF, W2H_SZ/4);

    for (int l = 0; l < NLAY; l++) {
        int* cnt_l = cnt + l * NEXP;

        gemm_qkv16<<<dim3(3*DD/128, NTOK/128), 256>>>(
            hh, wh + IPH_OFF + (size_t)l * 3*DD*DD, in_proj_b + (size_t)l * 3*DD);

        attn_fa_kernel<<<dim3(SS/QTILE, HH, BB), 256>>>();

        gemm_out16<<<dim3(DD/128, NTOK/128), 256>>>(
            ctxh, wh + OPH_OFF + (size_t)l * DD*DD, out_proj_b + (size_t)l * DD,
            p_tmp, DD, DD);

        add_ln1_gate_kernel<<<NTOK/8, 256>>>(
            p_tmp, ln1_g + (size_t)l * DD, ln1_b + (size_t)l * DD,
            gate_w + (size_t)l * NEXP*DD, gate_b + (size_t)l * NEXP, cnt_l);
        prefix_kernel<<<1, 32>>>(cnt_l);
        scatter_kernel<<<NTOK/256, 256>>>();

        moe_gemm1_16<<<dim3(EHID/128, NEXP*64), 256>>>(
            wh + W1H_OFF + (size_t)l * NEXP*EHID*DD, b1 + (size_t)l * NEXP*EHID, cnt_l);
        moe_gemm2_16<<<dim3(DD/128, NEXP*64), 256>>>(
            wh + W2H_OFF + (size_t)l * NEXP*DD*EHID, b2 + (size_t)l * NEXP*DD, cnt_l);

        add_ln2_kernel<<<NTOK/8, 256>>>(
            p_tmp, ln2_g + (size_t)l * DD, ln2_b + (size_t)l * DD);
    }

    head_kernel<<<BB, 256>>>(fc1_w, fc1_b, fc2_w, fc2_b, out);
}

// round 9
// speedup vs baseline: 39.4498x; 1.2406x over previous
#include <cuda_runtime.h>
#include <cuda_fp16.h>
#include <math.h>
#include <stdint.h>

// ---------------- model dims ----------------
#define BB    16
#define SS    512
#define DD    256
#define HH    8
#define DHD   32
#define NLAY  2
#define NEXP  8
#define EHID  1024
#define NTOK  (BB*SS)   // 8192

// ---------------- scratch (static device globals) ---------------------------
__device__ float  g_h   [NTOK*DD];
__device__ __half g_hh  [NTOK*DD];
__device__ __half g_qh  [NTOK*DD];     // Q fp16, pre-scaled, [B][H][S][32]
__device__ __half g_kh  [NTOK*DD];     // K fp16, [B][H][S][32]
__device__ __half g_vth [NTOK*DD];     // V fp16 transposed, [B][H][32][S]
__device__ __half g_ctxh[NTOK*DD];
__device__ float  g_tmp [NTOK*DD];
__device__ __half g_h1h [NTOK*EHID];   // MoE hidden (fp16, permuted rows)
__device__ float  g_pe  [SS*DD];
__device__ int    g_pad [NTOK];
__device__ int    g_eidx[NTOK];
__device__ float  g_ew  [NTOK];
__device__ int    g_cnt [NLAY*NEXP];
__device__ int    g_base[NEXP];
__device__ int    g_cursor[NEXP];
__device__ int    g_perm[NTOK];
__device__ float  g_pool[BB*8*DD];
__device__ int    g_pcnt[BB*8];

// fp16 weight buffer (converted once per launch)
#define IPH_OFF 0
#define IPH_SZ  (NLAY*3*DD*DD)
#define OPH_OFF (IPH_OFF + IPH_SZ)
#define OPH_SZ  (NLAY*DD*DD)
#define W1H_OFF (OPH_OFF + OPH_SZ)
#define W1H_SZ  (NLAY*NEXP*EHID*DD)
#define W2H_OFF (W1H_OFF + W1H_SZ)
#define W2H_SZ  (NLAY*NEXP*DD*EHID)
#define WH_TOTAL (W2H_OFF + W2H_SZ)
__device__ __half g_wh[WH_TOTAL];

// ---------------- helpers ----------------------------------------------------
__device__ __forceinline__ void mma_f16(float* d, uint32_t a0, uint32_t a1,
                                        uint32_t a2, uint32_t a3,
                                        uint32_t b0, uint32_t b1)
{
    asm volatile(
        "mma.sync.aligned.m16n8k16.row.col.f32.f16.f16.f32 "
        "{%0,%1,%2,%3}, {%4,%5,%6,%7}, {%8,%9}, {%0,%1,%2,%3};\n"
        : "+f"(d[0]), "+f"(d[1]), "+f"(d[2]), "+f"(d[3])
        : "r"(a0), "r"(a1), "r"(a2), "r"(a3), "r"(b0), "r"(b1));
}

__device__ __forceinline__ void ldm_x4(uint32_t& r0, uint32_t& r1,
                                       uint32_t& r2, uint32_t& r3, uint32_t addr)
{
    asm volatile("ldmatrix.sync.aligned.m8n8.x4.shared.b16 {%0,%1,%2,%3}, [%4];"
                 : "=r"(r0), "=r"(r1), "=r"(r2), "=r"(r3) : "r"(addr));
}

__device__ __forceinline__ float fexp(float x)
{
    x = fmaxf(x, -87.0f);
    const float L2E = 1.4426950408889634f;
    float t  = fmaf(x, L2E, 12582912.0f);
    int   ki = __float_as_int(t) - 0x4B400000;
    float kf = t - 12582912.0f;
    float r  = fmaf(x, L2E, -kf);
    float p  = 1.3333558146e-3f;
    p = fmaf(p, r, 9.6181291076e-3f);
    p = fmaf(p, r, 5.5504108664e-2f);
    p = fmaf(p, r, 2.4022650696e-1f);
    p = fmaf(p, r, 6.9314718056e-1f);
    p = fmaf(p, r, 1.0f);
    return p * __int_as_float((ki + 127) << 23);
}

__device__ __forceinline__ uint32_t packh2(float a, float b)
{
    __half2 h = __floats2half2_rn(a, b);
    return *(uint32_t*)&h;
}

__device__ __forceinline__ void cp16(uint32_t dst, const void* src)
{
    asm volatile("cp.async.ca.shared.global [%0], [%1], 16;\n"
                 :: "r"(dst), "l"(src));
}

// ---------------- fp16 pipelined 128x128 GEMM core (ldmatrix frags) ----------
#define HSTR 24
#define HBUF (128 * HSTR)

__device__ __forceinline__ void pipe16_mainloop(
    const __half* __restrict__ aptr,
    const __half* __restrict__ wptr,
    int K, __half* AsArr, __half* BsArr, float acc[4][4][4])
{
    int tid = threadIdx.x, lane = tid & 31, w = tid >> 5;
    int wm = w & 1, wn = w >> 1;
    int row = tid >> 1, seg = (tid & 1) * 8;

    uint32_t aBase = (uint32_t)__cvta_generic_to_shared(AsArr);
    uint32_t bBase = (uint32_t)__cvta_generic_to_shared(BsArr);
    uint32_t da = aBase + (row * HSTR + seg) * 2;
    uint32_t db = bBase + (row * HSTR + seg) * 2;
    const uint32_t BUFB = HBUF * 2;

    // ldmatrix per-lane addresses (byte offsets)
    int l7 = lane & 7, lg1 = (lane >> 3) & 1, lg2 = (lane >> 4) & 1;
    uint32_t offA[4], offB[2];
    #pragma unroll
    for (int mt = 0; mt < 4; mt++) {
        int ar = wm * 64 + mt * 16 + l7 + lg1 * 8;
        offA[mt] = aBase + (ar * HSTR + lg2 * 8) * 2;
    }
    #pragma unroll
    for (int p = 0; p < 2; p++) {
        int br = wn * 32 + (2 * p + lg2) * 8 + l7;
        offB[p] = bBase + (br * HSTR + lg1 * 8) * 2;
    }

    int KT = K / 16;

    cp16(da, aptr);
    cp16(db, wptr);
    asm volatile("cp.async.commit_group;\n");

    for (int kt = 0; kt < KT; kt++) {
        if (kt + 1 < KT) {
            uint32_t off = ((kt + 1) & 1) * BUFB;
            cp16(da + off, aptr + (kt + 1) * 16);
            cp16(db + off, wptr + (kt + 1) * 16);
            asm volatile("cp.async.commit_group;\n");
            asm volatile("cp.async.wait_group 1;\n");
        } else {
            asm volatile("cp.async.wait_group 0;\n");
        }
        __syncthreads();

        uint32_t so = (kt & 1) * BUFB;

        uint32_t afr[4][4], bfr[4][2];
        #pragma unroll
        for (int mt = 0; mt < 4; mt++)
            ldm_x4(afr[mt][0], afr[mt][1], afr[mt][2], afr[mt][3], offA[mt] + so);
        ldm_x4(bfr[0][0], bfr[0][1], bfr[1][0], bfr[1][1], offB[0] + so);
        ldm_x4(bfr[2][0], bfr[2][1], bfr[3][0], bfr[3][1], offB[1] + so);

        #pragma unroll
        for (int mt = 0; mt < 4; mt++)
            #pragma unroll
            for (int nt = 0; nt < 4; nt++)
                mma_f16(acc[mt][nt], afr[mt][0], afr[mt][1], afr[mt][2], afr[mt][3],
                        bfr[nt][0], bfr[nt][1]);
        __syncthreads();
    }
}

// ---------------- weight conversion (fp32 -> fp16) ---------------------------
__global__ void f2h_kernel(const float* __restrict__ src, __half* __restrict__ dst, int n4)
{
    int i = blockIdx.x * 256 + threadIdx.x;
    if (i < n4) {
        float4 v = ((const float4*)src)[i];
        ((__half2*)dst)[2 * i + 0] = __floats2half2_rn(v.x, v.y);
        ((__half2*)dst)[2 * i + 1] = __floats2half2_rn(v.z, v.w);
    }
}

// ---------------- positional encoding (cheap FP64) ---------------------------
// block = d (256 blocks), thread = s (512 threads)
__global__ void pe_kernel()
{
    int d = blockIdx.x, s = threadIdx.x;
    __shared__ double freq_sh;
    if (threadIdx.x == 0)
        freq_sh = exp(-(double)(d & ~1) * (log(10000.0) / (double)DD));
    __syncthreads();
    double arg = (double)s * freq_sh;
    const double TWOPI = 6.283185307179586476925286766559;
    double r = arg - TWOPI * rint(arg * (1.0 / TWOPI));
    float rf = (float)r;
    g_pe[s * DD + d] = (d & 1) ? cosf(rf) : sinf(rf);
}

__global__ void zero_cnt_all()
{
    if (threadIdx.x < NLAY * NEXP) g_cnt[threadIdx.x] = 0;
}

// ---------------- embedding + pad mask ---------------------------------------
__global__ void embed_kernel(const int* __restrict__ x, const float* __restrict__ emb)
{
    int n = blockIdx.x;
    int d = threadIdx.x;
    int tok = x[n];
    int s = n & (SS - 1);

    float v = emb[(size_t)tok * DD + d] * 16.0f + g_pe[s * DD + d];
    g_h [(size_t)n * DD + d] = v;
    g_hh[(size_t)n * DD + d] = __float2half(v);

    float sum = v;
    #pragma unroll
    for (int o = 16; o > 0; o >>= 1) sum += __shfl_xor_sync(0xffffffffu, sum, o);
    __shared__ float ws[8];
    if ((d & 31) == 0) ws[d >> 5] = sum;
    __syncthreads();
    if (d == 0) {
        float t = 0.f;
        #pragma unroll
        for (int i = 0; i < 8; i++) t += ws[i];
        g_pad[n] = (t == 0.0f) ? 1 : 0;
    }
}

// ---------------- QKV GEMM (fp16) + fp16 split store -------------------------
__global__ __launch_bounds__(256)
void gemm_qkv16(const __half* __restrict__ A,
                const __half* __restrict__ W,
                const float* __restrict__ bias)
{
    __shared__ __align__(16) __half As[2 * HBUF];
    __shared__ __align__(16) __half Bs[2 * HBUF];

    int tid = threadIdx.x, lane = tid & 31, w = tid >> 5;
    int wm = w & 1, wn = w >> 1, g = lane >> 2, T = lane & 3;
    int m0 = blockIdx.y * 128, n0 = blockIdx.x * 128;
    int row = tid >> 1, seg = (tid & 1) * 8;

    const float inv = 0.17677669529663689f;

    float acc[4][4][4] = {};
    pipe16_mainloop(A + (size_t)(m0 + row) * DD + seg,
                    W + (size_t)(n0 + row) * DD + seg, DD, As, Bs, acc);

    #pragma unroll
    for (int mt = 0; mt < 4; mt++) {
        #pragma unroll
        for (int nt = 0; nt < 4; nt++) {
            int r0 = m0 + wm * 64 + mt * 16 + g;
            int c0 = n0 + wn * 32 + nt * 8 + 2 * T;
            int t = c0 >> 8, h = (c0 >> 5) & 7, d = c0 & 31;
            float bx = bias[c0], by = bias[c0 + 1];
            #pragma unroll
            for (int half = 0; half < 2; half++) {
                int rr = r0 + half * 8;
                int b = rr >> 9, s = rr & (SS - 1);
                int bh = b * HH + h;
                float v0 = acc[mt][nt][half * 2 + 0] + bx;
                float v1 = acc[mt][nt][half * 2 + 1] + by;
                if (t == 0) {
                    *(uint32_t*)(g_qh + ((size_t)(bh * SS + s)) * DHD + d) =
                        packh2(v0 * inv, v1 * inv);
                } else if (t == 1) {
                    *(uint32_t*)(g_kh + ((size_t)(bh * SS + s)) * DHD + d) =
                        packh2(v0, v1);
                } else {
                    g_vth[((size_t)(bh * DHD + d    )) * SS + s] = __float2half(v0);
                    g_vth[((size_t)(bh * DHD + d + 1)) * SS + s] = __float2half(v1);
                }
            }
        }
    }
}

// ---------------- out-proj GEMM (fp16) ---------------------------------------
__global__ __launch_bounds__(256)
void gemm_out16(const __half* __restrict__ A,
                const __half* __restrict__ W,
                const float* __restrict__ bias,
                float* __restrict__ C, int Nc, int K)
{
    __shared__ __align__(16) __half As[2 * HBUF];
    __shared__ __align__(16) __half Bs[2 * HBUF];

    int tid = threadIdx.x, lane = tid & 31, w = tid >> 5;
    int wm = w & 1, wn = w >> 1, g = lane >> 2, T = lane & 3;
    int m0 = blockIdx.y * 128, n0 = blockIdx.x * 128;
    int row = tid >> 1, seg = (tid & 1) * 8;

    float acc[4][4][4] = {};
    pipe16_mainloop(A + (size_t)(m0 + row) * K + seg,
                    W + (size_t)(n0 + row) * K + seg, K, As, Bs, acc);

    #pragma unroll
    for (int mt = 0; mt < 4; mt++) {
        #pragma unroll
        for (int nt = 0; nt < 4; nt++) {
            int r0 = m0 + wm * 64 + mt * 16 + g;
            int c0 = n0 + wn * 32 + nt * 8 + 2 * T;
            float bx = bias[c0], by = bias[c0 + 1];
            #pragma unroll
            for (int half = 0; half < 2; half++) {
                int rr = r0 + half * 8;
                float2 v = make_float2(acc[mt][nt][half * 2 + 0] + bx,
                                       acc[mt][nt][half * 2 + 1] + by);
                *(float2*)(C + (size_t)rr * Nc + c0) = v;
            }
        }
    }
}

// ---------------- MoE GEMM1 (fp16): H = relu(Xperm @ W1[e]^T + b1) -----------
__global__ __launch_bounds__(256)
void moe_gemm1_16(const __half* __restrict__ w1, const float* __restrict__ b1,
                  const int* __restrict__ cnt_l)
{
    int y = blockIdx.y;
    int e = y >> 6, tile = y & 63;
    int cnt = cnt_l[e];
    if (tile * 128 >= cnt) return;
    int ebase = g_base[e];

    __shared__ __align__(16) __half As[2 * HBUF];
    __shared__ __align__(16) __half Bs[2 * HBUF];

    int tid = threadIdx.x, lane = tid & 31, w = tid >> 5;
    int wm = w & 1, wn = w >> 1, g = lane >> 2, T = lane & 3;
    int n0 = blockIdx.x * 128;
    int row = tid >> 1, seg = (tid & 1) * 8;

    int gr = tile * 128 + row;
    if (gr >= cnt) gr = cnt - 1;
    int token = g_perm[ebase + gr];

    float acc[4][4][4] = {};
    pipe16_mainloop(g_hh + (size_t)token * DD + seg,
                    w1 + (size_t)e * EHID * DD + (size_t)(n0 + row) * DD + seg,
                    DD, As, Bs, acc);

    #pragma unroll
    for (int mt = 0; mt < 4; mt++) {
        #pragma unroll
        for (int nt = 0; nt < 4; nt++) {
            int lr0 = wm * 64 + mt * 16 + g;
            int c0  = n0 + wn * 32 + nt * 8 + 2 * T;
            float bx = b1[e * EHID + c0], by = b1[e * EHID + c0 + 1];
            #pragma unroll
            for (int half = 0; half < 2; half++) {
                int grr = tile * 128 + lr0 + half * 8;
                if (grr < cnt) {
                    float v0 = fmaxf(acc[mt][nt][half * 2 + 0] + bx, 0.f);
                    float v1 = fmaxf(acc[mt][nt][half * 2 + 1] + by, 0.f);
                    *(uint32_t*)(g_h1h + (size_t)(ebase + grr) * EHID + c0) = packh2(v0, v1);
                }
            }
        }
    }
}

// ---------------- MoE GEMM2 (fp16): Y = gw*(H @ W2[e]^T + b2) ----------------
__global__ __launch_bounds__(256)
void moe_gemm2_16(const __half* __restrict__ w2, const float* __restrict__ b2,
                  const int* __restrict__ cnt_l)
{
    int y = blockIdx.y;
    int e = y >> 6, tile = y & 63;
    int cnt = cnt_l[e];
    if (tile * 128 >= cnt) return;
    int ebase = g_base[e];

    __shared__ __align__(16) __half As[2 * HBUF];
    __shared__ __align__(16) __half Bs[2 * HBUF];

    int tid = threadIdx.x, lane = tid & 31, w = tid >> 5;
    int wm = w & 1, wn = w >> 1, g = lane >> 2, T = lane & 3;
    int n0 = blockIdx.x * 128;
    int row = tid >> 1, seg = (tid & 1) * 8;

    int gr = tile * 128 + row;
    if (gr >= cnt) gr = cnt - 1;

    float acc[4][4][4] = {};
    pipe16_mainloop(g_h1h + (size_t)(ebase + gr) * EHID + seg,
                    w2 + (size_t)e * DD * EHID + (size_t)(n0 + row) * EHID + seg,
                    EHID, As, Bs, acc);

    #pragma unroll
    for (int mt = 0; mt < 4; mt++) {
        #pragma unroll
        for (int nt = 0; nt < 4; nt++) {
            int lr0 = wm * 64 + mt * 16 + g;
            int c0  = n0 + wn * 32 + nt * 8 + 2 * T;
            float bx = b2[e * DD + c0], by = b2[e * DD + c0 + 1];
            #pragma unroll
            for (int half = 0; half < 2; half++) {
                int grr = tile * 128 + lr0 + half * 8;
                if (grr < cnt) {
                    int token = g_perm[ebase + grr];
                    float gwv = g_ew[token];
                    float2 v = make_float2(gwv * (acc[mt][nt][half * 2 + 0] + bx),
                                           gwv * (acc[mt][nt][half * 2 + 1] + by));
                    *(float2*)(g_tmp + (size_t)token * DD + c0) = v;
                }
            }
        }
    }
}

// ---------------- flash attention (full fp16 datapath) -----------------------
#define QTILE 128
#define KCH   64
#define QH    40
#define VSTR  72

__global__ void attn_fa_kernel()
{
    __shared__ __align__(16) __half Qs [QTILE * QH];
    __shared__ __align__(16) __half Ks [KCH * QH];
    __shared__ __align__(16) __half Vts[DHD * VSTR];
    __shared__ int    mk[KCH];

    int qt = blockIdx.x, h = blockIdx.y, b = blockIdx.z;
    int tid = threadIdx.x, lane = tid & 31, w = tid >> 5;
    int g = lane >> 2, T = lane & 3;
    int bh = b * HH + h;

    const __half* Qgh = g_qh  + ((size_t)(bh * SS + qt * QTILE)) * DHD;
    const __half* Kgh = g_kh  + ((size_t)(bh * SS)) * DHD;
    const __half* Vgh = g_vth + ((size_t)bh * DHD) * SS;

    for (int i = tid; i < 512; i += 256) {
        int row = i >> 2, c = (i & 3) * 8;
        *(uint4*)(Qs + row * QH + c) = *(const uint4*)(Qgh + row * DHD + c);
    }

    float m_[2]  = {-1e30f, -1e30f};
    float sum_[2] = {0.f, 0.f};
    float o[4][4] = {};

    for (int kc = 0; kc < SS / KCH; kc++) {
        __syncthreads();
        {
            int row = tid >> 2, c = (tid & 3) * 8;
            *(uint4*)(Ks + row * QH + c) =
                *(const uint4*)(Kgh + (kc * KCH + row) * DHD + c);
        }
        {
            int d = tid >> 3, c = (tid & 7) * 8;
            *(uint4*)(Vts + d * VSTR + c) =
                *(const uint4*)(Vgh + (size_t)d * SS + kc * KCH + c);
        }
        if (tid < KCH) mk[tid] = g_pad[b * SS + kc * KCH + tid];
        __syncthreads();

        float s[8][4];
        #pragma unroll
        for (int nt = 0; nt < 8; nt++)
            #pragma unroll
            for (int j = 0; j < 4; j++) s[nt][j] = 0.f;

        #pragma unroll
        for (int ks = 0; ks < 2; ks++) {
            int row = w * 16 + g, col = ks * 16 + 2 * T;
            uint32_t a0 = *(const uint32_t*)(Qs + row * QH + col);
            uint32_t a1 = *(const uint32_t*)(Qs + (row + 8) * QH + col);
            uint32_t a2 = *(const uint32_t*)(Qs + row * QH + col + 8);
            uint32_t a3 = *(const uint32_t*)(Qs + (row + 8) * QH + col + 8);
            #pragma unroll
            for (int nt = 0; nt < 8; nt++) {
                int kr = nt * 8 + g;
                uint32_t b0 = *(const uint32_t*)(Ks + kr * QH + col);
                uint32_t b1 = *(const uint32_t*)(Ks + kr * QH + col + 8);
                mma_f16(s[nt], a0, a1, a2, a3, b0, b1);
            }
        }

        #pragma unroll
        for (int nt = 0; nt < 8; nt++) {
            if (mk[nt * 8 + 2 * T])     { s[nt][0] = -1e9f; s[nt][2] = -1e9f; }
            if (mk[nt * 8 + 2 * T + 1]) { s[nt][1] = -1e9f; s[nt][3] = -1e9f; }
        }

        #pragma unroll
        for (int half = 0; half < 2; half++) {
            float cmax = -1e30f;
            #pragma unroll
            for (int nt = 0; nt < 8; nt++)
                cmax = fmaxf(cmax, fmaxf(s[nt][2 * half], s[nt][2 * half + 1]));
            cmax = fmaxf(cmax, __shfl_xor_sync(0xffffffffu, cmax, 1));
            cmax = fmaxf(cmax, __shfl_xor_sync(0xffffffffu, cmax, 2));
            float mnew  = fmaxf(m_[half], cmax);
            float scale = fexp(m_[half] - mnew);
            m_[half] = mnew;
            float part = 0.f;
            #pragma unroll
            for (int nt = 0; nt < 8; nt++) {
                float p0 = fexp(s[nt][2 * half]     - mnew);
                float p1 = fexp(s[nt][2 * half + 1] - mnew);
                s[nt][2 * half] = p0; s[nt][2 * half + 1] = p1;
                part += p0 + p1;
            }
            part += __shfl_xor_sync(0xffffffffu, part, 1);
            part += __shfl_xor_sync(0xffffffffu, part, 2);
            sum_[half] = sum_[half] * scale + part;
            #pragma unroll
            for (int nt = 0; nt < 4; nt++) {
                o[nt][2 * half]     *= scale;
                o[nt][2 * half + 1] *= scale;
            }
        }

        #pragma unroll
        for (int kt = 0; kt < 4; kt++) {
            uint32_t a0 = packh2(s[2 * kt][0],     s[2 * kt][1]);
            uint32_t a1 = packh2(s[2 * kt][2],     s[2 * kt][3]);
            uint32_t a2 = packh2(s[2 * kt + 1][0], s[2 * kt + 1][1]);
            uint32_t a3 = packh2(s[2 * kt + 1][2], s[2 * kt + 1][3]);
            #pragma unroll
            for (int nt = 0; nt < 4; nt++) {
                const __half* vp = &Vts[(nt * 8 + g) * VSTR + kt * 16 + 2 * T];
                uint32_t b0 = *(const uint32_t*)vp;
                uint32_t b1 = *(const uint32_t*)(vp + 8);
                mma_f16(o[nt], a0, a1, a2, a3, b0, b1);
            }
        }
    }

    float i0 = 1.0f / sum_[0];
    float i1 = 1.0f / sum_[1];
    int q0 = qt * QTILE + w * 16 + g;
    #pragma unroll
    for (int nt = 0; nt < 4; nt++) {
        int col = h * DHD + nt * 8 + 2 * T;
        *(uint32_t*)(g_ctxh + (size_t)(b * SS + q0) * DD + col) =
            packh2(o[nt][0] * i0, o[nt][1] * i0);
        *(uint32_t*)(g_ctxh + (size_t)(b * SS + q0 + 8) * DD + col) =
            packh2(o[nt][2] * i1, o[nt][3] * i1);
    }
}

// ---------------- fused residual + LN (+optional gate) -----------------------
__device__ __forceinline__ void warp_add_ln(
    int n, int lane, const float* __restrict__ add,
    const float* __restrict__ gamma, const float* __restrict__ beta,
    float out[8])
{
    size_t base = (size_t)n * DD + lane;
    float v[8];
    float sum = 0.f;
    #pragma unroll
    for (int j = 0; j < 8; j++) {
        v[j] = g_h[base + 32 * j] + add[base + 32 * j];
        sum += v[j];
    }
    #pragma unroll
    for (int o = 16; o > 0; o >>= 1) sum += __shfl_xor_sync(0xffffffffu, sum, o);
    float mu = sum * (1.0f / DD);
    float sq = 0.f;
    #pragma unroll
    for (int j = 0; j < 8; j++) {
        v[j] -= mu;
        sq += v[j] * v[j];
    }
    #pragma unroll
    for (int o = 16; o > 0; o >>= 1) sq += __shfl_xor_sync(0xffffffffu, sq, o);
    float r = rsqrtf(sq * (1.0f / DD) + 1e-5f);
    #pragma unroll
    for (int j = 0; j < 8; j++) {
        out[j] = v[j] * r * gamma[lane + 32 * j] + beta[lane + 32 * j];
        g_h [base + 32 * j] = out[j];
        g_hh[base + 32 * j] = __float2half(out[j]);
    }
}

__global__ void add_ln2_kernel(const float* __restrict__ add,
                               const float* __restrict__ gamma,
                               const float* __restrict__ beta)
{
    int lane = threadIdx.x & 31;
    int n = blockIdx.x * 8 + (threadIdx.x >> 5);
    float out[8];
    warp_add_ln(n, lane, add, gamma, beta, out);
}

__global__ void add_ln1_gate_kernel(const float* __restrict__ add,
                                    const float* __restrict__ gamma,
                                    const float* __restrict__ beta,
                                    const float* __restrict__ gw,
                                    const float* __restrict__ gb,
                                    int* __restrict__ cnt_l)
{
    int lane = threadIdx.x & 31;
    int n = blockIdx.x * 8 + (threadIdx.x >> 5);
    float out[8];
    warp_add_ln(n, lane, add, gamma, beta, out);

    float lg[NEXP];
    #pragma unroll
    for (int e = 0; e < NEXP; e++) {
        float p = 0.f;
        #pragma unroll
        for (int j = 0; j < 8; j++)
            p = fmaf(gw[e * DD + lane + 32 * j], out[j], p);
        #pragma unroll
        for (int o = 16; o > 0; o >>= 1)
            p += __shfl_xor_sync(0xffffffffu, p, o);
        lg[e] = p;
    }
    if (lane == 0) {
        float m = -1e30f;
        #pragma unroll
        for (int i = 0; i < NEXP; i++) { lg[i] += gb[i]; m = fmaxf(m, lg[i]); }
        float p[NEXP], sum = 0.f;
        #pragma unroll
        for (int i = 0; i < NEXP; i++) { p[i] = expf(lg[i] - m); sum += p[i]; }
        int bi = 0; float bw = p[0];
        #pragma unroll
        for (int i = 1; i < NEXP; i++) if (p[i] > bw) { bw = p[i]; bi = i; }
        g_eidx[n] = bi;
        g_ew[n]   = bw / sum;
        atomicAdd(&cnt_l[bi], 1);
    }
}

// ---------------- routing bookkeeping ----------------------------------------
__global__ void prefix_kernel(const int* __restrict__ cnt_l)
{
    if (threadIdx.x == 0) {
        int acc = 0;
        #pragma unroll
        for (int e = 0; e < NEXP; e++) {
            g_base[e] = acc; g_cursor[e] = acc; acc += cnt_l[e];
        }
    }
}

__global__ void scatter_kernel()
{
    int n = blockIdx.x * blockDim.x + threadIdx.x;
    if (n < NTOK) {
        int e = g_eidx[n];
        int pos = atomicAdd(&g_cursor[e], 1);
        g_perm[pos] = n;
    }
}

// ---------------- head: partial pooling (deterministic) ----------------------
__global__ void pool_kernel()
{
    int b = blockIdx.x, c = blockIdx.y;
    int tid = threadIdx.x;
    int base = b * SS + c * 64;
    float s = 0.f;
    #pragma unroll 8
    for (int i = 0; i < 64; i++) {
        int n = base + i;
        if (!g_pad[n]) s += g_h[(size_t)n * DD + tid];
    }
    g_pool[(b * 8 + c) * DD + tid] = s;
    if (tid == 0) {
        int t = 0;
        #pragma unroll 8
        for (int i = 0; i < 64; i++) t += (g_pad[base + i] == 0);
        g_pcnt[b * 8 + c] = t;
    }
}

__global__ void head_final(const float* __restrict__ fc1w, const float* __restrict__ fc1b,
                           const float* __restrict__ fc2w, const float* __restrict__ fc2b,
                           float* __restrict__ out)
{
    int b = blockIdx.x, tid = threadIdx.x;
    __shared__ float pooled[DD];
    __shared__ float z[128];
    __shared__ int scnt;

    float s = 0.f;
    #pragma unroll
    for (int c = 0; c < 8; c++) s += g_pool[(b * 8 + c) * DD + tid];
    if (tid == 0) {
        int t = 0;
        #pragma unroll
        for (int c = 0; c < 8; c++) t += g_pcnt[b * 8 + c];
        scnt = t;
    }
    __syncthreads();
    pooled[tid] = s / fmaxf((float)scnt, 1.0f);
    __syncthreads();

    if (tid < 128) {
        float a = fc1b[tid];
        const float* wr = fc1w + (size_t)tid * DD;
        #pragma unroll 8
        for (int d = 0; d < DD; d++) a += pooled[d] * wr[d];
        z[tid] = fmaxf(a, 0.f);
    }
    __syncthreads();
    if (tid < 2) {
        float a = fc2b[tid];
        const float* wr = fc2w + (size_t)tid * 128;
        #pragma unroll 8
        for (int i = 0; i < 128; i++) a += z[i] * wr[i];
        out[b * 2 + tid] = a;
    }
}

// ---------------- host launch ------------------------------------------------
static void* sym_addr(const void* sym)
{
    void* p = nullptr;
    cudaGetSymbolAddress(&p, sym);
    return p;
}

extern "C" void kernel_launch(void* const* d_in, const int* in_sizes, int n_in,
                              void* d_out, int out_size)
{
    const int*   x          = (const int*)  d_in[0];
    const float* emb        = (const float*)d_in[1];
    const float* in_proj_w  = (const float*)d_in[2];
    const float* in_proj_b  = (const float*)d_in[3];
    const float* out_proj_w = (const float*)d_in[4];
    const float* out_proj_b = (const float*)d_in[5];
    const float* ln1_g      = (const float*)d_in[6];
    const float* ln1_b      = (const float*)d_in[7];
    const float* ln2_g      = (const float*)d_in[8];
    const float* ln2_b      = (const float*)d_in[9];
    const float* gate_w     = (const float*)d_in[10];
    const float* gate_b     = (const float*)d_in[11];
    const float* w1         = (const float*)d_in[12];
    const float* b1         = (const float*)d_in[13];
    const float* w2         = (const float*)d_in[14];
    const float* b2         = (const float*)d_in[15];
    const float* fc1_w      = (const float*)d_in[16];
    const float* fc1_b      = (const float*)d_in[17];
    const float* fc2_w      = (const float*)d_in[18];
    const float* fc2_b      = (const float*)d_in[19];
    float* out = (float*)d_out;

    __half* wh    = (__half*)sym_addr(g_wh);
    __half* hh    = (__half*)sym_addr(g_hh);
    __half* ctxh  = (__half*)sym_addr(g_ctxh);
    float*  p_tmp = (float*)sym_addr(g_tmp);
    int*    cnt   = (int*)sym_addr(g_cnt);

    pe_kernel<<<DD, SS>>>();
    zero_cnt_all<<<1, 32>>>();
    embed_kernel<<<NTOK, DD>>>(x, emb);
    f2h_kernel<<<(IPH_SZ/4 + 255)/256, 256>>>(in_proj_w,  wh + IPH_OFF, IPH_SZ/4);
    f2h_kernel<<<(OPH_SZ/4 + 255)/256, 256>>>(out_proj_w, wh + OPH_OFF, OPH_SZ/4);
    f2h_kernel<<<(W1H_SZ/4 + 255)/256, 256>>>(w1,         wh + W1H_OFF, W1H_SZ/4);
    f2h_kernel<<<(W2H_SZ/4 + 255)/256, 256>>>(w2,         wh + W2H_OFF, W2H_SZ/4);

    for (int l = 0; l < NLAY; l++) {
        int* cnt_l = cnt + l * NEXP;

        gemm_qkv16<<<dim3(3*DD/128, NTOK/128), 256>>>(
            hh, wh + IPH_OFF + (size_t)l * 3*DD*DD, in_proj_b + (size_t)l * 3*DD);

        attn_fa_kernel<<<dim3(SS/QTILE, HH, BB), 256>>>();

        gemm_out16<<<dim3(DD/128, NTOK/128), 256>>>(
            ctxh, wh + OPH_OFF + (size_t)l * DD*DD, out_proj_b + (size_t)l * DD,
            p_tmp, DD, DD);

        add_ln1_gate_kernel<<<NTOK/8, 256>>>(
            p_tmp, ln1_g + (size_t)l * DD, ln1_b + (size_t)l * DD,
            gate_w + (size_t)l * NEXP*DD, gate_b + (size_t)l * NEXP, cnt_l);
        prefix_kernel<<<1, 32>>>(cnt_l);
        scatter_kernel<<<NTOK/256, 256>>>();

        moe_gemm1_16<<<dim3(EHID/128, NEXP*64), 256>>>(
            wh + W1H_OFF + (size_t)l * NEXP*EHID*DD, b1 + (size_t)l * NEXP*EHID, cnt_l);
        moe_gemm2_16<<<dim3(DD/128, NEXP*64), 256>>>(
            wh + W2H_OFF + (size_t)l * NEXP*DD*EHID, b2 + (size_t)l * NEXP*DD, cnt_l);

        add_ln2_kernel<<<NTOK/8, 256>>>(
            p_tmp, ln2_g + (size_t)l * DD, ln2_b + (size_t)l * DD);
    }

    pool_kernel<<<dim3(BB, 8), 256>>>();
    head_final<<<BB, 256>>>(fc1_w, fc1_b, fc2_w, fc2_b, out);
}

// round 10
// speedup vs baseline: 43.5775x; 1.1046x over previous
#include <cuda_runtime.h>
#include <cuda_fp16.h>
#include <math.h>
#include <stdint.h>

// ---------------- model dims ----------------
#define BB    16
#define SS    512
#define DD    256
#define HH    8
#define DHD   32
#define NLAY  2
#define NEXP  8
#define EHID  1024
#define NTOK  (BB*SS)   // 8192

// ---------------- scratch (static device globals) ---------------------------
__device__ float  g_h   [NTOK*DD];
__device__ __half g_hh  [NTOK*DD];
__device__ __half g_qh  [NTOK*DD];     // Q fp16, pre-scaled, [B][H][S][32]
__device__ __half g_kh  [NTOK*DD];     // K fp16, [B][H][S][32]
__device__ __half g_vth [NTOK*DD];     // V fp16 transposed, [B][H][32][S]
__device__ __half g_ctxh[NTOK*DD];
__device__ float  g_tmp [NTOK*DD];
__device__ __half g_h1h [NTOK*EHID];   // MoE hidden (fp16, permuted rows)
__device__ float  g_pe  [SS*DD];
__device__ int    g_pad [NTOK];
__device__ int    g_eidx[NTOK];
__device__ float  g_ew  [NTOK];
__device__ int    g_cnt [NLAY*NEXP];
__device__ int    g_base[NEXP];
__device__ int    g_cursor[NEXP];
__device__ int    g_perm[NTOK];
__device__ float  g_pool[BB*8*DD];
__device__ int    g_pcnt[BB*8];
__device__ int    g_tiletab[80];
__device__ int    g_ntiles;

// fp16 weight buffer (converted once per launch)
#define IPH_OFF 0
#define IPH_SZ  (NLAY*3*DD*DD)
#define OPH_OFF (IPH_OFF + IPH_SZ)
#define OPH_SZ  (NLAY*DD*DD)
#define W1H_OFF (OPH_OFF + OPH_SZ)
#define W1H_SZ  (NLAY*NEXP*EHID*DD)
#define W2H_OFF (W1H_OFF + W1H_SZ)
#define W2H_SZ  (NLAY*NEXP*DD*EHID)
#define WH_TOTAL (W2H_OFF + W2H_SZ)
__device__ __half g_wh[WH_TOTAL];

// ---------------- helpers ----------------------------------------------------
__device__ __forceinline__ void mma_f16(float* d, uint32_t a0, uint32_t a1,
                                        uint32_t a2, uint32_t a3,
                                        uint32_t b0, uint32_t b1)
{
    asm volatile(
        "mma.sync.aligned.m16n8k16.row.col.f32.f16.f16.f32 "
        "{%0,%1,%2,%3}, {%4,%5,%6,%7}, {%8,%9}, {%0,%1,%2,%3};\n"
        : "+f"(d[0]), "+f"(d[1]), "+f"(d[2]), "+f"(d[3])
        : "r"(a0), "r"(a1), "r"(a2), "r"(a3), "r"(b0), "r"(b1));
}

__device__ __forceinline__ void ldm_x4(uint32_t& r0, uint32_t& r1,
                                       uint32_t& r2, uint32_t& r3, uint32_t addr)
{
    asm volatile("ldmatrix.sync.aligned.m8n8.x4.shared.b16 {%0,%1,%2,%3}, [%4];"
                 : "=r"(r0), "=r"(r1), "=r"(r2), "=r"(r3) : "r"(addr));
}

__device__ __forceinline__ float fexp(float x)
{
    x = fmaxf(x, -87.0f);
    const float L2E = 1.4426950408889634f;
    float t  = fmaf(x, L2E, 12582912.0f);
    int   ki = __float_as_int(t) - 0x4B400000;
    float kf = t - 12582912.0f;
    float r  = fmaf(x, L2E, -kf);
    float p  = 1.3333558146e-3f;
    p = fmaf(p, r, 9.6181291076e-3f);
    p = fmaf(p, r, 5.5504108664e-2f);
    p = fmaf(p, r, 2.4022650696e-1f);
    p = fmaf(p, r, 6.9314718056e-1f);
    p = fmaf(p, r, 1.0f);
    return p * __int_as_float((ki + 127) << 23);
}

__device__ __forceinline__ uint32_t packh2(float a, float b)
{
    __half2 h = __floats2half2_rn(a, b);
    return *(uint32_t*)&h;
}

__device__ __forceinline__ void cp16(uint32_t dst, const void* src)
{
    asm volatile("cp.async.ca.shared.global [%0], [%1], 16;\n"
                 :: "r"(dst), "l"(src));
}

// ---------------- fp16 pipelined 128x128 GEMM core (ldmatrix frags) ----------
#define HSTR 24
#define HBUF (128 * HSTR)

__device__ __forceinline__ void pipe16_mainloop(
    const __half* __restrict__ aptr,
    const __half* __restrict__ wptr,
    int K, __half* AsArr, __half* BsArr, float acc[4][4][4])
{
    int tid = threadIdx.x, lane = tid & 31, w = tid >> 5;
    int wm = w & 1, wn = w >> 1;
    int row = tid >> 1, seg = (tid & 1) * 8;

    uint32_t aBase = (uint32_t)__cvta_generic_to_shared(AsArr);
    uint32_t bBase = (uint32_t)__cvta_generic_to_shared(BsArr);
    uint32_t da = aBase + (row * HSTR + seg) * 2;
    uint32_t db = bBase + (row * HSTR + seg) * 2;
    const uint32_t BUFB = HBUF * 2;

    int l7 = lane & 7, lg1 = (lane >> 3) & 1, lg2 = (lane >> 4) & 1;
    uint32_t offA[4], offB[2];
    #pragma unroll
    for (int mt = 0; mt < 4; mt++) {
        int ar = wm * 64 + mt * 16 + l7 + lg1 * 8;
        offA[mt] = aBase + (ar * HSTR + lg2 * 8) * 2;
    }
    #pragma unroll
    for (int p = 0; p < 2; p++) {
        int br = wn * 32 + (2 * p + lg2) * 8 + l7;
        offB[p] = bBase + (br * HSTR + lg1 * 8) * 2;
    }

    int KT = K / 16;

    cp16(da, aptr);
    cp16(db, wptr);
    asm volatile("cp.async.commit_group;\n");

    for (int kt = 0; kt < KT; kt++) {
        if (kt + 1 < KT) {
            uint32_t off = ((kt + 1) & 1) * BUFB;
            cp16(da + off, aptr + (kt + 1) * 16);
            cp16(db + off, wptr + (kt + 1) * 16);
            asm volatile("cp.async.commit_group;\n");
            asm volatile("cp.async.wait_group 1;\n");
        } else {
            asm volatile("cp.async.wait_group 0;\n");
        }
        __syncthreads();

        uint32_t so = (kt & 1) * BUFB;

        uint32_t afr[4][4], bfr[4][2];
        #pragma unroll
        for (int mt = 0; mt < 4; mt++)
            ldm_x4(afr[mt][0], afr[mt][1], afr[mt][2], afr[mt][3], offA[mt] + so);
        ldm_x4(bfr[0][0], bfr[0][1], bfr[1][0], bfr[1][1], offB[0] + so);
        ldm_x4(bfr[2][0], bfr[2][1], bfr[3][0], bfr[3][1], offB[1] + so);

        #pragma unroll
        for (int mt = 0; mt < 4; mt++)
            #pragma unroll
            for (int nt = 0; nt < 4; nt++)
                mma_f16(acc[mt][nt], afr[mt][0], afr[mt][1], afr[mt][2], afr[mt][3],
                        bfr[nt][0], bfr[nt][1]);
        __syncthreads();
    }
}

// ---------------- fused weight conversion (fp32 -> fp16, one kernel) ---------
__global__ void f2h_all(const float* __restrict__ s0, const float* __restrict__ s1,
                        const float* __restrict__ s2, const float* __restrict__ s3)
{
    int i = blockIdx.x * 256 + threadIdx.x;   // quad index into g_wh
    if (i >= WH_TOTAL / 4) return;
    const float* src;
    int local;
    if (i < IPH_SZ / 4)                        { src = s0; local = i; }
    else if (i < (IPH_SZ + OPH_SZ) / 4)        { src = s1; local = i - IPH_SZ / 4; }
    else if (i < (IPH_SZ + OPH_SZ + W1H_SZ)/4) { src = s2; local = i - (IPH_SZ + OPH_SZ) / 4; }
    else                                       { src = s3; local = i - (IPH_SZ + OPH_SZ + W1H_SZ) / 4; }
    float4 v = ((const float4*)src)[local];
    ((__half2*)g_wh)[2 * i + 0] = __floats2half2_rn(v.x, v.y);
    ((__half2*)g_wh)[2 * i + 1] = __floats2half2_rn(v.z, v.w);
}

// ---------------- positional encoding (cheap FP64) ---------------------------
__global__ void pe_kernel()
{
    int d = blockIdx.x, s = threadIdx.x;
    __shared__ double freq_sh;
    if (threadIdx.x == 0)
        freq_sh = exp(-(double)(d & ~1) * (log(10000.0) / (double)DD));
    __syncthreads();
    double arg = (double)s * freq_sh;
    const double TWOPI = 6.283185307179586476925286766559;
    double r = arg - TWOPI * rint(arg * (1.0 / TWOPI));
    float rf = (float)r;
    g_pe[s * DD + d] = (d & 1) ? cosf(rf) : sinf(rf);
}

__global__ void zero_cnt_all()
{
    if (threadIdx.x < NLAY * NEXP) g_cnt[threadIdx.x] = 0;
}

// ---------------- embedding + pad mask ---------------------------------------
__global__ void embed_kernel(const int* __restrict__ x, const float* __restrict__ emb)
{
    int n = blockIdx.x;
    int d = threadIdx.x;
    int tok = x[n];
    int s = n & (SS - 1);

    float v = emb[(size_t)tok * DD + d] * 16.0f + g_pe[s * DD + d];
    g_h [(size_t)n * DD + d] = v;
    g_hh[(size_t)n * DD + d] = __float2half(v);

    float sum = v;
    #pragma unroll
    for (int o = 16; o > 0; o >>= 1) sum += __shfl_xor_sync(0xffffffffu, sum, o);
    __shared__ float ws[8];
    if ((d & 31) == 0) ws[d >> 5] = sum;
    __syncthreads();
    if (d == 0) {
        float t = 0.f;
        #pragma unroll
        for (int i = 0; i < 8; i++) t += ws[i];
        g_pad[n] = (t == 0.0f) ? 1 : 0;
    }
}

// ---------------- QKV GEMM (fp16) + fp16 split store -------------------------
__global__ __launch_bounds__(256)
void gemm_qkv16(const __half* __restrict__ A,
                const __half* __restrict__ W,
                const float* __restrict__ bias)
{
    __shared__ __align__(16) __half As[2 * HBUF];
    __shared__ __align__(16) __half Bs[2 * HBUF];

    int tid = threadIdx.x, lane = tid & 31, w = tid >> 5;
    int wm = w & 1, wn = w >> 1, g = lane >> 2, T = lane & 3;
    int m0 = blockIdx.y * 128, n0 = blockIdx.x * 128;
    int row = tid >> 1, seg = (tid & 1) * 8;

    const float inv = 0.17677669529663689f;

    float acc[4][4][4] = {};
    pipe16_mainloop(A + (size_t)(m0 + row) * DD + seg,
                    W + (size_t)(n0 + row) * DD + seg, DD, As, Bs, acc);

    #pragma unroll
    for (int mt = 0; mt < 4; mt++) {
        #pragma unroll
        for (int nt = 0; nt < 4; nt++) {
            int r0 = m0 + wm * 64 + mt * 16 + g;
            int c0 = n0 + wn * 32 + nt * 8 + 2 * T;
            int t = c0 >> 8, h = (c0 >> 5) & 7, d = c0 & 31;
            float bx = bias[c0], by = bias[c0 + 1];
            #pragma unroll
            for (int half = 0; half < 2; half++) {
                int rr = r0 + half * 8;
                int b = rr >> 9, s = rr & (SS - 1);
                int bh = b * HH + h;
                float v0 = acc[mt][nt][half * 2 + 0] + bx;
                float v1 = acc[mt][nt][half * 2 + 1] + by;
                if (t == 0) {
                    *(uint32_t*)(g_qh + ((size_t)(bh * SS + s)) * DHD + d) =
                        packh2(v0 * inv, v1 * inv);
                } else if (t == 1) {
                    *(uint32_t*)(g_kh + ((size_t)(bh * SS + s)) * DHD + d) =
                        packh2(v0, v1);
                } else {
                    g_vth[((size_t)(bh * DHD + d    )) * SS + s] = __float2half(v0);
                    g_vth[((size_t)(bh * DHD + d + 1)) * SS + s] = __float2half(v1);
                }
            }
        }
    }
}

// ---------------- out-proj GEMM (fp16) ---------------------------------------
__global__ __launch_bounds__(256)
void gemm_out16(const __half* __restrict__ A,
                const __half* __restrict__ W,
                const float* __restrict__ bias,
                float* __restrict__ C, int Nc, int K)
{
    __shared__ __align__(16) __half As[2 * HBUF];
    __shared__ __align__(16) __half Bs[2 * HBUF];

    int tid = threadIdx.x, lane = tid & 31, w = tid >> 5;
    int wm = w & 1, wn = w >> 1, g = lane >> 2, T = lane & 3;
    int m0 = blockIdx.y * 128, n0 = blockIdx.x * 128;
    int row = tid >> 1, seg = (tid & 1) * 8;

    float acc[4][4][4] = {};
    pipe16_mainloop(A + (size_t)(m0 + row) * K + seg,
                    W + (size_t)(n0 + row) * K + seg, K, As, Bs, acc);

    #pragma unroll
    for (int mt = 0; mt < 4; mt++) {
        #pragma unroll
        for (int nt = 0; nt < 4; nt++) {
            int r0 = m0 + wm * 64 + mt * 16 + g;
            int c0 = n0 + wn * 32 + nt * 8 + 2 * T;
            float bx = bias[c0], by = bias[c0 + 1];
            #pragma unroll
            for (int half = 0; half < 2; half++) {
                int rr = r0 + half * 8;
                float2 v = make_float2(acc[mt][nt][half * 2 + 0] + bx,
                                       acc[mt][nt][half * 2 + 1] + by);
                *(float2*)(C + (size_t)rr * Nc + c0) = v;
            }
        }
    }
}

// ---------------- MoE GEMM1 (fp16, work-queue grid) --------------------------
__global__ __launch_bounds__(256)
void moe_gemm1_16(const __half* __restrict__ w1, const float* __restrict__ b1,
                  const int* __restrict__ cnt_l)
{
    int y = blockIdx.y;
    if (y >= g_ntiles) return;
    int ent = g_tiletab[y];
    int e = ent >> 16, tile = ent & 0xFFFF;
    int cnt = cnt_l[e];
    int ebase = g_base[e];

    __shared__ __align__(16) __half As[2 * HBUF];
    __shared__ __align__(16) __half Bs[2 * HBUF];

    int tid = threadIdx.x, lane = tid & 31, w = tid >> 5;
    int wm = w & 1, wn = w >> 1, g = lane >> 2, T = lane & 3;
    int n0 = blockIdx.x * 128;
    int row = tid >> 1, seg = (tid & 1) * 8;

    int gr = tile * 128 + row;
    if (gr >= cnt) gr = cnt - 1;
    int token = g_perm[ebase + gr];

    float acc[4][4][4] = {};
    pipe16_mainloop(g_hh + (size_t)token * DD + seg,
                    w1 + (size_t)e * EHID * DD + (size_t)(n0 + row) * DD + seg,
                    DD, As, Bs, acc);

    #pragma unroll
    for (int mt = 0; mt < 4; mt++) {
        #pragma unroll
        for (int nt = 0; nt < 4; nt++) {
            int lr0 = wm * 64 + mt * 16 + g;
            int c0  = n0 + wn * 32 + nt * 8 + 2 * T;
            float bx = b1[e * EHID + c0], by = b1[e * EHID + c0 + 1];
            #pragma unroll
            for (int half = 0; half < 2; half++) {
                int grr = tile * 128 + lr0 + half * 8;
                if (grr < cnt) {
                    float v0 = fmaxf(acc[mt][nt][half * 2 + 0] + bx, 0.f);
                    float v1 = fmaxf(acc[mt][nt][half * 2 + 1] + by, 0.f);
                    *(uint32_t*)(g_h1h + (size_t)(ebase + grr) * EHID + c0) = packh2(v0, v1);
                }
            }
        }
    }
}

// ---------------- MoE GEMM2 (fp16, work-queue grid) --------------------------
__global__ __launch_bounds__(256)
void moe_gemm2_16(const __half* __restrict__ w2, const float* __restrict__ b2,
                  const int* __restrict__ cnt_l)
{
    int y = blockIdx.y;
    if (y >= g_ntiles) return;
    int ent = g_tiletab[y];
    int e = ent >> 16, tile = ent & 0xFFFF;
    int cnt = cnt_l[e];
    int ebase = g_base[e];

    __shared__ __align__(16) __half As[2 * HBUF];
    __shared__ __align__(16) __half Bs[2 * HBUF];

    int tid = threadIdx.x, lane = tid & 31, w = tid >> 5;
    int wm = w & 1, wn = w >> 1, g = lane >> 2, T = lane & 3;
    int n0 = blockIdx.x * 128;
    int row = tid >> 1, seg = (tid & 1) * 8;

    int gr = tile * 128 + row;
    if (gr >= cnt) gr = cnt - 1;

    float acc[4][4][4] = {};
    pipe16_mainloop(g_h1h + (size_t)(ebase + gr) * EHID + seg,
                    w2 + (size_t)e * DD * EHID + (size_t)(n0 + row) * EHID + seg,
                    EHID, As, Bs, acc);

    #pragma unroll
    for (int mt = 0; mt < 4; mt++) {
        #pragma unroll
        for (int nt = 0; nt < 4; nt++) {
            int lr0 = wm * 64 + mt * 16 + g;
            int c0  = n0 + wn * 32 + nt * 8 + 2 * T;
            float bx = b2[e * DD + c0], by = b2[e * DD + c0 + 1];
            #pragma unroll
            for (int half = 0; half < 2; half++) {
                int grr = tile * 128 + lr0 + half * 8;
                if (grr < cnt) {
                    int token = g_perm[ebase + grr];
                    float gwv = g_ew[token];
                    float2 v = make_float2(gwv * (acc[mt][nt][half * 2 + 0] + bx),
                                           gwv * (acc[mt][nt][half * 2 + 1] + by));
                    *(float2*)(g_tmp + (size_t)token * DD + c0) = v;
                }
            }
        }
    }
}

// ---------------- flash attention (fp16, cp.async double-buffered K/V) -------
#define QTILE 128
#define KCH   64
#define QH    40
#define VSTR  72

__global__ void attn_fa_kernel()
{
    __shared__ __align__(16) __half Qs [QTILE * QH];
    __shared__ __align__(16) __half Ks [2][KCH * QH];
    __shared__ __align__(16) __half Vts[2][DHD * VSTR];
    __shared__ __align__(16) int    mk [2][KCH];

    int qt = blockIdx.x, h = blockIdx.y, b = blockIdx.z;
    int tid = threadIdx.x, lane = tid & 31, w = tid >> 5;
    int g = lane >> 2, T = lane & 3;
    int bh = b * HH + h;

    const __half* Qgh = g_qh  + ((size_t)(bh * SS + qt * QTILE)) * DHD;
    const __half* Kgh = g_kh  + ((size_t)(bh * SS)) * DHD;
    const __half* Vgh = g_vth + ((size_t)bh * DHD) * SS;
    const int*    Pg  = g_pad + b * SS;

    // per-thread cp.async source/dest geometry
    int krow = tid >> 2, kcol = (tid & 3) * 8;            // K: 64x32 halves
    int vd   = tid >> 3, vcol = (tid & 7) * 8;            // V: 32x64 halves
    uint32_t ksd[2], vsd[2];
    #pragma unroll
    for (int p = 0; p < 2; p++) {
        ksd[p] = (uint32_t)__cvta_generic_to_shared(&Ks[p][krow * QH + kcol]);
        vsd[p] = (uint32_t)__cvta_generic_to_shared(&Vts[p][vd * VSTR + vcol]);
    }

    // load Q tile (regular loads)
    for (int i = tid; i < 512; i += 256) {
        int row = i >> 2, c = (i & 3) * 8;
        *(uint4*)(Qs + row * QH + c) = *(const uint4*)(Qgh + row * DHD + c);
    }

    // prefetch chunk 0
    {
        cp16(ksd[0], Kgh + (size_t)krow * DHD + kcol);
        cp16(vsd[0], Vgh + (size_t)vd * SS + vcol);
        if (tid < 16)
            cp16((uint32_t)__cvta_generic_to_shared(&mk[0][tid * 4]), Pg + tid * 4);
        asm volatile("cp.async.commit_group;\n");
    }

    float m_[2]  = {-1e30f, -1e30f};
    float sum_[2] = {0.f, 0.f};
    float o[4][4] = {};

    for (int kc = 0; kc < SS / KCH; kc++) {
        int buf = kc & 1;
        if (kc + 1 < SS / KCH) {
            int nb = (kc + 1) & 1;
            cp16(ksd[nb], Kgh + (size_t)((kc + 1) * KCH + krow) * DHD + kcol);
            cp16(vsd[nb], Vgh + (size_t)vd * SS + (kc + 1) * KCH + vcol);
            if (tid < 16)
                cp16((uint32_t)__cvta_generic_to_shared(&mk[nb][tid * 4]),
                     Pg + (kc + 1) * KCH + tid * 4);
            asm volatile("cp.async.commit_group;\n");
            asm volatile("cp.async.wait_group 1;\n");
        } else {
            asm volatile("cp.async.wait_group 0;\n");
        }
        __syncthreads();

        float s[8][4];
        #pragma unroll
        for (int nt = 0; nt < 8; nt++)
            #pragma unroll
            for (int j = 0; j < 4; j++) s[nt][j] = 0.f;

        #pragma unroll
        for (int ks = 0; ks < 2; ks++) {
            int row = w * 16 + g, col = ks * 16 + 2 * T;
            uint32_t a0 = *(const uint32_t*)(Qs + row * QH + col);
            uint32_t a1 = *(const uint32_t*)(Qs + (row + 8) * QH + col);
            uint32_t a2 = *(const uint32_t*)(Qs + row * QH + col + 8);
            uint32_t a3 = *(const uint32_t*)(Qs + (row + 8) * QH + col + 8);
            #pragma unroll
            for (int nt = 0; nt < 8; nt++) {
                int kr = nt * 8 + g;
                uint32_t b0 = *(const uint32_t*)(&Ks[buf][kr * QH + col]);
                uint32_t b1 = *(const uint32_t*)(&Ks[buf][kr * QH + col + 8]);
                mma_f16(s[nt], a0, a1, a2, a3, b0, b1);
            }
        }

        #pragma unroll
        for (int nt = 0; nt < 8; nt++) {
            if (mk[buf][nt * 8 + 2 * T])     { s[nt][0] = -1e9f; s[nt][2] = -1e9f; }
            if (mk[buf][nt * 8 + 2 * T + 1]) { s[nt][1] = -1e9f; s[nt][3] = -1e9f; }
        }

        #pragma unroll
        for (int half = 0; half < 2; half++) {
            float cmax = -1e30f;
            #pragma unroll
            for (int nt = 0; nt < 8; nt++)
                cmax = fmaxf(cmax, fmaxf(s[nt][2 * half], s[nt][2 * half + 1]));
            cmax = fmaxf(cmax, __shfl_xor_sync(0xffffffffu, cmax, 1));
            cmax = fmaxf(cmax, __shfl_xor_sync(0xffffffffu, cmax, 2));
            float mnew  = fmaxf(m_[half], cmax);
            float scale = fexp(m_[half] - mnew);
            m_[half] = mnew;
            float part = 0.f;
            #pragma unroll
            for (int nt = 0; nt < 8; nt++) {
                float p0 = fexp(s[nt][2 * half]     - mnew);
                float p1 = fexp(s[nt][2 * half + 1] - mnew);
                s[nt][2 * half] = p0; s[nt][2 * half + 1] = p1;
                part += p0 + p1;
            }
            part += __shfl_xor_sync(0xffffffffu, part, 1);
            part += __shfl_xor_sync(0xffffffffu, part, 2);
            sum_[half] = sum_[half] * scale + part;
            #pragma unroll
            for (int nt = 0; nt < 4; nt++) {
                o[nt][2 * half]     *= scale;
                o[nt][2 * half + 1] *= scale;
            }
        }

        #pragma unroll
        for (int kt = 0; kt < 4; kt++) {
            uint32_t a0 = packh2(s[2 * kt][0],     s[2 * kt][1]);
            uint32_t a1 = packh2(s[2 * kt][2],     s[2 * kt][3]);
            uint32_t a2 = packh2(s[2 * kt + 1][0], s[2 * kt + 1][1]);
            uint32_t a3 = packh2(s[2 * kt + 1][2], s[2 * kt + 1][3]);
            #pragma unroll
            for (int nt = 0; nt < 4; nt++) {
                const __half* vp = &Vts[buf][(nt * 8 + g) * VSTR + kt * 16 + 2 * T];
                uint32_t b0 = *(const uint32_t*)vp;
                uint32_t b1 = *(const uint32_t*)(vp + 8);
                mma_f16(o[nt], a0, a1, a2, a3, b0, b1);
            }
        }
        __syncthreads();   // protect this buffer before next prefetch overwrites it
    }

    float i0 = 1.0f / sum_[0];
    float i1 = 1.0f / sum_[1];
    int q0 = qt * QTILE + w * 16 + g;
    #pragma unroll
    for (int nt = 0; nt < 4; nt++) {
        int col = h * DHD + nt * 8 + 2 * T;
        *(uint32_t*)(g_ctxh + (size_t)(b * SS + q0) * DD + col) =
            packh2(o[nt][0] * i0, o[nt][1] * i0);
        *(uint32_t*)(g_ctxh + (size_t)(b * SS + q0 + 8) * DD + col) =
            packh2(o[nt][2] * i1, o[nt][3] * i1);
    }
}

// ---------------- fused residual + LN (+optional gate) -----------------------
__device__ __forceinline__ void warp_add_ln(
    int n, int lane, const float* __restrict__ add,
    const float* __restrict__ gamma, const float* __restrict__ beta,
    float out[8])
{
    size_t base = (size_t)n * DD + lane;
    float v[8];
    float sum = 0.f;
    #pragma unroll
    for (int j = 0; j < 8; j++) {
        v[j] = g_h[base + 32 * j] + add[base + 32 * j];
        sum += v[j];
    }
    #pragma unroll
    for (int o = 16; o > 0; o >>= 1) sum += __shfl_xor_sync(0xffffffffu, sum, o);
    float mu = sum * (1.0f / DD);
    float sq = 0.f;
    #pragma unroll
    for (int j = 0; j < 8; j++) {
        v[j] -= mu;
        sq += v[j] * v[j];
    }
    #pragma unroll
    for (int o = 16; o > 0; o >>= 1) sq += __shfl_xor_sync(0xffffffffu, sq, o);
    float r = rsqrtf(sq * (1.0f / DD) + 1e-5f);
    #pragma unroll
    for (int j = 0; j < 8; j++) {
        out[j] = v[j] * r * gamma[lane + 32 * j] + beta[lane + 32 * j];
        g_h [base + 32 * j] = out[j];
        g_hh[base + 32 * j] = __float2half(out[j]);
    }
}

__global__ void add_ln2_kernel(const float* __restrict__ add,
                               const float* __restrict__ gamma,
                               const float* __restrict__ beta)
{
    int lane = threadIdx.x & 31;
    int n = blockIdx.x * 8 + (threadIdx.x >> 5);
    float out[8];
    warp_add_ln(n, lane, add, gamma, beta, out);
}

__global__ void add_ln1_gate_kernel(const float* __restrict__ add,
                                    const float* __restrict__ gamma,
                                    const float* __restrict__ beta,
                                    const float* __restrict__ gw,
                                    const float* __restrict__ gb,
                                    int* __restrict__ cnt_l)
{
    int lane = threadIdx.x & 31;
    int n = blockIdx.x * 8 + (threadIdx.x >> 5);
    float out[8];
    warp_add_ln(n, lane, add, gamma, beta, out);

    float lg[NEXP];
    #pragma unroll
    for (int e = 0; e < NEXP; e++) {
        float p = 0.f;
        #pragma unroll
        for (int j = 0; j < 8; j++)
            p = fmaf(gw[e * DD + lane + 32 * j], out[j], p);
        #pragma unroll
        for (int o = 16; o > 0; o >>= 1)
            p += __shfl_xor_sync(0xffffffffu, p, o);
        lg[e] = p;
    }
    if (lane == 0) {
        float m = -1e30f;
        #pragma unroll
        for (int i = 0; i < NEXP; i++) { lg[i] += gb[i]; m = fmaxf(m, lg[i]); }
        float p[NEXP], sum = 0.f;
        #pragma unroll
        for (int i = 0; i < NEXP; i++) { p[i] = expf(lg[i] - m); sum += p[i]; }
        int bi = 0; float bw = p[0];
        #pragma unroll
        for (int i = 1; i < NEXP; i++) if (p[i] > bw) { bw = p[i]; bi = i; }
        g_eidx[n] = bi;
        g_ew[n]   = bw / sum;
        atomicAdd(&cnt_l[bi], 1);
    }
}

// ---------------- routing bookkeeping (prefix + tile table) ------------------
__global__ void prefix_kernel(const int* __restrict__ cnt_l)
{
    if (threadIdx.x == 0) {
        int acc = 0, idx = 0;
        #pragma unroll
        for (int e = 0; e < NEXP; e++) {
            g_base[e] = acc; g_cursor[e] = acc;
            int c = cnt_l[e];
            acc += c;
            int nt = (c + 127) >> 7;
            for (int t = 0; t < nt; t++) g_tiletab[idx++] = (e << 16) | t;
        }
        g_ntiles = idx;
    }
}

__global__ void scatter_kernel()
{
    int n = blockIdx.x * blockDim.x + threadIdx.x;
    if (n < NTOK) {
        int e = g_eidx[n];
        int pos = atomicAdd(&g_cursor[e], 1);
        g_perm[pos] = n;
    }
}

// ---------------- head: partial pooling + final ------------------------------
__global__ void pool_kernel()
{
    int b = blockIdx.x, c = blockIdx.y;
    int tid = threadIdx.x;
    int base = b * SS + c * 64;
    float s = 0.f;
    #pragma unroll 8
    for (int i = 0; i < 64; i++) {
        int n = base + i;
        if (!g_pad[n]) s += g_h[(size_t)n * DD + tid];
    }
    g_pool[(b * 8 + c) * DD + tid] = s;
    if (tid == 0) {
        int t = 0;
        #pragma unroll 8
        for (int i = 0; i < 64; i++) t += (g_pad[base + i] == 0);
        g_pcnt[b * 8 + c] = t;
    }
}

__global__ void head_final(const float* __restrict__ fc1w, const float* __restrict__ fc1b,
                           const float* __restrict__ fc2w, const float* __restrict__ fc2b,
                           float* __restrict__ out)
{
    int b = blockIdx.x, tid = threadIdx.x;
    __shared__ float pooled[DD];
    __shared__ float z[128];
    __shared__ int scnt;

    float s = 0.f;
    #pragma unroll
    for (int c = 0; c < 8; c++) s += g_pool[(b * 8 + c) * DD + tid];
    if (tid == 0) {
        int t = 0;
        #pragma unroll
        for (int c = 0; c < 8; c++) t += g_pcnt[b * 8 + c];
        scnt = t;
    }
    __syncthreads();
    pooled[tid] = s / fmaxf((float)scnt, 1.0f);
    __syncthreads();

    if (tid < 128) {
        float a = fc1b[tid];
        const float* wr = fc1w + (size_t)tid * DD;
        #pragma unroll 8
        for (int d = 0; d < DD; d++) a += pooled[d] * wr[d];
        z[tid] = fmaxf(a, 0.f);
    }
    __syncthreads();
    if (tid < 2) {
        float a = fc2b[tid];
        const float* wr = fc2w + (size_t)tid * 128;
        #pragma unroll 8
        for (int i = 0; i < 128; i++) a += z[i] * wr[i];
        out[b * 2 + tid] = a;
    }
}

// ---------------- host launch ------------------------------------------------
static void* sym_addr(const void* sym)
{
    void* p = nullptr;
    cudaGetSymbolAddress(&p, sym);
    return p;
}

extern "C" void kernel_launch(void* const* d_in, const int* in_sizes, int n_in,
                              void* d_out, int out_size)
{
    const int*   x          = (const int*)  d_in[0];
    const float* emb        = (const float*)d_in[1];
    const float* in_proj_w  = (const float*)d_in[2];
    const float* in_proj_b  = (const float*)d_in[3];
    const float* out_proj_w = (const float*)d_in[4];
    const float* out_proj_b = (const float*)d_in[5];
    const float* ln1_g      = (const float*)d_in[6];
    const float* ln1_b      = (const float*)d_in[7];
    const float* ln2_g      = (const float*)d_in[8];
    const float* ln2_b      = (const float*)d_in[9];
    const float* gate_w     = (const float*)d_in[10];
    const float* gate_b     = (const float*)d_in[11];
    const float* w1         = (const float*)d_in[12];
    const float* b1         = (const float*)d_in[13];
    const float* w2         = (const float*)d_in[14];
    const float* b2         = (const float*)d_in[15];
    const float* fc1_w      = (const float*)d_in[16];
    const float* fc1_b      = (const float*)d_in[17];
    const float* fc2_w      = (const float*)d_in[18];
    const float* fc2_b      = (const float*)d_in[19];
    float* out = (float*)d_out;

    __half* wh    = (__half*)sym_addr(g_wh);
    __half* hh    = (__half*)sym_addr(g_hh);
    __half* ctxh  = (__half*)sym_addr(g_ctxh);
    float*  p_tmp = (float*)sym_addr(g_tmp);
    int*    cnt   = (int*)sym_addr(g_cnt);

    pe_kernel<<<DD, SS>>>();
    zero_cnt_all<<<1, 32>>>();
    embed_kernel<<<NTOK, DD>>>(x, emb);
    f2h_all<<<(WH_TOTAL/4 + 255)/256, 256>>>(in_proj_w, out_proj_w, w1, w2);

    for (int l = 0; l < NLAY; l++) {
        int* cnt_l = cnt + l * NEXP;

        gemm_qkv16<<<dim3(3*DD/128, NTOK/128), 256>>>(
            hh, wh + IPH_OFF + (size_t)l * 3*DD*DD, in_proj_b + (size_t)l * 3*DD);

        attn_fa_kernel<<<dim3(SS/QTILE, HH, BB), 256>>>();

        gemm_out16<<<dim3(DD/128, NTOK/128), 256>>>(
            ctxh, wh + OPH_OFF + (size_t)l * DD*DD, out_proj_b + (size_t)l * DD,
            p_tmp, DD, DD);

        add_ln1_gate_kernel<<<NTOK/8, 256>>>(
            p_tmp, ln1_g + (size_t)l * DD, ln1_b + (size_t)l * DD,
            gate_w + (size_t)l * NEXP*DD, gate_b + (size_t)l * NEXP, cnt_l);
        prefix_kernel<<<1, 32>>>(cnt_l);
        scatter_kernel<<<NTOK/256, 256>>>();

        moe_gemm1_16<<<dim3(EHID/128, 71), 256>>>(
            wh + W1H_OFF + (size_t)l * NEXP*EHID*DD, b1 + (size_t)l * NEXP*EHID, cnt_l);
        moe_gemm2_16<<<dim3(DD/128, 71), 256>>>(
            wh + W2H_OFF + (size_t)l * NEXP*DD*EHID, b2 + (size_t)l * NEXP*DD, cnt_l);

        add_ln2_kernel<<<NTOK/8, 256>>>(
            p_tmp, ln2_g + (size_t)l * DD, ln2_b + (size_t)l * DD);
    }

    pool_kernel<<<dim3(BB, 8), 256>>>();
    head_final<<<BB, 256>>>(fc1_w, fc1_b, fc2_w, fc2_b, out);
}

// round 12
// speedup vs baseline: 46.6034x; 1.0694x over previous
#include <cuda_runtime.h>
#include <cuda_fp16.h>
#include <math.h>
#include <stdint.h>

// ---------------- model dims ----------------
#define BB    16
#define SS    512
#define DD    256
#define HH    8
#define DHD   32
#define NLAY  2
#define NEXP  8
#define EHID  1024
#define NTOK  (BB*SS)   // 8192

// ---------------- scratch (static device globals) ---------------------------
__device__ float  g_h   [NTOK*DD];
__device__ __half g_hh  [NTOK*DD];
__device__ __half g_qh  [NTOK*DD];     // Q fp16, pre-scaled, [B][H][S][32]
__device__ __half g_kh  [NTOK*DD];     // K fp16, [B][H][S][32]
__device__ __half g_vth [NTOK*DD];     // V fp16 transposed, [B][H][32][S]
__device__ __half g_ctxh[NTOK*DD];
__device__ float  g_tmp [NTOK*DD];
__device__ __half g_h1h [NTOK*EHID];   // MoE hidden (fp16, permuted rows)
__device__ float  g_pe  [SS*DD];
__device__ int    g_pad [NTOK];
__device__ int    g_eidx[NTOK];
__device__ float  g_ew  [NTOK];
__device__ int    g_cnt [NLAY*NEXP];
__device__ int    g_base[NEXP];
__device__ int    g_cursor[NEXP];
__device__ int    g_perm[NTOK];
__device__ float  g_pool[BB*8*DD];
__device__ int    g_pcnt[BB*8];
__device__ int    g_tiletab[80];
__device__ int    g_ntiles;

// fp16 weight buffer (converted once per launch)
#define IPH_OFF 0
#define IPH_SZ  (NLAY*3*DD*DD)
#define OPH_OFF (IPH_OFF + IPH_SZ)
#define OPH_SZ  (NLAY*DD*DD)
#define W1H_OFF (OPH_OFF + OPH_SZ)
#define W1H_SZ  (NLAY*NEXP*EHID*DD)
#define W2H_OFF (W1H_OFF + W1H_SZ)
#define W2H_SZ  (NLAY*NEXP*DD*EHID)
#define WH_TOTAL (W2H_OFF + W2H_SZ)
__device__ __half g_wh[WH_TOTAL];

// ---------------- helpers ----------------------------------------------------
__device__ __forceinline__ void mma_f16(float* d, uint32_t a0, uint32_t a1,
                                        uint32_t a2, uint32_t a3,
                                        uint32_t b0, uint32_t b1)
{
    asm volatile(
        "mma.sync.aligned.m16n8k16.row.col.f32.f16.f16.f32 "
        "{%0,%1,%2,%3}, {%4,%5,%6,%7}, {%8,%9}, {%0,%1,%2,%3};\n"
        : "+f"(d[0]), "+f"(d[1]), "+f"(d[2]), "+f"(d[3])
        : "r"(a0), "r"(a1), "r"(a2), "r"(a3), "r"(b0), "r"(b1));
}

__device__ __forceinline__ void ldm_x4(uint32_t& r0, uint32_t& r1,
                                       uint32_t& r2, uint32_t& r3, uint32_t addr)
{
    asm volatile("ldmatrix.sync.aligned.m8n8.x4.shared.b16 {%0,%1,%2,%3}, [%4];"
                 : "=r"(r0), "=r"(r1), "=r"(r2), "=r"(r3) : "r"(addr));
}

__device__ __forceinline__ float fexp(float x)
{
    x = fmaxf(x, -87.0f);
    const float L2E = 1.4426950408889634f;
    float t  = fmaf(x, L2E, 12582912.0f);
    int   ki = __float_as_int(t) - 0x4B400000;
    float kf = t - 12582912.0f;
    float r  = fmaf(x, L2E, -kf);
    float p  = 1.3333558146e-3f;
    p = fmaf(p, r, 9.6181291076e-3f);
    p = fmaf(p, r, 5.5504108664e-2f);
    p = fmaf(p, r, 2.4022650696e-1f);
    p = fmaf(p, r, 6.9314718056e-1f);
    p = fmaf(p, r, 1.0f);
    return p * __int_as_float((ki + 127) << 23);
}

__device__ __forceinline__ uint32_t packh2(float a, float b)
{
    __half2 h = __floats2half2_rn(a, b);
    return *(uint32_t*)&h;
}

__device__ __forceinline__ void cp16(uint32_t dst, const void* src)
{
    asm volatile("cp.async.ca.shared.global [%0], [%1], 16;\n"
                 :: "r"(dst), "l"(src));
}

// ---------------- fp16 pipelined 128x128 GEMM core, BK=32 --------------------
// stride 40 halves (80B): ldmatrix rows hit distinct 16B banks (80r mod 128
// cycles over {0,80,32,112,64,16,96,48}).
#define H2STR 40
#define H2BUF (128 * H2STR)   // halves per stage buffer

__device__ __forceinline__ void pipe16_mainloop(
    const __half* __restrict__ aptr,   // pre-offset by this thread's seg
    const __half* __restrict__ wptr,
    int K, __half* AsArr, __half* BsArr, float acc[4][4][4])
{
    int tid = threadIdx.x, lane = tid & 31, w = tid >> 5;
    int wm = w & 1, wn = w >> 1;
    int row = tid >> 1, seg = (tid & 1) * 16;

    uint32_t aBase = (uint32_t)__cvta_generic_to_shared(AsArr);
    uint32_t bBase = (uint32_t)__cvta_generic_to_shared(BsArr);
    uint32_t da = aBase + (row * H2STR + seg) * 2;
    uint32_t db = bBase + (row * H2STR + seg) * 2;
    const uint32_t BUFB = H2BUF * 2;   // bytes per stage

    int l7 = lane & 7, lg1 = (lane >> 3) & 1, lg2 = (lane >> 4) & 1;
    uint32_t offA[4], offB[2];
    #pragma unroll
    for (int mt = 0; mt < 4; mt++) {
        int ar = wm * 64 + mt * 16 + l7 + lg1 * 8;
        offA[mt] = aBase + (ar * H2STR + lg2 * 8) * 2;
    }
    #pragma unroll
    for (int p = 0; p < 2; p++) {
        int br = wn * 32 + (2 * p + lg2) * 8 + l7;
        offB[p] = bBase + (br * H2STR + lg1 * 8) * 2;
    }

    int KT = K / 32;

    cp16(da,      aptr);     cp16(da + 16, aptr + 8);
    cp16(db,      wptr);     cp16(db + 16, wptr + 8);
    asm volatile("cp.async.commit_group;\n");

    for (int kt = 0; kt < KT; kt++) {
        if (kt + 1 < KT) {
            uint32_t off = ((kt + 1) & 1) * BUFB;
            const float* dummy;
            const __half* as = aptr + (kt + 1) * 32;
            const __half* ws = wptr + (kt + 1) * 32;
            (void)dummy;
            cp16(da + off,      as);     cp16(da + off + 16, as + 8);
            cp16(db + off,      ws);     cp16(db + off + 16, ws + 8);
            asm volatile("cp.async.commit_group;\n");
            asm volatile("cp.async.wait_group 1;\n");
        } else {
            asm volatile("cp.async.wait_group 0;\n");
        }
        __syncthreads();

        uint32_t so = (kt & 1) * BUFB;

        #pragma unroll
        for (int kh = 0; kh < 2; kh++) {
            uint32_t ko = so + kh * 32;   // 16 halves = 32 bytes
            uint32_t afr[4][4], bfr[4][2];
            #pragma unroll
            for (int mt = 0; mt < 4; mt++)
                ldm_x4(afr[mt][0], afr[mt][1], afr[mt][2], afr[mt][3], offA[mt] + ko);
            ldm_x4(bfr[0][0], bfr[0][1], bfr[1][0], bfr[1][1], offB[0] + ko);
            ldm_x4(bfr[2][0], bfr[2][1], bfr[3][0], bfr[3][1], offB[1] + ko);

            #pragma unroll
            for (int mt = 0; mt < 4; mt++)
                #pragma unroll
                for (int nt = 0; nt < 4; nt++)
                    mma_f16(acc[mt][nt], afr[mt][0], afr[mt][1], afr[mt][2], afr[mt][3],
                            bfr[nt][0], bfr[nt][1]);
        }
        __syncthreads();
    }
}

// ---------------- fused weight conversion (fp32 -> fp16, one kernel) ---------
__global__ void f2h_all(const float* __restrict__ s0, const float* __restrict__ s1,
                        const float* __restrict__ s2, const float* __restrict__ s3)
{
    int i = blockIdx.x * 256 + threadIdx.x;
    if (i >= WH_TOTAL / 4) return;
    const float* src;
    int local;
    if (i < IPH_SZ / 4)                        { src = s0; local = i; }
    else if (i < (IPH_SZ + OPH_SZ) / 4)        { src = s1; local = i - IPH_SZ / 4; }
    else if (i < (IPH_SZ + OPH_SZ + W1H_SZ)/4) { src = s2; local = i - (IPH_SZ + OPH_SZ) / 4; }
    else                                       { src = s3; local = i - (IPH_SZ + OPH_SZ + W1H_SZ) / 4; }
    float4 v = ((const float4*)src)[local];
    ((__half2*)g_wh)[2 * i + 0] = __floats2half2_rn(v.x, v.y);
    ((__half2*)g_wh)[2 * i + 1] = __floats2half2_rn(v.z, v.w);
}

// ---------------- positional encoding (cheap FP64) ---------------------------
__global__ void pe_kernel()
{
    int d = blockIdx.x, s = threadIdx.x;
    __shared__ double freq_sh;
    if (threadIdx.x == 0)
        freq_sh = exp(-(double)(d & ~1) * (log(10000.0) / (double)DD));
    __syncthreads();
    double arg = (double)s * freq_sh;
    const double TWOPI = 6.283185307179586476925286766559;
    double r = arg - TWOPI * rint(arg * (1.0 / TWOPI));
    float rf = (float)r;
    g_pe[s * DD + d] = (d & 1) ? cosf(rf) : sinf(rf);
}

__global__ void zero_cnt_all()
{
    if (threadIdx.x < NLAY * NEXP) g_cnt[threadIdx.x] = 0;
}

// ---------------- embedding + pad mask (warp per token) ----------------------
__global__ void embed_kernel(const int* __restrict__ x, const float* __restrict__ emb)
{
    int lane = threadIdx.x & 31;
    int n = blockIdx.x * 8 + (threadIdx.x >> 5);
    int tok = x[n];
    int s = n & (SS - 1);

    const float* er = emb + (size_t)tok * DD;
    const float* pr = g_pe + s * DD;
    size_t base = (size_t)n * DD;

    float v[8];
    float sum = 0.f;
    #pragma unroll
    for (int j = 0; j < 8; j++) {
        int d = lane + 32 * j;
        v[j] = er[d] * 16.0f + pr[d];
        sum += v[j];
        g_h [base + d] = v[j];
        g_hh[base + d] = __float2half(v[j]);
    }
    #pragma unroll
    for (int o = 16; o > 0; o >>= 1) sum += __shfl_xor_sync(0xffffffffu, sum, o);
    if (lane == 0) g_pad[n] = (sum == 0.0f) ? 1 : 0;
}

// ---------------- QKV GEMM (fp16) + fp16 split store -------------------------
__global__ __launch_bounds__(256)
void gemm_qkv16(const __half* __restrict__ A,
                const __half* __restrict__ W,
                const float* __restrict__ bias)
{
    __shared__ __align__(16) __half As[2 * H2BUF];
    __shared__ __align__(16) __half Bs[2 * H2BUF];

    int tid = threadIdx.x, lane = tid & 31, w = tid >> 5;
    int wm = w & 1, wn = w >> 1, g = lane >> 2, T = lane & 3;
    int m0 = blockIdx.y * 128, n0 = blockIdx.x * 128;
    int row = tid >> 1, seg = (tid & 1) * 16;

    const float inv = 0.17677669529663689f;

    float acc[4][4][4] = {};
    pipe16_mainloop(A + (size_t)(m0 + row) * DD + seg,
                    W + (size_t)(n0 + row) * DD + seg, DD, As, Bs, acc);

    #pragma unroll
    for (int mt = 0; mt < 4; mt++) {
        #pragma unroll
        for (int nt = 0; nt < 4; nt++) {
            int r0 = m0 + wm * 64 + mt * 16 + g;
            int c0 = n0 + wn * 32 + nt * 8 + 2 * T;
            int t = c0 >> 8, h = (c0 >> 5) & 7, d = c0 & 31;
            float bx = bias[c0], by = bias[c0 + 1];
            #pragma unroll
            for (int half = 0; half < 2; half++) {
                int rr = r0 + half * 8;
                int b = rr >> 9, s = rr & (SS - 1);
                int bh = b * HH + h;
                float v0 = acc[mt][nt][half * 2 + 0] + bx;
                float v1 = acc[mt][nt][half * 2 + 1] + by;
                if (t == 0) {
                    *(uint32_t*)(g_qh + ((size_t)(bh * SS + s)) * DHD + d) =
                        packh2(v0 * inv, v1 * inv);
                } else if (t == 1) {
                    *(uint32_t*)(g_kh + ((size_t)(bh * SS + s)) * DHD + d) =
                        packh2(v0, v1);
                } else {
                    g_vth[((size_t)(bh * DHD + d    )) * SS + s] = __float2half(v0);
                    g_vth[((size_t)(bh * DHD + d + 1)) * SS + s] = __float2half(v1);
                }
            }
        }
    }
}

// ---------------- out-proj GEMM (fp16) ---------------------------------------
__global__ __launch_bounds__(256)
void gemm_out16(const __half* __restrict__ A,
                const __half* __restrict__ W,
                const float* __restrict__ bias,
                float* __restrict__ C, int Nc, int K)
{
    __shared__ __align__(16) __half As[2 * H2BUF];
    __shared__ __align__(16) __half Bs[2 * H2BUF];

    int tid = threadIdx.x, lane = tid & 31, w = tid >> 5;
    int wm = w & 1, wn = w >> 1, g = lane >> 2, T = lane & 3;
    int m0 = blockIdx.y * 128, n0 = blockIdx.x * 128;
    int row = tid >> 1, seg = (tid & 1) * 16;

    float acc[4][4][4] = {};
    pipe16_mainloop(A + (size_t)(m0 + row) * K + seg,
                    W + (size_t)(n0 + row) * K + seg, K, As, Bs, acc);

    #pragma unroll
    for (int mt = 0; mt < 4; mt++) {
        #pragma unroll
        for (int nt = 0; nt < 4; nt++) {
            int r0 = m0 + wm * 64 + mt * 16 + g;
            int c0 = n0 + wn * 32 + nt * 8 + 2 * T;
            float bx = bias[c0], by = bias[c0 + 1];
            #pragma unroll
            for (int half = 0; half < 2; half++) {
                int rr = r0 + half * 8;
                float2 v = make_float2(acc[mt][nt][half * 2 + 0] + bx,
                                       acc[mt][nt][half * 2 + 1] + by);
                *(float2*)(C + (size_t)rr * Nc + c0) = v;
            }
        }
    }
}

// ---------------- MoE GEMM1 (fp16, work-queue grid) --------------------------
__global__ __launch_bounds__(256)
void moe_gemm1_16(const __half* __restrict__ w1, const float* __restrict__ b1,
                  const int* __restrict__ cnt_l)
{
    int y = blockIdx.y;
    if (y >= g_ntiles) return;
    int ent = g_tiletab[y];
    int e = ent >> 16, tile = ent & 0xFFFF;
    int cnt = cnt_l[e];
    int ebase = g_base[e];

    __shared__ __align__(16) __half As[2 * H2BUF];
    __shared__ __align__(16) __half Bs[2 * H2BUF];

    int tid = threadIdx.x, lane = tid & 31, w = tid >> 5;
    int wm = w & 1, wn = w >> 1, g = lane >> 2, T = lane & 3;
    int n0 = blockIdx.x * 128;
    int row = tid >> 1, seg = (tid & 1) * 16;

    int gr = tile * 128 + row;
    if (gr >= cnt) gr = cnt - 1;
    int token = g_perm[ebase + gr];

    float acc[4][4][4] = {};
    pipe16_mainloop(g_hh + (size_t)token * DD + seg,
                    w1 + (size_t)e * EHID * DD + (size_t)(n0 + row) * DD + seg,
                    DD, As, Bs, acc);

    #pragma unroll
    for (int mt = 0; mt < 4; mt++) {
        #pragma unroll
        for (int nt = 0; nt < 4; nt++) {
            int lr0 = wm * 64 + mt * 16 + g;
            int c0  = n0 + wn * 32 + nt * 8 + 2 * T;
            float bx = b1[e * EHID + c0], by = b1[e * EHID + c0 + 1];
            #pragma unroll
            for (int half = 0; half < 2; half++) {
                int grr = tile * 128 + lr0 + half * 8;
                if (grr < cnt) {
                    float v0 = fmaxf(acc[mt][nt][half * 2 + 0] + bx, 0.f);
                    float v1 = fmaxf(acc[mt][nt][half * 2 + 1] + by, 0.f);
                    *(uint32_t*)(g_h1h + (size_t)(ebase + grr) * EHID + c0) = packh2(v0, v1);
                }
            }
        }
    }
}

// ---------------- MoE GEMM2 (fp16, work-queue grid) --------------------------
__global__ __launch_bounds__(256)
void moe_gemm2_16(const __half* __restrict__ w2, const float* __restrict__ b2,
                  const int* __restrict__ cnt_l)
{
    int y = blockIdx.y;
    if (y >= g_ntiles) return;
    int ent = g_tiletab[y];
    int e = ent >> 16, tile = ent & 0xFFFF;
    int cnt = cnt_l[e];
    int ebase = g_base[e];

    __shared__ __align__(16) __half As[2 * H2BUF];
    __shared__ __align__(16) __half Bs[2 * H2BUF];

    int tid = threadIdx.x, lane = tid & 31, w = tid >> 5;
    int wm = w & 1, wn = w >> 1, g = lane >> 2, T = lane & 3;
    int n0 = blockIdx.x * 128;
    int row = tid >> 1, seg = (tid & 1) * 16;

    int gr = tile * 128 + row;
    if (gr >= cnt) gr = cnt - 1;

    float acc[4][4][4] = {};
    pipe16_mainloop(g_h1h + (size_t)(ebase + gr) * EHID + seg,
                    w2 + (size_t)e * DD * EHID + (size_t)(n0 + row) * EHID + seg,
                    EHID, As, Bs, acc);

    #pragma unroll
    for (int mt = 0; mt < 4; mt++) {
        #pragma unroll
        for (int nt = 0; nt < 4; nt++) {
            int lr0 = wm * 64 + mt * 16 + g;
            int c0  = n0 + wn * 32 + nt * 8 + 2 * T;
            float bx = b2[e * DD + c0], by = b2[e * DD + c0 + 1];
            #pragma unroll
            for (int half = 0; half < 2; half++) {
                int grr = tile * 128 + lr0 + half * 8;
                if (grr < cnt) {
                    int token = g_perm[ebase + grr];
                    float gwv = g_ew[token];
                    float2 v = make_float2(gwv * (acc[mt][nt][half * 2 + 0] + bx),
                                           gwv * (acc[mt][nt][half * 2 + 1] + by));
                    *(float2*)(g_tmp + (size_t)token * DD + c0) = v;
                }
            }
        }
    }
}

// ---------------- flash attention (fp16, cp.async double-buffered K/V) -------
#define QTILE 128
#define KCH   64
#define QH    40
#define VSTR  72

__global__ void attn_fa_kernel()
{
    __shared__ __align__(16) __half Qs [QTILE * QH];
    __shared__ __align__(16) __half Ks [2][KCH * QH];
    __shared__ __align__(16) __half Vts[2][DHD * VSTR];
    __shared__ __align__(16) int    mk [2][KCH];

    int qt = blockIdx.x, h = blockIdx.y, b = blockIdx.z;
    int tid = threadIdx.x, lane = tid & 31, w = tid >> 5;
    int g = lane >> 2, T = lane & 3;
    int bh = b * HH + h;

    const __half* Qgh = g_qh  + ((size_t)(bh * SS + qt * QTILE)) * DHD;
    const __half* Kgh = g_kh  + ((size_t)(bh * SS)) * DHD;
    const __half* Vgh = g_vth + ((size_t)bh * DHD) * SS;
    const int*    Pg  = g_pad + b * SS;

    int krow = tid >> 2, kcol = (tid & 3) * 8;
    int vd   = tid >> 3, vcol = (tid & 7) * 8;
    uint32_t ksd[2], vsd[2];
    #pragma unroll
    for (int p = 0; p < 2; p++) {
        ksd[p] = (uint32_t)__cvta_generic_to_shared(&Ks[p][krow * QH + kcol]);
        vsd[p] = (uint32_t)__cvta_generic_to_shared(&Vts[p][vd * VSTR + vcol]);
    }

    for (int i = tid; i < 512; i += 256) {
        int row = i >> 2, c = (i & 3) * 8;
        *(uint4*)(Qs + row * QH + c) = *(const uint4*)(Qgh + row * DHD + c);
    }

    {
        cp16(ksd[0], Kgh + (size_t)krow * DHD + kcol);
        cp16(vsd[0], Vgh + (size_t)vd * SS + vcol);
        if (tid < 16)
            cp16((uint32_t)__cvta_generic_to_shared(&mk[0][tid * 4]), Pg + tid * 4);
        asm volatile("cp.async.commit_group;\n");
    }

    float m_[2]  = {-1e30f, -1e30f};
    float sum_[2] = {0.f, 0.f};
    float o[4][4] = {};

    for (int kc = 0; kc < SS / KCH; kc++) {
        int buf = kc & 1;
        if (kc + 1 < SS / KCH) {
            int nb = (kc + 1) & 1;
            cp16(ksd[nb], Kgh + (size_t)((kc + 1) * KCH + krow) * DHD + kcol);
            cp16(vsd[nb], Vgh + (size_t)vd * SS + (kc + 1) * KCH + vcol);
            if (tid < 16)
                cp16((uint32_t)__cvta_generic_to_shared(&mk[nb][tid * 4]),
                     Pg + (kc + 1) * KCH + tid * 4);
            asm volatile("cp.async.commit_group;\n");
            asm volatile("cp.async.wait_group 1;\n");
        } else {
            asm volatile("cp.async.wait_group 0;\n");
        }
        __syncthreads();

        float s[8][4];
        #pragma unroll
        for (int nt = 0; nt < 8; nt++)
            #pragma unroll
            for (int j = 0; j < 4; j++) s[nt][j] = 0.f;

        #pragma unroll
        for (int ks = 0; ks < 2; ks++) {
            int row = w * 16 + g, col = ks * 16 + 2 * T;
            uint32_t a0 = *(const uint32_t*)(Qs + row * QH + col);
            uint32_t a1 = *(const uint32_t*)(Qs + (row + 8) * QH + col);
            uint32_t a2 = *(const uint32_t*)(Qs + row * QH + col + 8);
            uint32_t a3 = *(const uint32_t*)(Qs + (row + 8) * QH + col + 8);
            #pragma unroll
            for (int nt = 0; nt < 8; nt++) {
                int kr = nt * 8 + g;
                uint32_t b0 = *(const uint32_t*)(&Ks[buf][kr * QH + col]);
                uint32_t b1 = *(const uint32_t*)(&Ks[buf][kr * QH + col + 8]);
                mma_f16(s[nt], a0, a1, a2, a3, b0, b1);
            }
        }

        #pragma unroll
        for (int nt = 0; nt < 8; nt++) {
            if (mk[buf][nt * 8 + 2 * T])     { s[nt][0] = -1e9f; s[nt][2] = -1e9f; }
            if (mk[buf][nt * 8 + 2 * T + 1]) { s[nt][1] = -1e9f; s[nt][3] = -1e9f; }
        }

        #pragma unroll
        for (int half = 0; half < 2; half++) {
            float cmax = -1e30f;
            #pragma unroll
            for (int nt = 0; nt < 8; nt++)
                cmax = fmaxf(cmax, fmaxf(s[nt][2 * half], s[nt][2 * half + 1]));
            cmax = fmaxf(cmax, __shfl_xor_sync(0xffffffffu, cmax, 1));
            cmax = fmaxf(cmax, __shfl_xor_sync(0xffffffffu, cmax, 2));
            float mnew  = fmaxf(m_[half], cmax);
            float scale = fexp(m_[half] - mnew);
            m_[half] = mnew;
            float part = 0.f;
            #pragma unroll
            for (int nt = 0; nt < 8; nt++) {
                float p0 = fexp(s[nt][2 * half]     - mnew);
                float p1 = fexp(s[nt][2 * half + 1] - mnew);
                s[nt][2 * half] = p0; s[nt][2 * half + 1] = p1;
                part += p0 + p1;
            }
            part += __shfl_xor_sync(0xffffffffu, part, 1);
            part += __shfl_xor_sync(0xffffffffu, part, 2);
            sum_[half] = sum_[half] * scale + part;
            #pragma unroll
            for (int nt = 0; nt < 4; nt++) {
                o[nt][2 * half]     *= scale;
                o[nt][2 * half + 1] *= scale;
            }
        }

        #pragma unroll
        for (int kt = 0; kt < 4; kt++) {
            uint32_t a0 = packh2(s[2 * kt][0],     s[2 * kt][1]);
            uint32_t a1 = packh2(s[2 * kt][2],     s[2 * kt][3]);
            uint32_t a2 = packh2(s[2 * kt + 1][0], s[2 * kt + 1][1]);
            uint32_t a3 = packh2(s[2 * kt + 1][2], s[2 * kt + 1][3]);
            #pragma unroll
            for (int nt = 0; nt < 4; nt++) {
                const __half* vp = &Vts[buf][(nt * 8 + g) * VSTR + kt * 16 + 2 * T];
                uint32_t b0 = *(const uint32_t*)vp;
                uint32_t b1 = *(const uint32_t*)(vp + 8);
                mma_f16(o[nt], a0, a1, a2, a3, b0, b1);
            }
        }
        __syncthreads();
    }

    float i0 = 1.0f / sum_[0];
    float i1 = 1.0f / sum_[1];
    int q0 = qt * QTILE + w * 16 + g;
    #pragma unroll
    for (int nt = 0; nt < 4; nt++) {
        int col = h * DHD + nt * 8 + 2 * T;
        *(uint32_t*)(g_ctxh + (size_t)(b * SS + q0) * DD + col) =
            packh2(o[nt][0] * i0, o[nt][1] * i0);
        *(uint32_t*)(g_ctxh + (size_t)(b * SS + q0 + 8) * DD + col) =
            packh2(o[nt][2] * i1, o[nt][3] * i1);
    }
}

// ---------------- fused residual + LN (+optional gate) -----------------------
__device__ __forceinline__ void warp_add_ln(
    int n, int lane, const float* __restrict__ add,
    const float* __restrict__ gamma, const float* __restrict__ beta,
    float out[8])
{
    size_t base = (size_t)n * DD + lane;
    float v[8];
    float sum = 0.f;
    #pragma unroll
    for (int j = 0; j < 8; j++) {
        v[j] = g_h[base + 32 * j] + add[base + 32 * j];
        sum += v[j];
    }
    #pragma unroll
    for (int o = 16; o > 0; o >>= 1) sum += __shfl_xor_sync(0xffffffffu, sum, o);
    float mu = sum * (1.0f / DD);
    float sq = 0.f;
    #pragma unroll
    for (int j = 0; j < 8; j++) {
        v[j] -= mu;
        sq += v[j] * v[j];
    }
    #pragma unroll
    for (int o = 16; o > 0; o >>= 1) sq += __shfl_xor_sync(0xffffffffu, sq, o);
    float r = rsqrtf(sq * (1.0f / DD) + 1e-5f);
    #pragma unroll
    for (int j = 0; j < 8; j++) {
        out[j] = v[j] * r * gamma[lane + 32 * j] + beta[lane + 32 * j];
        g_h [base + 32 * j] = out[j];
        g_hh[base + 32 * j] = __float2half(out[j]);
    }
}

__global__ void add_ln2_kernel(const float* __restrict__ add,
                               const float* __restrict__ gamma,
                               const float* __restrict__ beta)
{
    int lane = threadIdx.x & 31;
    int n = blockIdx.x * 8 + (threadIdx.x >> 5);
    float out[8];
    warp_add_ln(n, lane, add, gamma, beta, out);
}

__global__ void add_ln1_gate_kernel(const float* __restrict__ add,
                                    const float* __restrict__ gamma,
                                    const float* __restrict__ beta,
                                    const float* __restrict__ gw,
                                    const float* __restrict__ gb,
                                    int* __restrict__ cnt_l)
{
    int lane = threadIdx.x & 31;
    int n = blockIdx.x * 8 + (threadIdx.x >> 5);
    float out[8];
    warp_add_ln(n, lane, add, gamma, beta, out);

    float lg[NEXP];
    #pragma unroll
    for (int e = 0; e < NEXP; e++) {
        float p = 0.f;
        #pragma unroll
        for (int j = 0; j < 8; j++)
            p = fmaf(gw[e * DD + lane + 32 * j], out[j], p);
        #pragma unroll
        for (int o = 16; o > 0; o >>= 1)
            p += __shfl_xor_sync(0xffffffffu, p, o);
        lg[e] = p;
    }
    if (lane == 0) {
        float m = -1e30f;
        #pragma unroll
        for (int i = 0; i < NEXP; i++) { lg[i] += gb[i]; m = fmaxf(m, lg[i]); }
        float p[NEXP], sum = 0.f;
        #pragma unroll
        for (int i = 0; i < NEXP; i++) { p[i] = expf(lg[i] - m); sum += p[i]; }
        int bi = 0; float bw = p[0];
        #pragma unroll
        for (int i = 1; i < NEXP; i++) if (p[i] > bw) { bw = p[i]; bi = i; }
        g_eidx[n] = bi;
        g_ew[n]   = bw / sum;
        atomicAdd(&cnt_l[bi], 1);
    }
}

// ---------------- routing bookkeeping (prefix + tile table) ------------------
__global__ void prefix_kernel(const int* __restrict__ cnt_l)
{
    if (threadIdx.x == 0) {
        int acc = 0, idx = 0;
        #pragma unroll
        for (int e = 0; e < NEXP; e++) {
            g_base[e] = acc; g_cursor[e] = acc;
            int c = cnt_l[e];
            acc += c;
            int nt = (c + 127) >> 7;
            for (int t = 0; t < nt; t++) g_tiletab[idx++] = (e << 16) | t;
        }
        g_ntiles = idx;
    }
}

__global__ void scatter_kernel()
{
    int n = blockIdx.x * blockDim.x + threadIdx.x;
    if (n < NTOK) {
        int e = g_eidx[n];
        int pos = atomicAdd(&g_cursor[e], 1);
        g_perm[pos] = n;
    }
}

// ---------------- head: partial pooling + final ------------------------------
__global__ void pool_kernel()
{
    int b = blockIdx.x, c = blockIdx.y;
    int tid = threadIdx.x;
    int base = b * SS + c * 64;
    float s = 0.f;
    #pragma unroll 8
    for (int i = 0; i < 64; i++) {
        int n = base + i;
        if (!g_pad[n]) s += g_h[(size_t)n * DD + tid];
    }
    g_pool[(b * 8 + c) * DD + tid] = s;
    if (tid == 0) {
        int t = 0;
        #pragma unroll 8
        for (int i = 0; i < 64; i++) t += (g_pad[base + i] == 0);
        g_pcnt[b * 8 + c] = t;
    }
}

__global__ void head_final(const float* __restrict__ fc1w, const float* __restrict__ fc1b,
                           const float* __restrict__ fc2w, const float* __restrict__ fc2b,
                           float* __restrict__ out)
{
    int b = blockIdx.x, tid = threadIdx.x;
    __shared__ float pooled[DD];
    __shared__ float z[128];
    __shared__ int scnt;

    float s = 0.f;
    #pragma unroll
    for (int c = 0; c < 8; c++) s += g_pool[(b * 8 + c) * DD + tid];
    if (tid == 0) {
        int t = 0;
        #pragma unroll
        for (int c = 0; c < 8; c++) t += g_pcnt[b * 8 + c];
        scnt = t;
    }
    __syncthreads();
    pooled[tid] = s / fmaxf((float)scnt, 1.0f);
    __syncthreads();

    if (tid < 128) {
        float a = fc1b[tid];
        const float* wr = fc1w + (size_t)tid * DD;
        #pragma unroll 8
        for (int d = 0; d < DD; d++) a += pooled[d] * wr[d];
        z[tid] = fmaxf(a, 0.f);
    }
    __syncthreads();
    if (tid < 2) {
        float a = fc2b[tid];
        const float* wr = fc2w + (size_t)tid * 128;
        #pragma unroll 8
        for (int i = 0; i < 128; i++) a += z[i] * wr[i];
        out[b * 2 + tid] = a;
    }
}

// ---------------- host launch ------------------------------------------------
static void* sym_addr(const void* sym)
{
    void* p = nullptr;
    cudaGetSymbolAddress(&p, sym);
    return p;
}

extern "C" void kernel_launch(void* const* d_in, const int* in_sizes, int n_in,
                              void* d_out, int out_size)
{
    const int*   x          = (const int*)  d_in[0];
    const float* emb        = (const float*)d_in[1];
    const float* in_proj_w  = (const float*)d_in[2];
    const float* in_proj_b  = (const float*)d_in[3];
    const float* out_proj_w = (const float*)d_in[4];
    const float* out_proj_b = (const float*)d_in[5];
    const float* ln1_g      = (const float*)d_in[6];
    const float* ln1_b      = (const float*)d_in[7];
    const float* ln2_g      = (const float*)d_in[8];
    const float* ln2_b      = (const float*)d_in[9];
    const float* gate_w     = (const float*)d_in[10];
    const float* gate_b     = (const float*)d_in[11];
    const float* w1         = (const float*)d_in[12];
    const float* b1         = (const float*)d_in[13];
    const float* w2         = (const float*)d_in[14];
    const float* b2         = (const float*)d_in[15];
    const float* fc1_w      = (const float*)d_in[16];
    const float* fc1_b      = (const float*)d_in[17];
    const float* fc2_w      = (const float*)d_in[18];
    const float* fc2_b      = (const float*)d_in[19];
    float* out = (float*)d_out;

    __half* wh    = (__half*)sym_addr(g_wh);
    __half* hh    = (__half*)sym_addr(g_hh);
    __half* ctxh  = (__half*)sym_addr(g_ctxh);
    float*  p_tmp = (float*)sym_addr(g_tmp);
    int*    cnt   = (int*)sym_addr(g_cnt);

    pe_kernel<<<DD, SS>>>();
    zero_cnt_all<<<1, 32>>>();
    embed_kernel<<<NTOK/8, 256>>>(x, emb);
    f2h_all<<<(WH_TOTAL/4 + 255)/256, 256>>>(in_proj_w, out_proj_w, w1, w2);

    for (int l = 0; l < NLAY; l++) {
        int* cnt_l = cnt + l * NEXP;

        gemm_qkv16<<<dim3(3*DD/128, NTOK/128), 256>>>(
            hh, wh + IPH_OFF + (size_t)l * 3*DD*DD, in_proj_b + (size_t)l * 3*DD);

        attn_fa_kernel<<<dim3(SS/QTILE, HH, BB), 256>>>();

        gemm_out16<<<dim3(DD/128, NTOK/128), 256>>>(
            ctxh, wh + OPH_OFF + (size_t)l * DD*DD, out_proj_b + (size_t)l * DD,
            p_tmp, DD, DD);

        add_ln1_gate_kernel<<<NTOK/8, 256>>>(
            p_tmp, ln1_g + (size_t)l * DD, ln1_b + (size_t)l * DD,
            gate_w + (size_t)l * NEXP*DD, gate_b + (size_t)l * NEXP, cnt_l);
        prefix_kernel<<<1, 32>>>(cnt_l);
        scatter_kernel<<<NTOK/256, 256>>>();

        moe_gemm1_16<<<dim3(EHID/128, 71), 256>>>(
            wh + W1H_OFF + (size_t)l * NEXP*EHID*DD, b1 + (size_t)l * NEXP*EHID, cnt_l);
        moe_gemm2_16<<<dim3(DD/128, 71), 256>>>(
            wh + W2H_OFF + (size_t)l * NEXP*DD*EHID, b2 + (size_t)l * NEXP*DD, cnt_l);

        add_ln2_kernel<<<NTOK/8, 256>>>(
            p_tmp, ln2_g + (size_t)l * DD, ln2_b + (size_t)l * DD);
    }

    pool_kernel<<<dim3(BB, 8), 256>>>();
    head_final<<<BB, 256>>>(fc1_w, fc1_b, fc2_w, fc2_b, out);
}